// round 3
// baseline (speedup 1.0000x reference)
#include <cuda_runtime.h>
#include <cstdint>

#define HID 256
#define NHEAD 4
#define MAXN 20000
#define MAXE 320000

// ---------------- scratch (device globals; no allocation allowed) ----------------
__device__ float    g_h   [(size_t)MAXN * HID];        // ln1 out, reused as h2
__device__ float    g_q   [(size_t)MAXN * HID];
__device__ float    g_k   [(size_t)MAXN * HID];
__device__ float    g_v   [(size_t)MAXN * HID];
__device__ float    g_conv[(size_t)MAXN * HID];        // skip proj, then += edge agg
__device__ float    g_x1  [(size_t)MAXN * HID];        // x + conv
__device__ float    g_mid [(size_t)MAXN * 2 * HID];    // FF hidden
__device__ float    g_scores[(size_t)MAXE * NHEAD];    // logits, then exp weights
__device__ unsigned g_mkey[MAXN * NHEAD];              // segment-max keys
__device__ float    g_den [MAXN * NHEAD];              // softmax denominators
__device__ int      g_is64;                            // edge_index stored as int64?

// ---------------- helpers ----------------
__device__ __forceinline__ unsigned fkey(float x) {
    unsigned u = __float_as_uint(x);
    return (u & 0x80000000u) ? ~u : (u | 0x80000000u);
}
__device__ __forceinline__ float funkey(unsigned u) {
    u = (u & 0x80000000u) ? (u & 0x7fffffffu) : ~u;
    return __uint_as_float(u);
}
// pos in [0, 2E): logical element index into edge_index flattened [2, E]
__device__ __forceinline__ int load_idx(const int* __restrict__ ei, int pos, int is64) {
    return is64 ? ei[(size_t)pos * 2] : ei[pos];   // little-endian low word
}
__device__ __forceinline__ void red_add_v4(float* p, float a, float b, float c, float d) {
    asm volatile("red.global.add.v4.f32 [%0], {%1,%2,%3,%4};"
                 :: "l"(p), "f"(a), "f"(b), "f"(c), "f"(d) : "memory");
}
__device__ __forceinline__ float gelu_exact(float v) {
    return 0.5f * v * (1.0f + erff(v * 0.7071067811865476f));
}

// ---------------- dtype detection (1 warp) ----------------
// int64 layout => odd int32 words are high halves of indices < 2^31 => all 0.
// int32 layout => odd words are real random indices; 512 of them all-zero is impossible.
__global__ void detect_kernel(const int* __restrict__ ei, int E) {
    int lane = threadIdx.x;
    int nz = 0;
    for (int i = lane; i < 512 && i < E; i += 32)
        nz |= ei[2 * i + 1];
    #pragma unroll
    for (int o = 16; o > 0; o >>= 1) nz |= __shfl_xor_sync(0xffffffffu, nz, o);
    if (lane == 0) g_is64 = (nz == 0) ? 1 : 0;
}

// ---------------- init ----------------
__global__ void init_kernel(unsigned* __restrict__ mkey, float* __restrict__ den, int n4) {
    int i = blockIdx.x * blockDim.x + threadIdx.x;
    if (i < n4) { mkey[i] = 0u; den[i] = 0.0f; }
}

// ---------------- LayerNorm (warp per row of 256) ----------------
__global__ void ln_kernel(const float* __restrict__ x, const float* __restrict__ w,
                          const float* __restrict__ b, float* __restrict__ out, int n) {
    int row = (blockIdx.x * blockDim.x + threadIdx.x) >> 5;
    if (row >= n) return;
    int lane = threadIdx.x & 31;
    const float4* xp = (const float4*)(x + (size_t)row * HID);
    float4 v0 = xp[lane * 2], v1 = xp[lane * 2 + 1];
    float s  = v0.x + v0.y + v0.z + v0.w + v1.x + v1.y + v1.z + v1.w;
    float sq = v0.x*v0.x + v0.y*v0.y + v0.z*v0.z + v0.w*v0.w
             + v1.x*v1.x + v1.y*v1.y + v1.z*v1.z + v1.w*v1.w;
    #pragma unroll
    for (int o = 16; o > 0; o >>= 1) {
        s  += __shfl_xor_sync(0xffffffffu, s,  o);
        sq += __shfl_xor_sync(0xffffffffu, sq, o);
    }
    float mean = s * (1.0f / HID);
    float var  = sq * (1.0f / HID) - mean * mean;
    float rstd = rsqrtf(var + 1e-5f);
    const float4* wp = (const float4*)w;
    const float4* bp = (const float4*)b;
    float4* op = (float4*)(out + (size_t)row * HID);
    #pragma unroll
    for (int i = 0; i < 2; i++) {
        float4 xv = (i == 0) ? v0 : v1;
        float4 wv = wp[lane * 2 + i], bv = bp[lane * 2 + i];
        float4 o;
        o.x = (xv.x - mean) * rstd * wv.x + bv.x;
        o.y = (xv.y - mean) * rstd * wv.y + bv.y;
        o.z = (xv.z - mean) * rstd * wv.z + bv.z;
        o.w = (xv.w - mean) * rstd * wv.w + bv.w;
        op[lane * 2 + i] = o;
    }
}

// ---------------- x1 = x + conv; store x1; h2 = LN2(x1) ----------------
__global__ void add_ln_kernel(const float* __restrict__ x, const float* __restrict__ conv,
                              const float* __restrict__ w, const float* __restrict__ b,
                              float* __restrict__ x1out, float* __restrict__ hout, int n) {
    int row = (blockIdx.x * blockDim.x + threadIdx.x) >> 5;
    if (row >= n) return;
    int lane = threadIdx.x & 31;
    const float4* xp = (const float4*)(x    + (size_t)row * HID);
    const float4* cp = (const float4*)(conv + (size_t)row * HID);
    float4 a0 = xp[lane * 2], a1 = xp[lane * 2 + 1];
    float4 c0 = cp[lane * 2], c1 = cp[lane * 2 + 1];
    float4 v0 = make_float4(a0.x + c0.x, a0.y + c0.y, a0.z + c0.z, a0.w + c0.w);
    float4 v1 = make_float4(a1.x + c1.x, a1.y + c1.y, a1.z + c1.z, a1.w + c1.w);
    float4* x1p = (float4*)(x1out + (size_t)row * HID);
    x1p[lane * 2]     = v0;
    x1p[lane * 2 + 1] = v1;
    float s  = v0.x + v0.y + v0.z + v0.w + v1.x + v1.y + v1.z + v1.w;
    float sq = v0.x*v0.x + v0.y*v0.y + v0.z*v0.z + v0.w*v0.w
             + v1.x*v1.x + v1.y*v1.y + v1.z*v1.z + v1.w*v1.w;
    #pragma unroll
    for (int o = 16; o > 0; o >>= 1) {
        s  += __shfl_xor_sync(0xffffffffu, s,  o);
        sq += __shfl_xor_sync(0xffffffffu, sq, o);
    }
    float mean = s * (1.0f / HID);
    float var  = sq * (1.0f / HID) - mean * mean;
    float rstd = rsqrtf(var + 1e-5f);
    const float4* wp = (const float4*)w;
    const float4* bp = (const float4*)b;
    float4* op = (float4*)(hout + (size_t)row * HID);
    #pragma unroll
    for (int i = 0; i < 2; i++) {
        float4 xv = (i == 0) ? v0 : v1;
        float4 wv = wp[lane * 2 + i], bv = bp[lane * 2 + i];
        float4 o;
        o.x = (xv.x - mean) * rstd * wv.x + bv.x;
        o.y = (xv.y - mean) * rstd * wv.y + bv.y;
        o.z = (xv.z - mean) * rstd * wv.z + bv.z;
        o.w = (xv.w - mean) * rstd * wv.w + bv.w;
        op[lane * 2 + i] = o;
    }
}

// ---------------- GEMM: C[M,N] = A[M,K] @ W[K,N] + bias (+ epilogue) ----------------
// EPI 0: bias only; 1: bias+GELU; 2: bias + residual add
#define BM 128
#define BN 128
#define BK 16
template<int EPI>
__global__ __launch_bounds__(256, 2)
void gemm_kernel(const float* __restrict__ A, const float* __restrict__ W,
                 const float* __restrict__ bias, const float* __restrict__ res,
                 float* __restrict__ C, int M, int N, int K) {
    __shared__ float As[BK][BM + 4];
    __shared__ float Bs[BK][BN];
    int t  = threadIdx.x;
    int tx = t & 15, ty = t >> 4;
    int mBase = blockIdx.x * BM;
    int nBase = blockIdx.y * BN;
    float acc[8][8];
    #pragma unroll
    for (int i = 0; i < 8; i++)
        #pragma unroll
        for (int j = 0; j < 8; j++) acc[i][j] = 0.0f;

    for (int kb = 0; kb < K; kb += BK) {
        #pragma unroll
        for (int i = 0; i < 2; i++) {
            int idx = t + i * 256;
            int row = idx >> 2;
            int c4  = (idx & 3) * 4;
            int gr  = mBase + row;
            float4 va = (gr < M) ? *(const float4*)(A + (size_t)gr * K + kb + c4)
                                 : make_float4(0.f, 0.f, 0.f, 0.f);
            As[c4 + 0][row] = va.x;
            As[c4 + 1][row] = va.y;
            As[c4 + 2][row] = va.z;
            As[c4 + 3][row] = va.w;
        }
        #pragma unroll
        for (int i = 0; i < 2; i++) {
            int idx = t + i * 256;
            int row = idx >> 5;
            int c4  = (idx & 31) * 4;
            *(float4*)&Bs[row][c4] = *(const float4*)(W + (size_t)(kb + row) * N + nBase + c4);
        }
        __syncthreads();
        #pragma unroll
        for (int kk = 0; kk < BK; kk++) {
            float a[8], b[8];
            *(float4*)&a[0] = *(const float4*)&As[kk][ty * 8];
            *(float4*)&a[4] = *(const float4*)&As[kk][ty * 8 + 4];
            *(float4*)&b[0] = *(const float4*)&Bs[kk][tx * 8];
            *(float4*)&b[4] = *(const float4*)&Bs[kk][tx * 8 + 4];
            #pragma unroll
            for (int i = 0; i < 8; i++)
                #pragma unroll
                for (int j = 0; j < 8; j++)
                    acc[i][j] += a[i] * b[j];
        }
        __syncthreads();
    }

    #pragma unroll
    for (int i = 0; i < 8; i++) {
        int gr = mBase + ty * 8 + i;
        if (gr >= M) break;
        #pragma unroll
        for (int j = 0; j < 8; j += 4) {
            int gc = nBase + tx * 8 + j;
            float4 bv = *(const float4*)(bias + gc);
            float4 o;
            o.x = acc[i][j + 0] + bv.x;
            o.y = acc[i][j + 1] + bv.y;
            o.z = acc[i][j + 2] + bv.z;
            o.w = acc[i][j + 3] + bv.w;
            if (EPI == 1) {
                o.x = gelu_exact(o.x); o.y = gelu_exact(o.y);
                o.z = gelu_exact(o.z); o.w = gelu_exact(o.w);
            }
            if (EPI == 2) {
                float4 rv = *(const float4*)(res + (size_t)gr * N + gc);
                o.x += rv.x; o.y += rv.y; o.z += rv.z; o.w += rv.w;
            }
            *(float4*)(C + (size_t)gr * N + gc) = o;
        }
    }
}

// ---------------- edge scores (warp per edge): s[e,h] = q[dst,h,:]·k[src,h,:]/8 ----------------
__global__ void edge_scores_kernel(const int* __restrict__ ei,
                                   const float* __restrict__ q, const float* __restrict__ k,
                                   float* __restrict__ scores, unsigned* __restrict__ mkey, int E) {
    int e = (blockIdx.x * blockDim.x + threadIdx.x) >> 5;
    if (e >= E) return;
    int lane = threadIdx.x & 31;
    int is64 = g_is64;
    int src = load_idx(ei, e, is64);
    int dst = load_idx(ei, E + e, is64);
    const float4* qp = (const float4*)(q + (size_t)dst * HID) + lane * 2;
    const float4* kp = (const float4*)(k + (size_t)src * HID) + lane * 2;
    float4 a0 = qp[0], a1 = qp[1];
    float4 b0 = kp[0], b1 = kp[1];
    float d = a0.x*b0.x + a0.y*b0.y + a0.z*b0.z + a0.w*b0.w
            + a1.x*b1.x + a1.y*b1.y + a1.z*b1.z + a1.w*b1.w;
    d += __shfl_xor_sync(0xffffffffu, d, 1);
    d += __shfl_xor_sync(0xffffffffu, d, 2);
    d += __shfl_xor_sync(0xffffffffu, d, 4);
    if ((lane & 7) == 0) {
        int h = lane >> 3;
        float s = d * 0.125f;   // 1/sqrt(64)
        scores[(size_t)e * NHEAD + h] = s;
        atomicMax(&mkey[dst * NHEAD + h], fkey(s));
    }
}

// ---------------- exp + denominator (thread per (edge, head)) ----------------
__global__ void edge_exp_kernel(const int* __restrict__ ei,
                                float* __restrict__ scores,
                                const unsigned* __restrict__ mkey,
                                float* __restrict__ den, int E) {
    int idx = blockIdx.x * blockDim.x + threadIdx.x;
    if (idx >= E * NHEAD) return;
    int e = idx >> 2, h = idx & 3;
    int dst = load_idx(ei, E + e, g_is64);
    float m = funkey(mkey[dst * NHEAD + h]);
    float w = __expf(scores[idx] - m);
    scores[idx] = w;
    atomicAdd(&den[dst * NHEAD + h], w);
}

// ---------------- aggregate (warp per edge): conv[dst] += attn * v[src] ----------------
__global__ void edge_agg_kernel(const int* __restrict__ ei,
                                const float* __restrict__ scores, const float* __restrict__ den,
                                const float* __restrict__ v, float* __restrict__ conv, int E) {
    int e = (blockIdx.x * blockDim.x + threadIdx.x) >> 5;
    if (e >= E) return;
    int lane = threadIdx.x & 31;
    int is64 = g_is64;
    int src = load_idx(ei, e, is64);
    int dst = load_idx(ei, E + e, is64);
    int h = lane >> 3;
    float attn = scores[(size_t)e * NHEAD + h] / den[dst * NHEAD + h];
    const float4* vp = (const float4*)(v + (size_t)src * HID) + lane * 2;
    float4 v0 = vp[0], v1 = vp[1];
    float* op = conv + (size_t)dst * HID + lane * 8;
    red_add_v4(op,     attn * v0.x, attn * v0.y, attn * v0.z, attn * v0.w);
    red_add_v4(op + 4, attn * v1.x, attn * v1.y, attn * v1.z, attn * v1.w);
}

// ---------------- host launch ----------------
extern "C" void kernel_launch(void* const* d_in, const int* in_sizes, int n_in,
                              void* d_out, int out_size) {
    const float* x     = (const float*)d_in[0];
    const int*   ei    = (const int*)d_in[1];      // int32 or int64; detected on device
    const float* ln1_w = (const float*)d_in[2];
    const float* ln1_b = (const float*)d_in[3];
    const float* ln2_w = (const float*)d_in[4];
    const float* ln2_b = (const float*)d_in[5];
    const float* wq    = (const float*)d_in[6];
    const float* bq    = (const float*)d_in[7];
    const float* wk    = (const float*)d_in[8];
    const float* bk    = (const float*)d_in[9];
    const float* wv    = (const float*)d_in[10];
    const float* bv    = (const float*)d_in[11];
    const float* wskip = (const float*)d_in[12];
    const float* bskip = (const float*)d_in[13];
    const float* w1    = (const float*)d_in[14];
    const float* b1    = (const float*)d_in[15];
    const float* w2    = (const float*)d_in[16];
    const float* b2    = (const float*)d_in[17];

    int n = in_sizes[0] / HID;
    int E = in_sizes[1] / 2;

    static float *h = nullptr, *q, *k, *v, *conv, *x1, *mid, *scores, *den;
    static unsigned* mkey;
    if (!h) {   // resolved on the first (uncaptured) correctness call; pure address lookup
        cudaGetSymbolAddress((void**)&h,      g_h);
        cudaGetSymbolAddress((void**)&q,      g_q);
        cudaGetSymbolAddress((void**)&k,      g_k);
        cudaGetSymbolAddress((void**)&v,      g_v);
        cudaGetSymbolAddress((void**)&conv,   g_conv);
        cudaGetSymbolAddress((void**)&x1,     g_x1);
        cudaGetSymbolAddress((void**)&mid,    g_mid);
        cudaGetSymbolAddress((void**)&scores, g_scores);
        cudaGetSymbolAddress((void**)&den,    g_den);
        cudaGetSymbolAddress((void**)&mkey,   g_mkey);
    }

    detect_kernel<<<1, 32>>>(ei, E);
    init_kernel<<<(n * NHEAD + 255) / 256, 256>>>(mkey, den, n * NHEAD);
    ln_kernel<<<(n * 32 + 255) / 256, 256>>>(x, ln1_w, ln1_b, h, n);

    dim3 g1((n + BM - 1) / BM, HID / BN);          // 157 x 2
    gemm_kernel<0><<<g1, 256>>>(h, wq, bq, nullptr, q,    n, HID, HID);
    gemm_kernel<0><<<g1, 256>>>(h, wk, bk, nullptr, k,    n, HID, HID);
    gemm_kernel<0><<<g1, 256>>>(h, wv, bv, nullptr, v,    n, HID, HID);
    gemm_kernel<0><<<g1, 256>>>(h, wskip, bskip, nullptr, conv, n, HID, HID);

    edge_scores_kernel<<<(E + 7) / 8, 256>>>(ei, q, k, scores, mkey, E);
    edge_exp_kernel<<<(E * NHEAD + 255) / 256, 256>>>(ei, scores, mkey, den, E);
    edge_agg_kernel<<<(E + 7) / 8, 256>>>(ei, scores, den, v, conv, E);

    add_ln_kernel<<<(n * 32 + 255) / 256, 256>>>(x, conv, ln2_w, ln2_b, x1, h, n);

    dim3 g2((n + BM - 1) / BM, (2 * HID) / BN);    // 157 x 4
    gemm_kernel<1><<<g2, 256>>>(h, w1, b1, nullptr, mid, n, 2 * HID, HID);

    dim3 g3((n + BM - 1) / BM, HID / BN);          // 157 x 2
    gemm_kernel<2><<<g3, 256>>>(mid, w2, b2, x1, (float*)d_out, n, HID, 2 * HID);
}

// round 4
// speedup vs baseline: 2.0312x; 2.0312x over previous
#include <cuda_runtime.h>
#include <cstdint>

#define HID 256
#define NHEAD 4
#define MAXN 20000
#define MAXE 320000

// ---------------- scratch (device globals; no allocation allowed) ----------------
__device__ float    g_h   [(size_t)MAXN * HID];        // ln1 out, reused as h2
__device__ float    g_q   [(size_t)MAXN * HID];
__device__ float    g_k   [(size_t)MAXN * HID];
__device__ float    g_v   [(size_t)MAXN * HID];
__device__ float    g_conv[(size_t)MAXN * HID];        // skip proj, then += edge agg
__device__ float    g_x1  [(size_t)MAXN * HID];        // x + conv
__device__ float    g_mid [(size_t)MAXN * 2 * HID];    // FF hidden
__device__ float    g_scores[(size_t)MAXE * NHEAD];    // logits, then exp weights
__device__ unsigned g_mkey[MAXN * NHEAD];              // segment-max keys
__device__ float    g_den [MAXN * NHEAD];              // softmax denominators
__device__ int      g_is64;                            // edge_index stored as int64?

// ---------------- helpers ----------------
__device__ __forceinline__ unsigned fkey(float x) {
    unsigned u = __float_as_uint(x);
    return (u & 0x80000000u) ? ~u : (u | 0x80000000u);
}
__device__ __forceinline__ float funkey(unsigned u) {
    u = (u & 0x80000000u) ? (u & 0x7fffffffu) : ~u;
    return __uint_as_float(u);
}
__device__ __forceinline__ int load_idx(const int* __restrict__ ei, int pos, int is64) {
    return is64 ? ei[(size_t)pos * 2] : ei[pos];   // little-endian low word
}
__device__ __forceinline__ void red_add_v4(float* p, float a, float b, float c, float d) {
    asm volatile("red.global.add.v4.f32 [%0], {%1,%2,%3,%4};"
                 :: "l"(p), "f"(a), "f"(b), "f"(c), "f"(d) : "memory");
}
__device__ __forceinline__ float gelu_exact(float v) {
    return 0.5f * v * (1.0f + erff(v * 0.7071067811865476f));
}
__device__ __forceinline__ uint32_t f2tf(float x) {
    uint32_t r; asm("cvt.rna.tf32.f32 %0, %1;" : "=r"(r) : "f"(x)); return r;
}
__device__ __forceinline__ void mma_tf32(float* c, const uint32_t* a, const uint32_t* b) {
    asm volatile("mma.sync.aligned.m16n8k8.row.col.f32.tf32.tf32.f32 "
                 "{%0,%1,%2,%3}, {%4,%5,%6,%7}, {%8,%9}, {%0,%1,%2,%3};"
                 : "+f"(c[0]), "+f"(c[1]), "+f"(c[2]), "+f"(c[3])
                 : "r"(a[0]), "r"(a[1]), "r"(a[2]), "r"(a[3]), "r"(b[0]), "r"(b[1]));
}

// ---------------- dtype detection (1 warp) ----------------
__global__ void detect_kernel(const int* __restrict__ ei, int E) {
    int lane = threadIdx.x;
    int nz = 0;
    for (int i = lane; i < 512 && i < E; i += 32)
        nz |= ei[2 * i + 1];
    #pragma unroll
    for (int o = 16; o > 0; o >>= 1) nz |= __shfl_xor_sync(0xffffffffu, nz, o);
    if (lane == 0) g_is64 = (nz == 0) ? 1 : 0;
}

// ---------------- init ----------------
__global__ void init_kernel(unsigned* __restrict__ mkey, float* __restrict__ den, int n4) {
    int i = blockIdx.x * blockDim.x + threadIdx.x;
    if (i < n4) { mkey[i] = 0u; den[i] = 0.0f; }
}

// ---------------- LayerNorm (warp per row of 256) ----------------
__global__ void ln_kernel(const float* __restrict__ x, const float* __restrict__ w,
                          const float* __restrict__ b, float* __restrict__ out, int n) {
    int row = (blockIdx.x * blockDim.x + threadIdx.x) >> 5;
    if (row >= n) return;
    int lane = threadIdx.x & 31;
    const float4* xp = (const float4*)(x + (size_t)row * HID);
    float4 v0 = xp[lane * 2], v1 = xp[lane * 2 + 1];
    float s  = v0.x + v0.y + v0.z + v0.w + v1.x + v1.y + v1.z + v1.w;
    float sq = v0.x*v0.x + v0.y*v0.y + v0.z*v0.z + v0.w*v0.w
             + v1.x*v1.x + v1.y*v1.y + v1.z*v1.z + v1.w*v1.w;
    #pragma unroll
    for (int o = 16; o > 0; o >>= 1) {
        s  += __shfl_xor_sync(0xffffffffu, s,  o);
        sq += __shfl_xor_sync(0xffffffffu, sq, o);
    }
    float mean = s * (1.0f / HID);
    float var  = sq * (1.0f / HID) - mean * mean;
    float rstd = rsqrtf(var + 1e-5f);
    const float4* wp = (const float4*)w;
    const float4* bp = (const float4*)b;
    float4* op = (float4*)(out + (size_t)row * HID);
    #pragma unroll
    for (int i = 0; i < 2; i++) {
        float4 xv = (i == 0) ? v0 : v1;
        float4 wv = wp[lane * 2 + i], bv = bp[lane * 2 + i];
        float4 o;
        o.x = (xv.x - mean) * rstd * wv.x + bv.x;
        o.y = (xv.y - mean) * rstd * wv.y + bv.y;
        o.z = (xv.z - mean) * rstd * wv.z + bv.z;
        o.w = (xv.w - mean) * rstd * wv.w + bv.w;
        op[lane * 2 + i] = o;
    }
}

// ---------------- x1 = x + conv; store x1; h2 = LN2(x1) ----------------
__global__ void add_ln_kernel(const float* __restrict__ x, const float* __restrict__ conv,
                              const float* __restrict__ w, const float* __restrict__ b,
                              float* __restrict__ x1out, float* __restrict__ hout, int n) {
    int row = (blockIdx.x * blockDim.x + threadIdx.x) >> 5;
    if (row >= n) return;
    int lane = threadIdx.x & 31;
    const float4* xp = (const float4*)(x    + (size_t)row * HID);
    const float4* cp = (const float4*)(conv + (size_t)row * HID);
    float4 a0 = xp[lane * 2], a1 = xp[lane * 2 + 1];
    float4 c0 = cp[lane * 2], c1 = cp[lane * 2 + 1];
    float4 v0 = make_float4(a0.x + c0.x, a0.y + c0.y, a0.z + c0.z, a0.w + c0.w);
    float4 v1 = make_float4(a1.x + c1.x, a1.y + c1.y, a1.z + c1.z, a1.w + c1.w);
    float4* x1p = (float4*)(x1out + (size_t)row * HID);
    x1p[lane * 2]     = v0;
    x1p[lane * 2 + 1] = v1;
    float s  = v0.x + v0.y + v0.z + v0.w + v1.x + v1.y + v1.z + v1.w;
    float sq = v0.x*v0.x + v0.y*v0.y + v0.z*v0.z + v0.w*v0.w
             + v1.x*v1.x + v1.y*v1.y + v1.z*v1.z + v1.w*v1.w;
    #pragma unroll
    for (int o = 16; o > 0; o >>= 1) {
        s  += __shfl_xor_sync(0xffffffffu, s,  o);
        sq += __shfl_xor_sync(0xffffffffu, sq, o);
    }
    float mean = s * (1.0f / HID);
    float var  = sq * (1.0f / HID) - mean * mean;
    float rstd = rsqrtf(var + 1e-5f);
    const float4* wp = (const float4*)w;
    const float4* bp = (const float4*)b;
    float4* op = (float4*)(hout + (size_t)row * HID);
    #pragma unroll
    for (int i = 0; i < 2; i++) {
        float4 xv = (i == 0) ? v0 : v1;
        float4 wv = wp[lane * 2 + i], bv = bp[lane * 2 + i];
        float4 o;
        o.x = (xv.x - mean) * rstd * wv.x + bv.x;
        o.y = (xv.y - mean) * rstd * wv.y + bv.y;
        o.z = (xv.z - mean) * rstd * wv.z + bv.z;
        o.w = (xv.w - mean) * rstd * wv.w + bv.w;
        op[lane * 2 + i] = o;
    }
}

// ---------------- TF32 tensor-core GEMM: C[M,N] = A[M,K] @ W[K,N] + bias ----------------
// 128x128 CTA tile, BK=16 double-buffered, 8 warps (2x4), 64x32 per warp.
// EPI 0: bias only; 1: bias+GELU; 2: bias + residual add
template<int EPI>
__global__ __launch_bounds__(256)
void gemm_tf32(const float* __restrict__ A, const float* __restrict__ W,
               const float* __restrict__ bias, const float* __restrict__ res,
               float* __restrict__ C, int M, int N, int K) {
    __shared__ uint32_t As[2][128][20];   // [m][k], pad 4 -> conflict-free frag loads
    __shared__ uint32_t Bs[2][16][132];   // [k][n], pad 4

    const int t = threadIdx.x;
    const int lane = t & 31, wid = t >> 5;
    const int wm = wid & 1, wn = wid >> 1;          // 2 x 4 warp grid
    const int mBase = blockIdx.x * 128;
    const int nBase = blockIdx.y * 128;
    const int lr = lane >> 2, lc = lane & 3;        // fragment row/col components

    // global-load assignments
    const int rA = t >> 2,  cA = (t & 3) * 4;       // A: rows rA, rA+64; cols cA..cA+3
    const int rB = t >> 5,  cB = (t & 31) * 4;      // B: rows rB, rB+8;  cols cB..cB+3

    float acc[4][4][4];
    #pragma unroll
    for (int i = 0; i < 4; i++)
        #pragma unroll
        for (int j = 0; j < 4; j++)
            #pragma unroll
            for (int r = 0; r < 4; r++) acc[i][j][r] = 0.0f;

    const int NK = K >> 4;
    float4 pa0, pa1, pb0, pb1;

    // prologue: load kb=0
    {
        int gr0 = mBase + rA, gr1 = gr0 + 64;
        pa0 = (gr0 < M) ? *(const float4*)(A + (size_t)gr0 * K + cA) : make_float4(0,0,0,0);
        pa1 = (gr1 < M) ? *(const float4*)(A + (size_t)gr1 * K + cA) : make_float4(0,0,0,0);
        pb0 = *(const float4*)(W + (size_t)rB       * N + nBase + cB);
        pb1 = *(const float4*)(W + (size_t)(rB + 8) * N + nBase + cB);
        uint32_t* d0 = &As[0][rA][cA];
        d0[0]=f2tf(pa0.x); d0[1]=f2tf(pa0.y); d0[2]=f2tf(pa0.z); d0[3]=f2tf(pa0.w);
        uint32_t* d1 = &As[0][rA + 64][cA];
        d1[0]=f2tf(pa1.x); d1[1]=f2tf(pa1.y); d1[2]=f2tf(pa1.z); d1[3]=f2tf(pa1.w);
        uint32_t* e0 = &Bs[0][rB][cB];
        e0[0]=f2tf(pb0.x); e0[1]=f2tf(pb0.y); e0[2]=f2tf(pb0.z); e0[3]=f2tf(pb0.w);
        uint32_t* e1 = &Bs[0][rB + 8][cB];
        e1[0]=f2tf(pb1.x); e1[1]=f2tf(pb1.y); e1[2]=f2tf(pb1.z); e1[3]=f2tf(pb1.w);
    }
    __syncthreads();

    for (int kb = 0; kb < NK; kb++) {
        const int buf = kb & 1;
        const bool more = (kb + 1 < NK);
        if (more) {
            int kofs = (kb + 1) * 16;
            int gr0 = mBase + rA, gr1 = gr0 + 64;
            pa0 = (gr0 < M) ? *(const float4*)(A + (size_t)gr0 * K + kofs + cA) : make_float4(0,0,0,0);
            pa1 = (gr1 < M) ? *(const float4*)(A + (size_t)gr1 * K + kofs + cA) : make_float4(0,0,0,0);
            pb0 = *(const float4*)(W + (size_t)(kofs + rB)     * N + nBase + cB);
            pb1 = *(const float4*)(W + (size_t)(kofs + rB + 8) * N + nBase + cB);
        }
        // compute on buf
        #pragma unroll
        for (int ks = 0; ks < 2; ks++) {
            const int kk = ks * 8 + lc;
            uint32_t a[4][4], b[4][2];
            #pragma unroll
            for (int mt = 0; mt < 4; mt++) {
                int r = wm * 64 + mt * 16 + lr;
                a[mt][0] = As[buf][r][kk];
                a[mt][1] = As[buf][r + 8][kk];
                a[mt][2] = As[buf][r][kk + 4];
                a[mt][3] = As[buf][r + 8][kk + 4];
            }
            #pragma unroll
            for (int nt = 0; nt < 4; nt++) {
                int c = wn * 32 + nt * 8 + lr;
                b[nt][0] = Bs[buf][ks * 8 + lc][c];
                b[nt][1] = Bs[buf][ks * 8 + 4 + lc][c];
            }
            #pragma unroll
            for (int mt = 0; mt < 4; mt++)
                #pragma unroll
                for (int nt = 0; nt < 4; nt++)
                    mma_tf32(acc[mt][nt], a[mt], b[nt]);
        }
        if (more) {
            int nb = buf ^ 1;
            uint32_t* d0 = &As[nb][rA][cA];
            d0[0]=f2tf(pa0.x); d0[1]=f2tf(pa0.y); d0[2]=f2tf(pa0.z); d0[3]=f2tf(pa0.w);
            uint32_t* d1 = &As[nb][rA + 64][cA];
            d1[0]=f2tf(pa1.x); d1[1]=f2tf(pa1.y); d1[2]=f2tf(pa1.z); d1[3]=f2tf(pa1.w);
            uint32_t* e0 = &Bs[nb][rB][cB];
            e0[0]=f2tf(pb0.x); e0[1]=f2tf(pb0.y); e0[2]=f2tf(pb0.z); e0[3]=f2tf(pb0.w);
            uint32_t* e1 = &Bs[nb][rB + 8][cB];
            e1[0]=f2tf(pb1.x); e1[1]=f2tf(pb1.y); e1[2]=f2tf(pb1.z); e1[3]=f2tf(pb1.w);
        }
        __syncthreads();
    }

    // epilogue: per fragment, rows lr and lr+8, cols 2*lc, 2*lc+1
    #pragma unroll
    for (int mt = 0; mt < 4; mt++) {
        int r0 = mBase + wm * 64 + mt * 16 + lr;
        #pragma unroll
        for (int nt = 0; nt < 4; nt++) {
            int col = nBase + wn * 32 + nt * 8 + lc * 2;
            float2 bv = *(const float2*)(bias + col);
            float* cc = acc[mt][nt];
            if (r0 < M) {
                float2 o = make_float2(cc[0] + bv.x, cc[1] + bv.y);
                if (EPI == 1) { o.x = gelu_exact(o.x); o.y = gelu_exact(o.y); }
                if (EPI == 2) {
                    float2 rv = *(const float2*)(res + (size_t)r0 * N + col);
                    o.x += rv.x; o.y += rv.y;
                }
                *(float2*)(C + (size_t)r0 * N + col) = o;
            }
            int r1 = r0 + 8;
            if (r1 < M) {
                float2 o = make_float2(cc[2] + bv.x, cc[3] + bv.y);
                if (EPI == 1) { o.x = gelu_exact(o.x); o.y = gelu_exact(o.y); }
                if (EPI == 2) {
                    float2 rv = *(const float2*)(res + (size_t)r1 * N + col);
                    o.x += rv.x; o.y += rv.y;
                }
                *(float2*)(C + (size_t)r1 * N + col) = o;
            }
        }
    }
}

// ---------------- edge scores (warp per edge): s[e,h] = q[dst,h,:]·k[src,h,:]/8 ----------------
__global__ void edge_scores_kernel(const int* __restrict__ ei,
                                   const float* __restrict__ q, const float* __restrict__ k,
                                   float* __restrict__ scores, unsigned* __restrict__ mkey, int E) {
    int e = (blockIdx.x * blockDim.x + threadIdx.x) >> 5;
    if (e >= E) return;
    int lane = threadIdx.x & 31;
    int is64 = g_is64;
    int src = load_idx(ei, e, is64);
    int dst = load_idx(ei, E + e, is64);
    const float4* qp = (const float4*)(q + (size_t)dst * HID) + lane * 2;
    const float4* kp = (const float4*)(k + (size_t)src * HID) + lane * 2;
    float4 a0 = qp[0], a1 = qp[1];
    float4 b0 = kp[0], b1 = kp[1];
    float d = a0.x*b0.x + a0.y*b0.y + a0.z*b0.z + a0.w*b0.w
            + a1.x*b1.x + a1.y*b1.y + a1.z*b1.z + a1.w*b1.w;
    d += __shfl_xor_sync(0xffffffffu, d, 1);
    d += __shfl_xor_sync(0xffffffffu, d, 2);
    d += __shfl_xor_sync(0xffffffffu, d, 4);
    if ((lane & 7) == 0) {
        int h = lane >> 3;
        float s = d * 0.125f;   // 1/sqrt(64)
        scores[(size_t)e * NHEAD + h] = s;
        atomicMax(&mkey[dst * NHEAD + h], fkey(s));
    }
}

// ---------------- exp + denominator (thread per (edge, head)) ----------------
__global__ void edge_exp_kernel(const int* __restrict__ ei,
                                float* __restrict__ scores,
                                const unsigned* __restrict__ mkey,
                                float* __restrict__ den, int E) {
    int idx = blockIdx.x * blockDim.x + threadIdx.x;
    if (idx >= E * NHEAD) return;
    int e = idx >> 2, h = idx & 3;
    int dst = load_idx(ei, E + e, g_is64);
    float m = funkey(mkey[dst * NHEAD + h]);
    float w = __expf(scores[idx] - m);
    scores[idx] = w;
    atomicAdd(&den[dst * NHEAD + h], w);
}

// ---------------- aggregate (warp per edge): conv[dst] += attn * v[src] ----------------
__global__ void edge_agg_kernel(const int* __restrict__ ei,
                                const float* __restrict__ scores, const float* __restrict__ den,
                                const float* __restrict__ v, float* __restrict__ conv, int E) {
    int e = (blockIdx.x * blockDim.x + threadIdx.x) >> 5;
    if (e >= E) return;
    int lane = threadIdx.x & 31;
    int is64 = g_is64;
    int src = load_idx(ei, e, is64);
    int dst = load_idx(ei, E + e, is64);
    int h = lane >> 3;
    float attn = scores[(size_t)e * NHEAD + h] / den[dst * NHEAD + h];
    const float4* vp = (const float4*)(v + (size_t)src * HID) + lane * 2;
    float4 v0 = vp[0], v1 = vp[1];
    float* op = conv + (size_t)dst * HID + lane * 8;
    red_add_v4(op,     attn * v0.x, attn * v0.y, attn * v0.z, attn * v0.w);
    red_add_v4(op + 4, attn * v1.x, attn * v1.y, attn * v1.z, attn * v1.w);
}

// ---------------- host launch ----------------
extern "C" void kernel_launch(void* const* d_in, const int* in_sizes, int n_in,
                              void* d_out, int out_size) {
    const float* x     = (const float*)d_in[0];
    const int*   ei    = (const int*)d_in[1];      // int32 or int64; detected on device
    const float* ln1_w = (const float*)d_in[2];
    const float* ln1_b = (const float*)d_in[3];
    const float* ln2_w = (const float*)d_in[4];
    const float* ln2_b = (const float*)d_in[5];
    const float* wq    = (const float*)d_in[6];
    const float* bq    = (const float*)d_in[7];
    const float* wk    = (const float*)d_in[8];
    const float* bk    = (const float*)d_in[9];
    const float* wv    = (const float*)d_in[10];
    const float* bv    = (const float*)d_in[11];
    const float* wskip = (const float*)d_in[12];
    const float* bskip = (const float*)d_in[13];
    const float* w1    = (const float*)d_in[14];
    const float* b1    = (const float*)d_in[15];
    const float* w2    = (const float*)d_in[16];
    const float* b2    = (const float*)d_in[17];

    int n = in_sizes[0] / HID;
    int E = in_sizes[1] / 2;

    static float *h = nullptr, *q, *k, *v, *conv, *x1, *mid, *scores, *den;
    static unsigned* mkey;
    if (!h) {   // resolved on the first (uncaptured) correctness call; pure address lookup
        cudaGetSymbolAddress((void**)&h,      g_h);
        cudaGetSymbolAddress((void**)&q,      g_q);
        cudaGetSymbolAddress((void**)&k,      g_k);
        cudaGetSymbolAddress((void**)&v,      g_v);
        cudaGetSymbolAddress((void**)&conv,   g_conv);
        cudaGetSymbolAddress((void**)&x1,     g_x1);
        cudaGetSymbolAddress((void**)&mid,    g_mid);
        cudaGetSymbolAddress((void**)&scores, g_scores);
        cudaGetSymbolAddress((void**)&den,    g_den);
        cudaGetSymbolAddress((void**)&mkey,   g_mkey);
    }

    detect_kernel<<<1, 32>>>(ei, E);
    init_kernel<<<(n * NHEAD + 255) / 256, 256>>>(mkey, den, n * NHEAD);
    ln_kernel<<<(n * 32 + 255) / 256, 256>>>(x, ln1_w, ln1_b, h, n);

    dim3 g1((n + 127) / 128, HID / 128);           // 157 x 2
    gemm_tf32<0><<<g1, 256>>>(h, wq, bq, nullptr, q,    n, HID, HID);
    gemm_tf32<0><<<g1, 256>>>(h, wk, bk, nullptr, k,    n, HID, HID);
    gemm_tf32<0><<<g1, 256>>>(h, wv, bv, nullptr, v,    n, HID, HID);
    gemm_tf32<0><<<g1, 256>>>(h, wskip, bskip, nullptr, conv, n, HID, HID);

    edge_scores_kernel<<<(E + 7) / 8, 256>>>(ei, q, k, scores, mkey, E);
    edge_exp_kernel<<<(E * NHEAD + 255) / 256, 256>>>(ei, scores, mkey, den, E);
    edge_agg_kernel<<<(E + 7) / 8, 256>>>(ei, scores, den, v, conv, E);

    add_ln_kernel<<<(n * 32 + 255) / 256, 256>>>(x, conv, ln2_w, ln2_b, x1, h, n);

    dim3 g2((n + 127) / 128, (2 * HID) / 128);     // 157 x 4
    gemm_tf32<1><<<g2, 256>>>(h, w1, b1, nullptr, mid, n, 2 * HID, HID);

    dim3 g3((n + 127) / 128, HID / 128);           // 157 x 2
    gemm_tf32<2><<<g3, 256>>>(mid, w2, b2, x1, (float*)d_out, n, HID, 2 * HID);
}

// round 6
// speedup vs baseline: 2.0841x; 1.0261x over previous
#include <cuda_runtime.h>
#include <cstdint>

#define HID 256
#define NHEAD 4
#define MAXN 20000
#define MAXE 320000

// ---------------- scratch (device globals; no allocation allowed) ----------------
__device__ float    g_h   [(size_t)MAXN * HID];        // ln1 out, reused as h2
__device__ float    g_q   [(size_t)MAXN * HID];
__device__ float    g_k   [(size_t)MAXN * HID];
__device__ float    g_v   [(size_t)MAXN * HID];
__device__ float    g_skip[(size_t)MAXN * HID];        // skip projection
__device__ float    g_agg [(size_t)MAXN * HID];        // unnormalized edge aggregate
__device__ float    g_x1  [(size_t)MAXN * HID];        // x + conv
__device__ float    g_mid [(size_t)MAXN * 2 * HID];    // FF hidden
__device__ float    g_scores[(size_t)MAXE * NHEAD];    // logits
__device__ unsigned g_mkey[MAXN * NHEAD];              // segment-max keys
__device__ float    g_den [MAXN * NHEAD];              // softmax denominators
__device__ int      g_is64;                            // edge_index stored as int64?

// ---------------- helpers ----------------
__device__ __forceinline__ unsigned fkey(float x) {
    unsigned u = __float_as_uint(x);
    return (u & 0x80000000u) ? ~u : (u | 0x80000000u);
}
__device__ __forceinline__ float funkey(unsigned u) {
    u = (u & 0x80000000u) ? (u & 0x7fffffffu) : ~u;
    return __uint_as_float(u);
}
__device__ __forceinline__ int load_idx(const int* __restrict__ ei, int pos, int is64) {
    return is64 ? ei[(size_t)pos * 2] : ei[pos];   // little-endian low word
}
__device__ __forceinline__ void red_add_v4(float* p, float a, float b, float c, float d) {
    asm volatile("red.global.add.v4.f32 [%0], {%1,%2,%3,%4};"
                 :: "l"(p), "f"(a), "f"(b), "f"(c), "f"(d) : "memory");
}
__device__ __forceinline__ float gelu_exact(float v) {
    return 0.5f * v * (1.0f + erff(v * 0.7071067811865476f));
}
__device__ __forceinline__ uint32_t f2tf(float x) {
    uint32_t r; asm("cvt.rna.tf32.f32 %0, %1;" : "=r"(r) : "f"(x)); return r;
}
__device__ __forceinline__ void mma_tf32(float* c, uint32_t a0, uint32_t a1, uint32_t a2,
                                         uint32_t a3, uint32_t b0, uint32_t b1) {
    asm volatile("mma.sync.aligned.m16n8k8.row.col.f32.tf32.tf32.f32 "
                 "{%0,%1,%2,%3}, {%4,%5,%6,%7}, {%8,%9}, {%0,%1,%2,%3};"
                 : "+f"(c[0]), "+f"(c[1]), "+f"(c[2]), "+f"(c[3])
                 : "r"(a0), "r"(a1), "r"(a2), "r"(a3), "r"(b0), "r"(b1));
}

// ---------------- dtype detection (1 warp) ----------------
__global__ void detect_kernel(const int* __restrict__ ei, int E) {
    int lane = threadIdx.x;
    int nz = 0;
    for (int i = lane; i < 512 && i < E; i += 32)
        nz |= ei[2 * i + 1];
    #pragma unroll
    for (int o = 16; o > 0; o >>= 1) nz |= __shfl_xor_sync(0xffffffffu, nz, o);
    if (lane == 0) g_is64 = (nz == 0) ? 1 : 0;
}

// ---------------- init: zero mkey/den and agg ----------------
__global__ void init_kernel(unsigned* __restrict__ mkey, float* __restrict__ den,
                            float* __restrict__ agg, int nh, int total) {
    int i = blockIdx.x * blockDim.x + threadIdx.x;
    if (i < nh) { mkey[i] = 0u; den[i] = 0.0f; }
    int j4 = i;
    if (j4 * 4 < total) ((float4*)agg)[j4] = make_float4(0.f, 0.f, 0.f, 0.f);
}

// ---------------- LayerNorm (warp per row of 256) ----------------
__global__ void ln_kernel(const float* __restrict__ x, const float* __restrict__ w,
                          const float* __restrict__ b, float* __restrict__ out, int n) {
    int row = (blockIdx.x * blockDim.x + threadIdx.x) >> 5;
    if (row >= n) return;
    int lane = threadIdx.x & 31;
    const float4* xp = (const float4*)(x + (size_t)row * HID);
    float4 v0 = xp[lane * 2], v1 = xp[lane * 2 + 1];
    float s  = v0.x + v0.y + v0.z + v0.w + v1.x + v1.y + v1.z + v1.w;
    float sq = v0.x*v0.x + v0.y*v0.y + v0.z*v0.z + v0.w*v0.w
             + v1.x*v1.x + v1.y*v1.y + v1.z*v1.z + v1.w*v1.w;
    #pragma unroll
    for (int o = 16; o > 0; o >>= 1) {
        s  += __shfl_xor_sync(0xffffffffu, s,  o);
        sq += __shfl_xor_sync(0xffffffffu, sq, o);
    }
    float mean = s * (1.0f / HID);
    float var  = sq * (1.0f / HID) - mean * mean;
    float rstd = rsqrtf(var + 1e-5f);
    const float4* wp = (const float4*)w;
    const float4* bp = (const float4*)b;
    float4* op = (float4*)(out + (size_t)row * HID);
    #pragma unroll
    for (int i = 0; i < 2; i++) {
        float4 xv = (i == 0) ? v0 : v1;
        float4 wv = wp[lane * 2 + i], bv = bp[lane * 2 + i];
        float4 o;
        o.x = (xv.x - mean) * rstd * wv.x + bv.x;
        o.y = (xv.y - mean) * rstd * wv.y + bv.y;
        o.z = (xv.z - mean) * rstd * wv.z + bv.z;
        o.w = (xv.w - mean) * rstd * wv.w + bv.w;
        op[lane * 2 + i] = o;
    }
}

// ---------------- x1 = x + skip + agg/den; h2 = LN2(x1) ----------------
__global__ void add_ln_kernel(const float* __restrict__ x, const float* __restrict__ skip,
                              const float* __restrict__ agg, const float* __restrict__ den,
                              const float* __restrict__ w, const float* __restrict__ b,
                              float* __restrict__ x1out, float* __restrict__ hout, int n) {
    int row = (blockIdx.x * blockDim.x + threadIdx.x) >> 5;
    if (row >= n) return;
    int lane = threadIdx.x & 31;
    int h = lane >> 3;                                  // lane covers cols lane*8..+7: one head
    float d = den[row * NHEAD + h];
    float rden = (d > 0.0f) ? (1.0f / d) : 0.0f;
    const float4* xp = (const float4*)(x    + (size_t)row * HID);
    const float4* sp = (const float4*)(skip + (size_t)row * HID);
    const float4* ap = (const float4*)(agg  + (size_t)row * HID);
    float4 a0 = xp[lane * 2], a1 = xp[lane * 2 + 1];
    float4 c0 = sp[lane * 2], c1 = sp[lane * 2 + 1];
    float4 g0 = ap[lane * 2], g1 = ap[lane * 2 + 1];
    float4 v0 = make_float4(a0.x + c0.x + g0.x * rden, a0.y + c0.y + g0.y * rden,
                            a0.z + c0.z + g0.z * rden, a0.w + c0.w + g0.w * rden);
    float4 v1 = make_float4(a1.x + c1.x + g1.x * rden, a1.y + c1.y + g1.y * rden,
                            a1.z + c1.z + g1.z * rden, a1.w + c1.w + g1.w * rden);
    float4* x1p = (float4*)(x1out + (size_t)row * HID);
    x1p[lane * 2]     = v0;
    x1p[lane * 2 + 1] = v1;
    float s  = v0.x + v0.y + v0.z + v0.w + v1.x + v1.y + v1.z + v1.w;
    float sq = v0.x*v0.x + v0.y*v0.y + v0.z*v0.z + v0.w*v0.w
             + v1.x*v1.x + v1.y*v1.y + v1.z*v1.z + v1.w*v1.w;
    #pragma unroll
    for (int o = 16; o > 0; o >>= 1) {
        s  += __shfl_xor_sync(0xffffffffu, s,  o);
        sq += __shfl_xor_sync(0xffffffffu, sq, o);
    }
    float mean = s * (1.0f / HID);
    float var  = sq * (1.0f / HID) - mean * mean;
    float rstd = rsqrtf(var + 1e-5f);
    const float4* wp = (const float4*)w;
    const float4* bp = (const float4*)b;
    float4* op = (float4*)(hout + (size_t)row * HID);
    #pragma unroll
    for (int i = 0; i < 2; i++) {
        float4 xv = (i == 0) ? v0 : v1;
        float4 wv = wp[lane * 2 + i], bv = bp[lane * 2 + i];
        float4 o;
        o.x = (xv.x - mean) * rstd * wv.x + bv.x;
        o.y = (xv.y - mean) * rstd * wv.y + bv.y;
        o.z = (xv.z - mean) * rstd * wv.z + bv.z;
        o.w = (xv.w - mean) * rstd * wv.w + bv.w;
        op[lane * 2 + i] = o;
    }
}

// ---------------- TF32 GEMM, MMA-native permuted smem, multi-weight via blockIdx.z ------
struct GemmPtrs { const float* W[4]; const float* bias[4]; float* out[4]; };

__device__ __forceinline__ void storeA(uint32_t* As, int m, int k0, float4 v) {
    int mt = m >> 4, s1 = (m >> 3) & 1, lr = m & 7;
    int ks = k0 >> 3, s2 = (k0 >> 2) & 1;
    int e = s1 * 2 + s2;
    int blk = (mt * 2 + ks) * 32;
    float f[4] = {v.x, v.y, v.z, v.w};
    #pragma unroll
    for (int j = 0; j < 4; j++) {
        int la = 4 * lr + j;
        la ^= (la >> 3) & 3;
        As[(blk + la) * 4 + e] = f2tf(f[j]);
    }
}
__device__ __forceinline__ void storeB(uint32_t* Bs, int k, int n0, float4 v) {
    int ks = k >> 3, s = (k >> 2) & 1, lcb = k & 3;
    float f[4] = {v.x, v.y, v.z, v.w};
    #pragma unroll
    for (int j = 0; j < 4; j++) {
        int n = n0 + j;
        int nt = n >> 3, lrb = n & 7;
        int lb = (4 * lrb + lcb) ^ nt;
        Bs[((nt * 2 + ks) * 32 + lb) * 2 + s] = f2tf(f[j]);
    }
}

template<int EPI>
__global__ __launch_bounds__(256)
void gemm_tf32(const float* __restrict__ A, GemmPtrs p,
               const float* __restrict__ res, int M, int N, int K) {
    __shared__ __align__(16) uint32_t As[2][2048];   // 8KB each
    __shared__ __align__(16) uint32_t Bs[2][2048];

    const float* __restrict__ W    = p.W[blockIdx.z];
    const float* __restrict__ bias = p.bias[blockIdx.z];
    float* __restrict__       C    = p.out[blockIdx.z];

    const int t = threadIdx.x;
    const int lane = t & 31, wid = t >> 5;
    const int wm = wid & 1, wn = wid >> 1;          // 2 x 4 warp grid
    const int mBase = blockIdx.x * 128;
    const int nBase = blockIdx.y * 128;
    const int lr = lane >> 2, lc = lane & 3;

    const int rA = t >> 2,  cA = (t & 3) * 4;       // A: rows rA, rA+64; k cols cA..cA+3
    const int rB = t >> 5,  cB = (t & 31) * 4;      // B: k rows rB, rB+8; cols cB..cB+3

    const int laneA = lane ^ ((lane >> 3) & 3);     // swizzled A read lane

    float acc[4][4][4];
    #pragma unroll
    for (int i = 0; i < 4; i++)
        #pragma unroll
        for (int j = 0; j < 4; j++)
            #pragma unroll
            for (int r = 0; r < 4; r++) acc[i][j][r] = 0.0f;

    const int NK = K >> 4;
    float4 pa0, pa1, pb0, pb1;

    {   // prologue kb=0
        int gr0 = mBase + rA, gr1 = gr0 + 64;
        pa0 = (gr0 < M) ? *(const float4*)(A + (size_t)gr0 * K + cA) : make_float4(0,0,0,0);
        pa1 = (gr1 < M) ? *(const float4*)(A + (size_t)gr1 * K + cA) : make_float4(0,0,0,0);
        pb0 = *(const float4*)(W + (size_t)rB       * N + nBase + cB);
        pb1 = *(const float4*)(W + (size_t)(rB + 8) * N + nBase + cB);
        storeA(As[0], rA,      cA, pa0);
        storeA(As[0], rA + 64, cA, pa1);
        storeB(Bs[0], rB,      cB, pb0);
        storeB(Bs[0], rB + 8,  cB, pb1);
    }
    __syncthreads();

    for (int kb = 0; kb < NK; kb++) {
        const int buf = kb & 1;
        const bool more = (kb + 1 < NK);
        if (more) {
            int kofs = (kb + 1) * 16;
            int gr0 = mBase + rA, gr1 = gr0 + 64;
            pa0 = (gr0 < M) ? *(const float4*)(A + (size_t)gr0 * K + kofs + cA) : make_float4(0,0,0,0);
            pa1 = (gr1 < M) ? *(const float4*)(A + (size_t)gr1 * K + kofs + cA) : make_float4(0,0,0,0);
            pb0 = *(const float4*)(W + (size_t)(kofs + rB)     * N + nBase + cB);
            pb1 = *(const float4*)(W + (size_t)(kofs + rB + 8) * N + nBase + cB);
        }
        #pragma unroll
        for (int ks = 0; ks < 2; ks++) {
            uint4 a[4]; uint2 b[4];
            #pragma unroll
            for (int mt = 0; mt < 4; mt++) {
                int mt_g = wm * 4 + mt;
                a[mt] = *(const uint4*)&As[buf][((mt_g * 2 + ks) * 32 + laneA) * 4];
            }
            #pragma unroll
            for (int nt = 0; nt < 4; nt++) {
                int nt_g = wn * 4 + nt;
                b[nt] = *(const uint2*)&Bs[buf][((nt_g * 2 + ks) * 32 + (lane ^ nt_g)) * 2];
            }
            #pragma unroll
            for (int mt = 0; mt < 4; mt++)
                #pragma unroll
                for (int nt = 0; nt < 4; nt++)
                    mma_tf32(acc[mt][nt], a[mt].x, a[mt].z, a[mt].y, a[mt].w,
                             b[nt].x, b[nt].y);
        }
        if (more) {
            int nb = buf ^ 1;
            storeA(As[nb], rA,      cA, pa0);
            storeA(As[nb], rA + 64, cA, pa1);
            storeB(Bs[nb], rB,      cB, pb0);
            storeB(Bs[nb], rB + 8,  cB, pb1);
        }
        __syncthreads();
    }

    // epilogue: per fragment, rows lr and lr+8, cols 2*lc, 2*lc+1
    #pragma unroll
    for (int mt = 0; mt < 4; mt++) {
        int r0 = mBase + wm * 64 + mt * 16 + lr;
        #pragma unroll
        for (int nt = 0; nt < 4; nt++) {
            int col = nBase + wn * 32 + nt * 8 + lc * 2;
            float2 bv = *(const float2*)(bias + col);
            float* cc = acc[mt][nt];
            if (r0 < M) {
                float2 o = make_float2(cc[0] + bv.x, cc[1] + bv.y);
                if (EPI == 1) { o.x = gelu_exact(o.x); o.y = gelu_exact(o.y); }
                if (EPI == 2) {
                    float2 rv = *(const float2*)(res + (size_t)r0 * N + col);
                    o.x += rv.x; o.y += rv.y;
                }
                *(float2*)(C + (size_t)r0 * N + col) = o;
            }
            int r1 = r0 + 8;
            if (r1 < M) {
                float2 o = make_float2(cc[2] + bv.x, cc[3] + bv.y);
                if (EPI == 1) { o.x = gelu_exact(o.x); o.y = gelu_exact(o.y); }
                if (EPI == 2) {
                    float2 rv = *(const float2*)(res + (size_t)r1 * N + col);
                    o.x += rv.x; o.y += rv.y;
                }
                *(float2*)(C + (size_t)r1 * N + col) = o;
            }
        }
    }
}

// ---------------- edge scores (warp per edge) ----------------
__global__ void edge_scores_kernel(const int* __restrict__ ei,
                                   const float* __restrict__ q, const float* __restrict__ k,
                                   float* __restrict__ scores, unsigned* __restrict__ mkey, int E) {
    int e = (blockIdx.x * blockDim.x + threadIdx.x) >> 5;
    if (e >= E) return;
    int lane = threadIdx.x & 31;
    int is64 = g_is64;
    int src = load_idx(ei, e, is64);
    int dst = load_idx(ei, E + e, is64);
    const float4* qp = (const float4*)(q + (size_t)dst * HID) + lane * 2;
    const float4* kp = (const float4*)(k + (size_t)src * HID) + lane * 2;
    float4 a0 = qp[0], a1 = qp[1];
    float4 b0 = kp[0], b1 = kp[1];
    float d = a0.x*b0.x + a0.y*b0.y + a0.z*b0.z + a0.w*b0.w
            + a1.x*b1.x + a1.y*b1.y + a1.z*b1.z + a1.w*b1.w;
    d += __shfl_xor_sync(0xffffffffu, d, 1);
    d += __shfl_xor_sync(0xffffffffu, d, 2);
    d += __shfl_xor_sync(0xffffffffu, d, 4);
    if ((lane & 7) == 0) {
        int h = lane >> 3;
        float s = d * 0.125f;   // 1/sqrt(64)
        scores[(size_t)e * NHEAD + h] = s;
        atomicMax(&mkey[dst * NHEAD + h], fkey(s));
    }
}

// ---------------- fused exp + aggregate (warp per edge) ----------------
// w = exp(s - m[dst]); den += w; agg[dst] += w * v[src]  (normalize later in add_ln)
__global__ void edge_exp_agg_kernel(const int* __restrict__ ei,
                                    const float* __restrict__ scores,
                                    const unsigned* __restrict__ mkey,
                                    float* __restrict__ den,
                                    const float* __restrict__ v,
                                    float* __restrict__ agg, int E) {
    int e = (blockIdx.x * blockDim.x + threadIdx.x) >> 5;
    if (e >= E) return;
    int lane = threadIdx.x & 31;
    int is64 = g_is64;
    int src = load_idx(ei, e, is64);
    int dst = load_idx(ei, E + e, is64);
    int h = lane >> 3;
    float s = scores[(size_t)e * NHEAD + h];
    float m = funkey(mkey[dst * NHEAD + h]);
    float w = __expf(s - m);
    if ((lane & 7) == 0) atomicAdd(&den[dst * NHEAD + h], w);
    const float4* vp = (const float4*)(v + (size_t)src * HID) + lane * 2;
    float4 v0 = vp[0], v1 = vp[1];
    float* op = agg + (size_t)dst * HID + lane * 8;
    red_add_v4(op,     w * v0.x, w * v0.y, w * v0.z, w * v0.w);
    red_add_v4(op + 4, w * v1.x, w * v1.y, w * v1.z, w * v1.w);
}

// ---------------- host launch ----------------
extern "C" void kernel_launch(void* const* d_in, const int* in_sizes, int n_in,
                              void* d_out, int out_size) {
    const float* x     = (const float*)d_in[0];
    const int*   ei    = (const int*)d_in[1];
    const float* ln1_w = (const float*)d_in[2];
    const float* ln1_b = (const float*)d_in[3];
    const float* ln2_w = (const float*)d_in[4];
    const float* ln2_b = (const float*)d_in[5];
    const float* wq    = (const float*)d_in[6];
    const float* bq    = (const float*)d_in[7];
    const float* wk    = (const float*)d_in[8];
    const float* bk    = (const float*)d_in[9];
    const float* wv    = (const float*)d_in[10];
    const float* bv    = (const float*)d_in[11];
    const float* wskip = (const float*)d_in[12];
    const float* bskip = (const float*)d_in[13];
    const float* w1    = (const float*)d_in[14];
    const float* b1    = (const float*)d_in[15];
    const float* w2    = (const float*)d_in[16];
    const float* b2    = (const float*)d_in[17];

    int n = in_sizes[0] / HID;
    int E = in_sizes[1] / 2;

    static float *h = nullptr, *q, *k, *v, *skip, *agg, *x1, *mid, *scores, *den;
    static unsigned* mkey;
    if (!h) {
        cudaGetSymbolAddress((void**)&h,      g_h);
        cudaGetSymbolAddress((void**)&q,      g_q);
        cudaGetSymbolAddress((void**)&k,      g_k);
        cudaGetSymbolAddress((void**)&v,      g_v);
        cudaGetSymbolAddress((void**)&skip,   g_skip);
        cudaGetSymbolAddress((void**)&agg,    g_agg);
        cudaGetSymbolAddress((void**)&x1,     g_x1);
        cudaGetSymbolAddress((void**)&mid,    g_mid);
        cudaGetSymbolAddress((void**)&scores, g_scores);
        cudaGetSymbolAddress((void**)&den,    g_den);
        cudaGetSymbolAddress((void**)&mkey,   g_mkey);
    }

    detect_kernel<<<1, 32>>>(ei, E);
    {
        int tot = n * HID;                // agg floats (multiple of 4)
        int work = tot / 4;               // float4 count >= n*NHEAD
        init_kernel<<<(work + 255) / 256, 256>>>(mkey, den, agg, n * NHEAD, tot);
    }
    ln_kernel<<<(n * 32 + 255) / 256, 256>>>(x, ln1_w, ln1_b, h, n);

    // fused Q/K/V/skip projections: grid.z selects weight set
    {
        GemmPtrs p;
        p.W[0] = wq;   p.bias[0] = bq;    p.out[0] = q;
        p.W[1] = wk;   p.bias[1] = bk;    p.out[1] = k;
        p.W[2] = wv;   p.bias[2] = bv;    p.out[2] = v;
        p.W[3] = wskip;p.bias[3] = bskip; p.out[3] = skip;
        dim3 g((n + 127) / 128, HID / 128, 4);     // 157 x 2 x 4
        gemm_tf32<0><<<g, 256>>>(h, p, nullptr, n, HID, HID);
    }

    edge_scores_kernel<<<(E + 7) / 8, 256>>>(ei, q, k, scores, mkey, E);
    edge_exp_agg_kernel<<<(E + 7) / 8, 256>>>(ei, scores, mkey, den, v, agg, E);

    add_ln_kernel<<<(n * 32 + 255) / 256, 256>>>(x, skip, agg, den, ln2_w, ln2_b, x1, h, n);

    {
        GemmPtrs p;
        p.W[0] = w1; p.bias[0] = b1; p.out[0] = mid;
        dim3 g((n + 127) / 128, (2 * HID) / 128, 1);   // 157 x 4
        gemm_tf32<1><<<g, 256>>>(h, p, nullptr, n, 2 * HID, HID);
    }
    {
        GemmPtrs p;
        p.W[0] = w2; p.bias[0] = b2; p.out[0] = (float*)d_out;
        dim3 g((n + 127) / 128, HID / 128, 1);         // 157 x 2
        gemm_tf32<2><<<g, 256>>>(mid, p, x1, n, HID, 2 * HID);
    }
}

// round 7
// speedup vs baseline: 2.1514x; 1.0323x over previous
#include <cuda_runtime.h>
#include <cstdint>

#define HID 256
#define NHEAD 4
#define MAXN 20000
#define MAXE 320000

// ---------------- scratch (device globals; no allocation allowed) ----------------
__device__ uint32_t g_h   [(size_t)MAXN * HID];        // ln1 out (tf32), reused as h2
__device__ float    g_q   [(size_t)MAXN * HID];
__device__ float    g_k   [(size_t)MAXN * HID];
__device__ float    g_v   [(size_t)MAXN * HID];
__device__ float    g_skip[(size_t)MAXN * HID];        // skip projection
__device__ float    g_agg [(size_t)MAXN * HID];        // unnormalized edge aggregate
__device__ float    g_x1  [(size_t)MAXN * HID];        // x + conv
__device__ uint32_t g_mid [(size_t)MAXN * 2 * HID];    // FF hidden (tf32)
__device__ float    g_scores[(size_t)MAXE * NHEAD];    // logits
__device__ unsigned g_mkey[MAXN * NHEAD];              // segment-max keys
__device__ float    g_den [MAXN * NHEAD];              // softmax denominators
__device__ int      g_is64;                            // edge_index stored as int64?
// tf32 weight copies
__device__ uint32_t g_wt  [4][HID * HID];              // wq, wk, wv, wskip
__device__ uint32_t g_w1t [HID * 2 * HID];
__device__ uint32_t g_w2t [2 * HID * HID];

// ---------------- helpers ----------------
__device__ __forceinline__ unsigned fkey(float x) {
    unsigned u = __float_as_uint(x);
    return (u & 0x80000000u) ? ~u : (u | 0x80000000u);
}
__device__ __forceinline__ float funkey(unsigned u) {
    u = (u & 0x80000000u) ? (u & 0x7fffffffu) : ~u;
    return __uint_as_float(u);
}
__device__ __forceinline__ int load_idx(const int* __restrict__ ei, int pos, int is64) {
    return is64 ? ei[(size_t)pos * 2] : ei[pos];
}
__device__ __forceinline__ void red_add_v4(float* p, float a, float b, float c, float d) {
    asm volatile("red.global.add.v4.f32 [%0], {%1,%2,%3,%4};"
                 :: "l"(p), "f"(a), "f"(b), "f"(c), "f"(d) : "memory");
}
__device__ __forceinline__ float gelu_exact(float v) {
    return 0.5f * v * (1.0f + erff(v * 0.7071067811865476f));
}
__device__ __forceinline__ uint32_t f2tf(float x) {
    uint32_t r; asm("cvt.rna.tf32.f32 %0, %1;" : "=r"(r) : "f"(x)); return r;
}
__device__ __forceinline__ void mma_tf32(float* c, uint32_t a0, uint32_t a1, uint32_t a2,
                                         uint32_t a3, uint32_t b0, uint32_t b1) {
    asm volatile("mma.sync.aligned.m16n8k8.row.col.f32.tf32.tf32.f32 "
                 "{%0,%1,%2,%3}, {%4,%5,%6,%7}, {%8,%9}, {%0,%1,%2,%3};"
                 : "+f"(c[0]), "+f"(c[1]), "+f"(c[2]), "+f"(c[3])
                 : "r"(a0), "r"(a1), "r"(a2), "r"(a3), "r"(b0), "r"(b1));
}

// ---------------- dtype detection (1 warp) ----------------
__global__ void detect_kernel(const int* __restrict__ ei, int E) {
    int lane = threadIdx.x;
    int nz = 0;
    for (int i = lane; i < 512 && i < E; i += 32)
        nz |= ei[2 * i + 1];
    #pragma unroll
    for (int o = 16; o > 0; o >>= 1) nz |= __shfl_xor_sync(0xffffffffu, nz, o);
    if (lane == 0) g_is64 = (nz == 0) ? 1 : 0;
}

// ---------------- one-shot weight conversion to tf32 ----------------
struct WCvt { const float* src[6]; uint32_t* dst[6]; };
__global__ void cvt_weights_kernel(WCvt wc) {
    int e4 = (blockIdx.x * blockDim.x + threadIdx.x) * 4;   // 524288 total elements
    int seg, base;
    if (e4 < 262144)      { seg = e4 >> 16; base = seg << 16; }
    else if (e4 < 393216) { seg = 4; base = 262144; }
    else                  { seg = 5; base = 393216; }
    int off = e4 - base;
    float4 v = *(const float4*)(wc.src[seg] + off);
    uint4 o = make_uint4(f2tf(v.x), f2tf(v.y), f2tf(v.z), f2tf(v.w));
    *(uint4*)(wc.dst[seg] + off) = o;
}

// ---------------- init: zero mkey/den and agg ----------------
__global__ void init_kernel(unsigned* __restrict__ mkey, float* __restrict__ den,
                            float* __restrict__ agg, int nh, int total) {
    int i = blockIdx.x * blockDim.x + threadIdx.x;
    if (i < nh) { mkey[i] = 0u; den[i] = 0.0f; }
    if (i * 4 < total) ((float4*)agg)[i] = make_float4(0.f, 0.f, 0.f, 0.f);
}

// ---------------- LayerNorm (warp per row of 256) -> tf32 out ----------------
__global__ void ln_kernel(const float* __restrict__ x, const float* __restrict__ w,
                          const float* __restrict__ b, uint32_t* __restrict__ out, int n) {
    int row = (blockIdx.x * blockDim.x + threadIdx.x) >> 5;
    if (row >= n) return;
    int lane = threadIdx.x & 31;
    const float4* xp = (const float4*)(x + (size_t)row * HID);
    float4 v0 = xp[lane * 2], v1 = xp[lane * 2 + 1];
    float s  = v0.x + v0.y + v0.z + v0.w + v1.x + v1.y + v1.z + v1.w;
    float sq = v0.x*v0.x + v0.y*v0.y + v0.z*v0.z + v0.w*v0.w
             + v1.x*v1.x + v1.y*v1.y + v1.z*v1.z + v1.w*v1.w;
    #pragma unroll
    for (int o = 16; o > 0; o >>= 1) {
        s  += __shfl_xor_sync(0xffffffffu, s,  o);
        sq += __shfl_xor_sync(0xffffffffu, sq, o);
    }
    float mean = s * (1.0f / HID);
    float var  = sq * (1.0f / HID) - mean * mean;
    float rstd = rsqrtf(var + 1e-5f);
    const float4* wp = (const float4*)w;
    const float4* bp = (const float4*)b;
    uint4* op = (uint4*)(out + (size_t)row * HID);
    #pragma unroll
    for (int i = 0; i < 2; i++) {
        float4 xv = (i == 0) ? v0 : v1;
        float4 wv = wp[lane * 2 + i], bv = bp[lane * 2 + i];
        uint4 o;
        o.x = f2tf((xv.x - mean) * rstd * wv.x + bv.x);
        o.y = f2tf((xv.y - mean) * rstd * wv.y + bv.y);
        o.z = f2tf((xv.z - mean) * rstd * wv.z + bv.z);
        o.w = f2tf((xv.w - mean) * rstd * wv.w + bv.w);
        op[lane * 2 + i] = o;
    }
}

// ---------------- x1 = x + skip + agg/den; h2 = LN2(x1) (tf32 out) ----------------
__global__ void add_ln_kernel(const float* __restrict__ x, const float* __restrict__ skip,
                              const float* __restrict__ agg, const float* __restrict__ den,
                              const float* __restrict__ w, const float* __restrict__ b,
                              float* __restrict__ x1out, uint32_t* __restrict__ hout, int n) {
    int row = (blockIdx.x * blockDim.x + threadIdx.x) >> 5;
    if (row >= n) return;
    int lane = threadIdx.x & 31;
    int h = lane >> 3;
    float d = den[row * NHEAD + h];
    float rden = (d > 0.0f) ? (1.0f / d) : 0.0f;
    const float4* xp = (const float4*)(x    + (size_t)row * HID);
    const float4* sp = (const float4*)(skip + (size_t)row * HID);
    const float4* ap = (const float4*)(agg  + (size_t)row * HID);
    float4 a0 = xp[lane * 2], a1 = xp[lane * 2 + 1];
    float4 c0 = sp[lane * 2], c1 = sp[lane * 2 + 1];
    float4 g0 = ap[lane * 2], g1 = ap[lane * 2 + 1];
    float4 v0 = make_float4(a0.x + c0.x + g0.x * rden, a0.y + c0.y + g0.y * rden,
                            a0.z + c0.z + g0.z * rden, a0.w + c0.w + g0.w * rden);
    float4 v1 = make_float4(a1.x + c1.x + g1.x * rden, a1.y + c1.y + g1.y * rden,
                            a1.z + c1.z + g1.z * rden, a1.w + c1.w + g1.w * rden);
    float4* x1p = (float4*)(x1out + (size_t)row * HID);
    x1p[lane * 2]     = v0;
    x1p[lane * 2 + 1] = v1;
    float s  = v0.x + v0.y + v0.z + v0.w + v1.x + v1.y + v1.z + v1.w;
    float sq = v0.x*v0.x + v0.y*v0.y + v0.z*v0.z + v0.w*v0.w
             + v1.x*v1.x + v1.y*v1.y + v1.z*v1.z + v1.w*v1.w;
    #pragma unroll
    for (int o = 16; o > 0; o >>= 1) {
        s  += __shfl_xor_sync(0xffffffffu, s,  o);
        sq += __shfl_xor_sync(0xffffffffu, sq, o);
    }
    float mean = s * (1.0f / HID);
    float var  = sq * (1.0f / HID) - mean * mean;
    float rstd = rsqrtf(var + 1e-5f);
    const float4* wp = (const float4*)w;
    const float4* bp = (const float4*)b;
    uint4* op = (uint4*)(hout + (size_t)row * HID);
    #pragma unroll
    for (int i = 0; i < 2; i++) {
        float4 xv = (i == 0) ? v0 : v1;
        float4 wv = wp[lane * 2 + i], bv = bp[lane * 2 + i];
        uint4 o;
        o.x = f2tf((xv.x - mean) * rstd * wv.x + bv.x);
        o.y = f2tf((xv.y - mean) * rstd * wv.y + bv.y);
        o.z = f2tf((xv.z - mean) * rstd * wv.z + bv.z);
        o.w = f2tf((xv.w - mean) * rstd * wv.w + bv.w);
        op[lane * 2 + i] = o;
    }
}

// ---------------- TF32 GEMM, pre-converted operands, hoisted swizzle ------
// EPI 0: bias -> f32 out; 1: bias+GELU -> tf32 out; 2: bias+residual -> f32 out
struct GemmPtrs { const uint32_t* W[4]; const float* bias[4]; void* out[4]; };

template<int EPI>
__global__ __launch_bounds__(256)
void gemm_tf32(const uint32_t* __restrict__ A, GemmPtrs p,
               const float* __restrict__ res, int M, int N, int K) {
    __shared__ __align__(16) uint32_t As[2][2048];   // 8KB each
    __shared__ __align__(16) uint32_t Bs[2][2048];

    const uint32_t* __restrict__ W    = p.W[blockIdx.z];
    const float* __restrict__    bias = p.bias[blockIdx.z];

    const int t = threadIdx.x;
    const int lane = t & 31, wid = t >> 5;
    const int wm = wid & 1, wn = wid >> 1;          // 2 x 4 warp grid
    const int mBase = blockIdx.x * 128;
    const int nBase = blockIdx.y * 128;
    const int lr = lane >> 2, lc = lane & 3;

    const int rA = t >> 2,  cA = (t & 3) * 4;       // A: rows rA, rA+64; k cols cA..cA+3
    const int rB = t >> 5,  cB = (t & 31) * 4;      // B: k rows rB, rB+8; cols cB..cB+3

    const int laneA = lane ^ ((lane >> 3) & 3);

    // precompute swizzled store offsets (words) -- loop-invariant
    int offA[4], offB[4];
    {
        int mt = rA >> 4, s1 = (rA >> 3) & 1, lr0 = rA & 7;
        int ks = cA >> 3, s2 = (cA >> 2) & 1;
        int e  = s1 * 2 + s2;
        int blk = (mt * 2 + ks) * 32;
        #pragma unroll
        for (int j = 0; j < 4; j++) {
            int la = 4 * lr0 + j;
            la ^= (la >> 3) & 3;
            offA[j] = (blk + la) * 4 + e;
        }
        int sB = (rB >> 2) & 1, lcb = rB & 3;       // rB in 0..7 -> ks=0
        #pragma unroll
        for (int j = 0; j < 4; j++) {
            int nn = cB + j;
            int nt = nn >> 3, lrb = nn & 7;
            int lb = (4 * lrb + lcb) ^ nt;
            offB[j] = (nt * 2 * 32 + lb) * 2 + sB;
        }
    }

    float acc[4][4][4];
    #pragma unroll
    for (int i = 0; i < 4; i++)
        #pragma unroll
        for (int j = 0; j < 4; j++)
            #pragma unroll
            for (int r = 0; r < 4; r++) acc[i][j][r] = 0.0f;

    const int NK = K >> 4;
    uint4 pa0, pa1, pb0, pb1;
    const uint4 z4 = make_uint4(0u, 0u, 0u, 0u);

    {   // prologue kb=0
        int gr0 = mBase + rA, gr1 = gr0 + 64;
        pa0 = (gr0 < M) ? *(const uint4*)(A + (size_t)gr0 * K + cA) : z4;
        pa1 = (gr1 < M) ? *(const uint4*)(A + (size_t)gr1 * K + cA) : z4;
        pb0 = *(const uint4*)(W + (size_t)rB       * N + nBase + cB);
        pb1 = *(const uint4*)(W + (size_t)(rB + 8) * N + nBase + cB);
        uint32_t* sa = As[0];
        sa[offA[0]] = pa0.x; sa[offA[1]] = pa0.y; sa[offA[2]] = pa0.z; sa[offA[3]] = pa0.w;
        sa += 1024;
        sa[offA[0]] = pa1.x; sa[offA[1]] = pa1.y; sa[offA[2]] = pa1.z; sa[offA[3]] = pa1.w;
        uint32_t* sb = Bs[0];
        sb[offB[0]] = pb0.x; sb[offB[1]] = pb0.y; sb[offB[2]] = pb0.z; sb[offB[3]] = pb0.w;
        sb += 64;
        sb[offB[0]] = pb1.x; sb[offB[1]] = pb1.y; sb[offB[2]] = pb1.z; sb[offB[3]] = pb1.w;
    }
    __syncthreads();

    for (int kb = 0; kb < NK; kb++) {
        const int buf = kb & 1;
        const bool more = (kb + 1 < NK);
        if (more) {
            int kofs = (kb + 1) * 16;
            int gr0 = mBase + rA, gr1 = gr0 + 64;
            pa0 = (gr0 < M) ? *(const uint4*)(A + (size_t)gr0 * K + kofs + cA) : z4;
            pa1 = (gr1 < M) ? *(const uint4*)(A + (size_t)gr1 * K + kofs + cA) : z4;
            pb0 = *(const uint4*)(W + (size_t)(kofs + rB)     * N + nBase + cB);
            pb1 = *(const uint4*)(W + (size_t)(kofs + rB + 8) * N + nBase + cB);
        }
        const uint32_t* curA = As[buf];
        const uint32_t* curB = Bs[buf];
        #pragma unroll
        for (int ks = 0; ks < 2; ks++) {
            uint4 a[4]; uint2 b[4];
            #pragma unroll
            for (int mt = 0; mt < 4; mt++) {
                int mt_g = wm * 4 + mt;
                a[mt] = *(const uint4*)&curA[((mt_g * 2 + ks) * 32 + laneA) * 4];
            }
            #pragma unroll
            for (int nt = 0; nt < 4; nt++) {
                int nt_g = wn * 4 + nt;
                b[nt] = *(const uint2*)&curB[((nt_g * 2 + ks) * 32 + (lane ^ nt_g)) * 2];
            }
            #pragma unroll
            for (int mt = 0; mt < 4; mt++)
                #pragma unroll
                for (int nt = 0; nt < 4; nt++)
                    mma_tf32(acc[mt][nt], a[mt].x, a[mt].z, a[mt].y, a[mt].w,
                             b[nt].x, b[nt].y);
        }
        if (more) {
            uint32_t* sa = As[buf ^ 1];
            sa[offA[0]] = pa0.x; sa[offA[1]] = pa0.y; sa[offA[2]] = pa0.z; sa[offA[3]] = pa0.w;
            sa += 1024;
            sa[offA[0]] = pa1.x; sa[offA[1]] = pa1.y; sa[offA[2]] = pa1.z; sa[offA[3]] = pa1.w;
            uint32_t* sb = Bs[buf ^ 1];
            sb[offB[0]] = pb0.x; sb[offB[1]] = pb0.y; sb[offB[2]] = pb0.z; sb[offB[3]] = pb0.w;
            sb += 64;
            sb[offB[0]] = pb1.x; sb[offB[1]] = pb1.y; sb[offB[2]] = pb1.z; sb[offB[3]] = pb1.w;
        }
        __syncthreads();
    }

    // epilogue: rows lr, lr+8; cols 2*lc, 2*lc+1 per fragment
    #pragma unroll
    for (int mt = 0; mt < 4; mt++) {
        int r0 = mBase + wm * 64 + mt * 16 + lr;
        #pragma unroll
        for (int nt = 0; nt < 4; nt++) {
            int col = nBase + wn * 32 + nt * 8 + lc * 2;
            float2 bv = *(const float2*)(bias + col);
            float* cc = acc[mt][nt];
            #pragma unroll
            for (int half = 0; half < 2; half++) {
                int r = r0 + half * 8;
                if (r >= M) continue;
                float ox = cc[half * 2 + 0] + bv.x;
                float oy = cc[half * 2 + 1] + bv.y;
                if (EPI == 1) {
                    ox = gelu_exact(ox); oy = gelu_exact(oy);
                    uint32_t* Cu = (uint32_t*)p.out[blockIdx.z];
                    *(uint2*)(Cu + (size_t)r * N + col) = make_uint2(f2tf(ox), f2tf(oy));
                } else {
                    if (EPI == 2) {
                        float2 rv = *(const float2*)(res + (size_t)r * N + col);
                        ox += rv.x; oy += rv.y;
                    }
                    float* Cf = (float*)p.out[blockIdx.z];
                    *(float2*)(Cf + (size_t)r * N + col) = make_float2(ox, oy);
                }
            }
        }
    }
}

// ---------------- edge scores (warp per edge) ----------------
__global__ void edge_scores_kernel(const int* __restrict__ ei,
                                   const float* __restrict__ q, const float* __restrict__ k,
                                   float* __restrict__ scores, unsigned* __restrict__ mkey, int E) {
    int e = (blockIdx.x * blockDim.x + threadIdx.x) >> 5;
    if (e >= E) return;
    int lane = threadIdx.x & 31;
    int is64 = g_is64;
    int src = load_idx(ei, e, is64);
    int dst = load_idx(ei, E + e, is64);
    const float4* qp = (const float4*)(q + (size_t)dst * HID) + lane * 2;
    const float4* kp = (const float4*)(k + (size_t)src * HID) + lane * 2;
    float4 a0 = qp[0], a1 = qp[1];
    float4 b0 = kp[0], b1 = kp[1];
    float d = a0.x*b0.x + a0.y*b0.y + a0.z*b0.z + a0.w*b0.w
            + a1.x*b1.x + a1.y*b1.y + a1.z*b1.z + a1.w*b1.w;
    d += __shfl_xor_sync(0xffffffffu, d, 1);
    d += __shfl_xor_sync(0xffffffffu, d, 2);
    d += __shfl_xor_sync(0xffffffffu, d, 4);
    if ((lane & 7) == 0) {
        int h = lane >> 3;
        float s = d * 0.125f;
        scores[(size_t)e * NHEAD + h] = s;
        atomicMax(&mkey[dst * NHEAD + h], fkey(s));
    }
}

// ---------------- fused exp + aggregate (warp per edge) ----------------
__global__ void edge_exp_agg_kernel(const int* __restrict__ ei,
                                    const float* __restrict__ scores,
                                    const unsigned* __restrict__ mkey,
                                    float* __restrict__ den,
                                    const float* __restrict__ v,
                                    float* __restrict__ agg, int E) {
    int e = (blockIdx.x * blockDim.x + threadIdx.x) >> 5;
    if (e >= E) return;
    int lane = threadIdx.x & 31;
    int is64 = g_is64;
    int src = load_idx(ei, e, is64);
    int dst = load_idx(ei, E + e, is64);
    int h = lane >> 3;
    float s = scores[(size_t)e * NHEAD + h];
    float m = funkey(mkey[dst * NHEAD + h]);
    float w = __expf(s - m);
    if ((lane & 7) == 0) atomicAdd(&den[dst * NHEAD + h], w);
    const float4* vp = (const float4*)(v + (size_t)src * HID) + lane * 2;
    float4 v0 = vp[0], v1 = vp[1];
    float* op = agg + (size_t)dst * HID + lane * 8;
    red_add_v4(op,     w * v0.x, w * v0.y, w * v0.z, w * v0.w);
    red_add_v4(op + 4, w * v1.x, w * v1.y, w * v1.z, w * v1.w);
}

// ---------------- host launch ----------------
extern "C" void kernel_launch(void* const* d_in, const int* in_sizes, int n_in,
                              void* d_out, int out_size) {
    const float* x     = (const float*)d_in[0];
    const int*   ei    = (const int*)d_in[1];
    const float* ln1_w = (const float*)d_in[2];
    const float* ln1_b = (const float*)d_in[3];
    const float* ln2_w = (const float*)d_in[4];
    const float* ln2_b = (const float*)d_in[5];
    const float* wq    = (const float*)d_in[6];
    const float* bq    = (const float*)d_in[7];
    const float* wk    = (const float*)d_in[8];
    const float* bk    = (const float*)d_in[9];
    const float* wv    = (const float*)d_in[10];
    const float* bv    = (const float*)d_in[11];
    const float* wskip = (const float*)d_in[12];
    const float* bskip = (const float*)d_in[13];
    const float* w1    = (const float*)d_in[14];
    const float* b1    = (const float*)d_in[15];
    const float* w2    = (const float*)d_in[16];
    const float* b2    = (const float*)d_in[17];

    int n = in_sizes[0] / HID;
    int E = in_sizes[1] / 2;

    static uint32_t *h = nullptr, *mid, *wt0, *wt1, *wt2, *wt3, *w1t, *w2t;
    static float *q, *k, *v, *skip, *agg, *x1, *scores, *den;
    static unsigned* mkey;
    if (!h) {
        cudaGetSymbolAddress((void**)&h,      g_h);
        cudaGetSymbolAddress((void**)&q,      g_q);
        cudaGetSymbolAddress((void**)&k,      g_k);
        cudaGetSymbolAddress((void**)&v,      g_v);
        cudaGetSymbolAddress((void**)&skip,   g_skip);
        cudaGetSymbolAddress((void**)&agg,    g_agg);
        cudaGetSymbolAddress((void**)&x1,     g_x1);
        cudaGetSymbolAddress((void**)&mid,    g_mid);
        cudaGetSymbolAddress((void**)&scores, g_scores);
        cudaGetSymbolAddress((void**)&den,    g_den);
        cudaGetSymbolAddress((void**)&mkey,   g_mkey);
        cudaGetSymbolAddress((void**)&wt0,    g_wt);
        wt1 = wt0 + HID * HID; wt2 = wt1 + HID * HID; wt3 = wt2 + HID * HID;
        cudaGetSymbolAddress((void**)&w1t,    g_w1t);
        cudaGetSymbolAddress((void**)&w2t,    g_w2t);
    }

    detect_kernel<<<1, 32>>>(ei, E);
    {
        WCvt wc;
        wc.src[0] = wq;  wc.dst[0] = wt0;
        wc.src[1] = wk;  wc.dst[1] = wt1;
        wc.src[2] = wv;  wc.dst[2] = wt2;
        wc.src[3] = wskip; wc.dst[3] = wt3;
        wc.src[4] = w1;  wc.dst[4] = w1t;
        wc.src[5] = w2;  wc.dst[5] = w2t;
        cvt_weights_kernel<<<512, 256>>>(wc);
    }
    {
        int tot = n * HID;
        init_kernel<<<(tot / 4 + 255) / 256, 256>>>(mkey, den, agg, n * NHEAD, tot);
    }
    ln_kernel<<<(n * 32 + 255) / 256, 256>>>(x, ln1_w, ln1_b, h, n);

    {
        GemmPtrs p;
        p.W[0] = wt0; p.bias[0] = bq;    p.out[0] = q;
        p.W[1] = wt1; p.bias[1] = bk;    p.out[1] = k;
        p.W[2] = wt2; p.bias[2] = bv;    p.out[2] = v;
        p.W[3] = wt3; p.bias[3] = bskip; p.out[3] = skip;
        dim3 g((n + 127) / 128, HID / 128, 4);     // 157 x 2 x 4
        gemm_tf32<0><<<g, 256>>>(h, p, nullptr, n, HID, HID);
    }

    edge_scores_kernel<<<(E + 7) / 8, 256>>>(ei, q, k, scores, mkey, E);
    edge_exp_agg_kernel<<<(E + 7) / 8, 256>>>(ei, scores, mkey, den, v, agg, E);

    add_ln_kernel<<<(n * 32 + 255) / 256, 256>>>(x, skip, agg, den, ln2_w, ln2_b, x1, h, n);

    {
        GemmPtrs p;
        p.W[0] = w1t; p.bias[0] = b1; p.out[0] = mid;
        dim3 g((n + 127) / 128, (2 * HID) / 128, 1);   // 157 x 4
        gemm_tf32<1><<<g, 256>>>(h, p, nullptr, n, 2 * HID, HID);
    }
    {
        GemmPtrs p;
        p.W[0] = w2t; p.bias[0] = b2; p.out[0] = d_out;
        dim3 g((n + 127) / 128, HID / 128, 1);         // 157 x 2
        gemm_tf32<2><<<g, 256>>>(mid, p, x1, n, HID, 2 * HID);
    }
}

// round 9
// speedup vs baseline: 2.3100x; 1.0737x over previous
#include <cuda_runtime.h>
#include <cstdint>

#define HID 256
#define NHEAD 4
#define MAXN 20000
#define MAXE 320000

// ---------------- scratch (device globals; no allocation allowed) ----------------
__device__ uint32_t g_h   [(size_t)MAXN * HID];        // ln1 out (tf32), reused as h2
__device__ float    g_q   [(size_t)MAXN * HID];
__device__ float    g_k   [(size_t)MAXN * HID];
__device__ float    g_v   [(size_t)MAXN * HID];
__device__ float    g_skip[(size_t)MAXN * HID];        // skip projection
__device__ float    g_agg [(size_t)MAXN * HID];        // unnormalized edge aggregate
__device__ float    g_x1  [(size_t)MAXN * HID];        // x + conv
__device__ uint32_t g_mid [(size_t)MAXN * 2 * HID];    // FF hidden (tf32)
__device__ float    g_den [MAXN * NHEAD];              // softmax denominators
__device__ int      g_is64;                            // edge_index stored as int64?
// tf32 weight copies
__device__ uint32_t g_wt  [4][HID * HID];              // wq, wk, wv, wskip
__device__ uint32_t g_w1t [HID * 2 * HID];
__device__ uint32_t g_w2t [2 * HID * HID];

// ---------------- helpers ----------------
__device__ __forceinline__ int load_idx(const int* __restrict__ ei, int pos, int is64) {
    return is64 ? ei[(size_t)pos * 2] : ei[pos];
}
__device__ __forceinline__ void red_add_v4(float* p, float a, float b, float c, float d) {
    asm volatile("red.global.add.v4.f32 [%0], {%1,%2,%3,%4};"
                 :: "l"(p), "f"(a), "f"(b), "f"(c), "f"(d) : "memory");
}
__device__ __forceinline__ float gelu_exact(float v) {
    return 0.5f * v * (1.0f + erff(v * 0.7071067811865476f));
}
__device__ __forceinline__ uint32_t f2tf(float x) {
    uint32_t r; asm("cvt.rna.tf32.f32 %0, %1;" : "=r"(r) : "f"(x)); return r;
}
__device__ __forceinline__ void mma_tf32(float* c, uint32_t a0, uint32_t a1, uint32_t a2,
                                         uint32_t a3, uint32_t b0, uint32_t b1) {
    asm volatile("mma.sync.aligned.m16n8k8.row.col.f32.tf32.tf32.f32 "
                 "{%0,%1,%2,%3}, {%4,%5,%6,%7}, {%8,%9}, {%0,%1,%2,%3};"
                 : "+f"(c[0]), "+f"(c[1]), "+f"(c[2]), "+f"(c[3])
                 : "r"(a0), "r"(a1), "r"(a2), "r"(a3), "r"(b0), "r"(b1));
}

// ---------------- dtype detection (1 warp) ----------------
__global__ void detect_kernel(const int* __restrict__ ei, int E) {
    int lane = threadIdx.x;
    int nz = 0;
    for (int i = lane; i < 512 && i < E; i += 32)
        nz |= ei[2 * i + 1];
    #pragma unroll
    for (int o = 16; o > 0; o >>= 1) nz |= __shfl_xor_sync(0xffffffffu, nz, o);
    if (lane == 0) g_is64 = (nz == 0) ? 1 : 0;
}

// ---------------- one-shot weight conversion to tf32 ----------------
struct WCvt { const float* src[6]; uint32_t* dst[6]; };
__global__ void cvt_weights_kernel(WCvt wc) {
    int e4 = (blockIdx.x * blockDim.x + threadIdx.x) * 4;   // 524288 total elements
    int seg, base;
    if (e4 < 262144)      { seg = e4 >> 16; base = seg << 16; }
    else if (e4 < 393216) { seg = 4; base = 262144; }
    else                  { seg = 5; base = 393216; }
    int off = e4 - base;
    float4 v = *(const float4*)(wc.src[seg] + off);
    uint4 o = make_uint4(f2tf(v.x), f2tf(v.y), f2tf(v.z), f2tf(v.w));
    *(uint4*)(wc.dst[seg] + off) = o;
}

// ---------------- init: zero den and agg ----------------
__global__ void init_kernel(float* __restrict__ den, float* __restrict__ agg,
                            int nh, int total) {
    int i = blockIdx.x * blockDim.x + threadIdx.x;
    if (i < nh) den[i] = 0.0f;
    if (i * 4 < total) ((float4*)agg)[i] = make_float4(0.f, 0.f, 0.f, 0.f);
}

// ---------------- LayerNorm (warp per row of 256) -> tf32 out ----------------
__global__ void ln_kernel(const float* __restrict__ x, const float* __restrict__ w,
                          const float* __restrict__ b, uint32_t* __restrict__ out, int n) {
    int row = (blockIdx.x * blockDim.x + threadIdx.x) >> 5;
    if (row >= n) return;
    int lane = threadIdx.x & 31;
    const float4* xp = (const float4*)(x + (size_t)row * HID);
    float4 v0 = xp[lane * 2], v1 = xp[lane * 2 + 1];
    float s  = v0.x + v0.y + v0.z + v0.w + v1.x + v1.y + v1.z + v1.w;
    float sq = v0.x*v0.x + v0.y*v0.y + v0.z*v0.z + v0.w*v0.w
             + v1.x*v1.x + v1.y*v1.y + v1.z*v1.z + v1.w*v1.w;
    #pragma unroll
    for (int o = 16; o > 0; o >>= 1) {
        s  += __shfl_xor_sync(0xffffffffu, s,  o);
        sq += __shfl_xor_sync(0xffffffffu, sq, o);
    }
    float mean = s * (1.0f / HID);
    float var  = sq * (1.0f / HID) - mean * mean;
    float rstd = rsqrtf(var + 1e-5f);
    const float4* wp = (const float4*)w;
    const float4* bp = (const float4*)b;
    uint4* op = (uint4*)(out + (size_t)row * HID);
    #pragma unroll
    for (int i = 0; i < 2; i++) {
        float4 xv = (i == 0) ? v0 : v1;
        float4 wv = wp[lane * 2 + i], bv = bp[lane * 2 + i];
        uint4 o;
        o.x = f2tf((xv.x - mean) * rstd * wv.x + bv.x);
        o.y = f2tf((xv.y - mean) * rstd * wv.y + bv.y);
        o.z = f2tf((xv.z - mean) * rstd * wv.z + bv.z);
        o.w = f2tf((xv.w - mean) * rstd * wv.w + bv.w);
        op[lane * 2 + i] = o;
    }
}

// ---------------- x1 = x + skip + agg/den; h2 = LN2(x1) (tf32 out) ----------------
__global__ void add_ln_kernel(const float* __restrict__ x, const float* __restrict__ skip,
                              const float* __restrict__ agg, const float* __restrict__ den,
                              const float* __restrict__ w, const float* __restrict__ b,
                              float* __restrict__ x1out, uint32_t* __restrict__ hout, int n) {
    int row = (blockIdx.x * blockDim.x + threadIdx.x) >> 5;
    if (row >= n) return;
    int lane = threadIdx.x & 31;
    int h = lane >> 3;
    float d = den[row * NHEAD + h];
    float rden = (d > 0.0f) ? (1.0f / d) : 0.0f;
    const float4* xp = (const float4*)(x    + (size_t)row * HID);
    const float4* sp = (const float4*)(skip + (size_t)row * HID);
    const float4* ap = (const float4*)(agg  + (size_t)row * HID);
    float4 a0 = xp[lane * 2], a1 = xp[lane * 2 + 1];
    float4 c0 = sp[lane * 2], c1 = sp[lane * 2 + 1];
    float4 g0 = ap[lane * 2], g1 = ap[lane * 2 + 1];
    float4 v0 = make_float4(a0.x + c0.x + g0.x * rden, a0.y + c0.y + g0.y * rden,
                            a0.z + c0.z + g0.z * rden, a0.w + c0.w + g0.w * rden);
    float4 v1 = make_float4(a1.x + c1.x + g1.x * rden, a1.y + c1.y + g1.y * rden,
                            a1.z + c1.z + g1.z * rden, a1.w + c1.w + g1.w * rden);
    float4* x1p = (float4*)(x1out + (size_t)row * HID);
    x1p[lane * 2]     = v0;
    x1p[lane * 2 + 1] = v1;
    float s  = v0.x + v0.y + v0.z + v0.w + v1.x + v1.y + v1.z + v1.w;
    float sq = v0.x*v0.x + v0.y*v0.y + v0.z*v0.z + v0.w*v0.w
             + v1.x*v1.x + v1.y*v1.y + v1.z*v1.z + v1.w*v1.w;
    #pragma unroll
    for (int o = 16; o > 0; o >>= 1) {
        s  += __shfl_xor_sync(0xffffffffu, s,  o);
        sq += __shfl_xor_sync(0xffffffffu, sq, o);
    }
    float mean = s * (1.0f / HID);
    float var  = sq * (1.0f / HID) - mean * mean;
    float rstd = rsqrtf(var + 1e-5f);
    const float4* wp = (const float4*)w;
    const float4* bp = (const float4*)b;
    uint4* op = (uint4*)(hout + (size_t)row * HID);
    #pragma unroll
    for (int i = 0; i < 2; i++) {
        float4 xv = (i == 0) ? v0 : v1;
        float4 wv = wp[lane * 2 + i], bv = bp[lane * 2 + i];
        uint4 o;
        o.x = f2tf((xv.x - mean) * rstd * wv.x + bv.x);
        o.y = f2tf((xv.y - mean) * rstd * wv.y + bv.y);
        o.z = f2tf((xv.z - mean) * rstd * wv.z + bv.z);
        o.w = f2tf((xv.w - mean) * rstd * wv.w + bv.w);
        op[lane * 2 + i] = o;
    }
}

// ---------------- TF32 GEMM, pre-converted operands, hoisted swizzle ------
// EPI 0: bias -> f32 out; 1: bias+GELU -> tf32 out; 2: bias+residual -> f32 out
struct GemmPtrs { const uint32_t* W[4]; const float* bias[4]; void* out[4]; };

template<int EPI>
__global__ __launch_bounds__(256)
void gemm_tf32(const uint32_t* __restrict__ A, GemmPtrs p,
               const float* __restrict__ res, int M, int N, int K) {
    __shared__ __align__(16) uint32_t As[2][2048];   // 8KB each
    __shared__ __align__(16) uint32_t Bs[2][2048];

    const uint32_t* __restrict__ W    = p.W[blockIdx.z];
    const float* __restrict__    bias = p.bias[blockIdx.z];

    const int t = threadIdx.x;
    const int lane = t & 31, wid = t >> 5;
    const int wm = wid & 1, wn = wid >> 1;          // 2 x 4 warp grid
    const int mBase = blockIdx.x * 128;
    const int nBase = blockIdx.y * 128;
    const int lr = lane >> 2, lc = lane & 3;

    const int rA = t >> 2,  cA = (t & 3) * 4;       // A: rows rA, rA+64; k cols cA..cA+3
    const int rB = t >> 5,  cB = (t & 31) * 4;      // B: k rows rB, rB+8; cols cB..cB+3

    const int laneA = lane ^ ((lane >> 3) & 3);

    // precompute swizzled store offsets (words) -- loop-invariant
    int offA[4], offB[4];
    {
        int mt = rA >> 4, s1 = (rA >> 3) & 1, lr0 = rA & 7;
        int ks = cA >> 3, s2 = (cA >> 2) & 1;
        int e  = s1 * 2 + s2;
        int blk = (mt * 2 + ks) * 32;
        #pragma unroll
        for (int j = 0; j < 4; j++) {
            int la = 4 * lr0 + j;
            la ^= (la >> 3) & 3;
            offA[j] = (blk + la) * 4 + e;
        }
        int sB = (rB >> 2) & 1, lcb = rB & 3;       // rB in 0..7 -> ks=0
        #pragma unroll
        for (int j = 0; j < 4; j++) {
            int nn = cB + j;
            int nt = nn >> 3, lrb = nn & 7;
            int lb = (4 * lrb + lcb) ^ nt;
            offB[j] = (nt * 2 * 32 + lb) * 2 + sB;
        }
    }

    float acc[4][4][4];
    #pragma unroll
    for (int i = 0; i < 4; i++)
        #pragma unroll
        for (int j = 0; j < 4; j++)
            #pragma unroll
            for (int r = 0; r < 4; r++) acc[i][j][r] = 0.0f;

    const int NK = K >> 4;
    uint4 pa0, pa1, pb0, pb1;
    const uint4 z4 = make_uint4(0u, 0u, 0u, 0u);

    {   // prologue kb=0
        int gr0 = mBase + rA, gr1 = gr0 + 64;
        pa0 = (gr0 < M) ? *(const uint4*)(A + (size_t)gr0 * K + cA) : z4;
        pa1 = (gr1 < M) ? *(const uint4*)(A + (size_t)gr1 * K + cA) : z4;
        pb0 = *(const uint4*)(W + (size_t)rB       * N + nBase + cB);
        pb1 = *(const uint4*)(W + (size_t)(rB + 8) * N + nBase + cB);
        uint32_t* sa = As[0];
        sa[offA[0]] = pa0.x; sa[offA[1]] = pa0.y; sa[offA[2]] = pa0.z; sa[offA[3]] = pa0.w;
        sa += 1024;
        sa[offA[0]] = pa1.x; sa[offA[1]] = pa1.y; sa[offA[2]] = pa1.z; sa[offA[3]] = pa1.w;
        uint32_t* sb = Bs[0];
        sb[offB[0]] = pb0.x; sb[offB[1]] = pb0.y; sb[offB[2]] = pb0.z; sb[offB[3]] = pb0.w;
        sb += 64;
        sb[offB[0]] = pb1.x; sb[offB[1]] = pb1.y; sb[offB[2]] = pb1.z; sb[offB[3]] = pb1.w;
    }
    __syncthreads();

    for (int kb = 0; kb < NK; kb++) {
        const int buf = kb & 1;
        const bool more = (kb + 1 < NK);
        if (more) {
            int kofs = (kb + 1) * 16;
            int gr0 = mBase + rA, gr1 = gr0 + 64;
            pa0 = (gr0 < M) ? *(const uint4*)(A + (size_t)gr0 * K + kofs + cA) : z4;
            pa1 = (gr1 < M) ? *(const uint4*)(A + (size_t)gr1 * K + kofs + cA) : z4;
            pb0 = *(const uint4*)(W + (size_t)(kofs + rB)     * N + nBase + cB);
            pb1 = *(const uint4*)(W + (size_t)(kofs + rB + 8) * N + nBase + cB);
        }
        const uint32_t* curA = As[buf];
        const uint32_t* curB = Bs[buf];
        #pragma unroll
        for (int ks = 0; ks < 2; ks++) {
            uint4 a[4]; uint2 b[4];
            #pragma unroll
            for (int mt = 0; mt < 4; mt++) {
                int mt_g = wm * 4 + mt;
                a[mt] = *(const uint4*)&curA[((mt_g * 2 + ks) * 32 + laneA) * 4];
            }
            #pragma unroll
            for (int nt = 0; nt < 4; nt++) {
                int nt_g = wn * 4 + nt;
                b[nt] = *(const uint2*)&curB[((nt_g * 2 + ks) * 32 + (lane ^ nt_g)) * 2];
            }
            #pragma unroll
            for (int mt = 0; mt < 4; mt++)
                #pragma unroll
                for (int nt = 0; nt < 4; nt++)
                    mma_tf32(acc[mt][nt], a[mt].x, a[mt].z, a[mt].y, a[mt].w,
                             b[nt].x, b[nt].y);
        }
        if (more) {
            uint32_t* sa = As[buf ^ 1];
            sa[offA[0]] = pa0.x; sa[offA[1]] = pa0.y; sa[offA[2]] = pa0.z; sa[offA[3]] = pa0.w;
            sa += 1024;
            sa[offA[0]] = pa1.x; sa[offA[1]] = pa1.y; sa[offA[2]] = pa1.z; sa[offA[3]] = pa1.w;
            uint32_t* sb = Bs[buf ^ 1];
            sb[offB[0]] = pb0.x; sb[offB[1]] = pb0.y; sb[offB[2]] = pb0.z; sb[offB[3]] = pb0.w;
            sb += 64;
            sb[offB[0]] = pb1.x; sb[offB[1]] = pb1.y; sb[offB[2]] = pb1.z; sb[offB[3]] = pb1.w;
        }
        __syncthreads();
    }

    // epilogue: rows lr, lr+8; cols 2*lc, 2*lc+1 per fragment
    #pragma unroll
    for (int mt = 0; mt < 4; mt++) {
        int r0 = mBase + wm * 64 + mt * 16 + lr;
        #pragma unroll
        for (int nt = 0; nt < 4; nt++) {
            int col = nBase + wn * 32 + nt * 8 + lc * 2;
            float2 bv = *(const float2*)(bias + col);
            float* cc = acc[mt][nt];
            #pragma unroll
            for (int half = 0; half < 2; half++) {
                int r = r0 + half * 8;
                if (r >= M) continue;
                float ox = cc[half * 2 + 0] + bv.x;
                float oy = cc[half * 2 + 1] + bv.y;
                if (EPI == 1) {
                    ox = gelu_exact(ox); oy = gelu_exact(oy);
                    uint32_t* Cu = (uint32_t*)p.out[blockIdx.z];
                    *(uint2*)(Cu + (size_t)r * N + col) = make_uint2(f2tf(ox), f2tf(oy));
                } else {
                    if (EPI == 2) {
                        float2 rv = *(const float2*)(res + (size_t)r * N + col);
                        ox += rv.x; oy += rv.y;
                    }
                    float* Cf = (float*)p.out[blockIdx.z];
                    *(float2*)(Cf + (size_t)r * N + col) = make_float2(ox, oy);
                }
            }
        }
    }
}

// ---------------- fully fused edge kernel (warp per edge) ----------------
// s = q[dst]·k[src]/8 per head; w = exp(s)  (no max shift: |s| is O(0.1), exp-safe;
// softmax is shift-invariant so result identical to reference up to fp rounding)
// den[dst,h] += w;  agg[dst] += w * v[src]   (normalized later in add_ln)
__global__ void edge_fused_kernel(const int* __restrict__ ei,
                                  const float* __restrict__ q, const float* __restrict__ k,
                                  const float* __restrict__ v,
                                  float* __restrict__ den, float* __restrict__ agg, int E) {
    int e = (blockIdx.x * blockDim.x + threadIdx.x) >> 5;
    if (e >= E) return;
    int lane = threadIdx.x & 31;
    int is64 = g_is64;
    int src = load_idx(ei, e, is64);
    int dst = load_idx(ei, E + e, is64);
    const float4* qp = (const float4*)(q + (size_t)dst * HID) + lane * 2;
    const float4* kp = (const float4*)(k + (size_t)src * HID) + lane * 2;
    float4 a0 = qp[0], a1 = qp[1];
    float4 b0 = kp[0], b1 = kp[1];
    float d = a0.x*b0.x + a0.y*b0.y + a0.z*b0.z + a0.w*b0.w
            + a1.x*b1.x + a1.y*b1.y + a1.z*b1.z + a1.w*b1.w;
    d += __shfl_xor_sync(0xffffffffu, d, 1);
    d += __shfl_xor_sync(0xffffffffu, d, 2);
    d += __shfl_xor_sync(0xffffffffu, d, 4);      // all 8 lanes of the head hold the dot
    float w = __expf(d * 0.125f);                 // 1/sqrt(64)
    int h = lane >> 3;
    if ((lane & 7) == 0) atomicAdd(&den[dst * NHEAD + h], w);
    const float4* vp = (const float4*)(v + (size_t)src * HID) + lane * 2;
    float4 v0 = vp[0], v1 = vp[1];
    float* op = agg + (size_t)dst * HID + lane * 8;
    red_add_v4(op,     w * v0.x, w * v0.y, w * v0.z, w * v0.w);
    red_add_v4(op + 4, w * v1.x, w * v1.y, w * v1.z, w * v1.w);
}

// ---------------- host launch ----------------
extern "C" void kernel_launch(void* const* d_in, const int* in_sizes, int n_in,
                              void* d_out, int out_size) {
    const float* x     = (const float*)d_in[0];
    const int*   ei    = (const int*)d_in[1];
    const float* ln1_w = (const float*)d_in[2];
    const float* ln1_b = (const float*)d_in[3];
    const float* ln2_w = (const float*)d_in[4];
    const float* ln2_b = (const float*)d_in[5];
    const float* wq    = (const float*)d_in[6];
    const float* bq    = (const float*)d_in[7];
    const float* wk    = (const float*)d_in[8];
    const float* bk    = (const float*)d_in[9];
    const float* wv    = (const float*)d_in[10];
    const float* bv    = (const float*)d_in[11];
    const float* wskip = (const float*)d_in[12];
    const float* bskip = (const float*)d_in[13];
    const float* w1    = (const float*)d_in[14];
    const float* b1    = (const float*)d_in[15];
    const float* w2    = (const float*)d_in[16];
    const float* b2    = (const float*)d_in[17];

    int n = in_sizes[0] / HID;
    int E = in_sizes[1] / 2;

    static uint32_t *h = nullptr, *mid, *wt0, *wt1, *wt2, *wt3, *w1t, *w2t;
    static float *q, *k, *v, *skip, *agg, *x1, *den;
    if (!h) {
        cudaGetSymbolAddress((void**)&h,      g_h);
        cudaGetSymbolAddress((void**)&q,      g_q);
        cudaGetSymbolAddress((void**)&k,      g_k);
        cudaGetSymbolAddress((void**)&v,      g_v);
        cudaGetSymbolAddress((void**)&skip,   g_skip);
        cudaGetSymbolAddress((void**)&agg,    g_agg);
        cudaGetSymbolAddress((void**)&x1,     g_x1);
        cudaGetSymbolAddress((void**)&mid,    g_mid);
        cudaGetSymbolAddress((void**)&den,    g_den);
        cudaGetSymbolAddress((void**)&wt0,    g_wt);
        wt1 = wt0 + HID * HID; wt2 = wt1 + HID * HID; wt3 = wt2 + HID * HID;
        cudaGetSymbolAddress((void**)&w1t,    g_w1t);
        cudaGetSymbolAddress((void**)&w2t,    g_w2t);
    }

    detect_kernel<<<1, 32>>>(ei, E);
    {
        WCvt wc;
        wc.src[0] = wq;    wc.dst[0] = wt0;
        wc.src[1] = wk;    wc.dst[1] = wt1;
        wc.src[2] = wv;    wc.dst[2] = wt2;
        wc.src[3] = wskip; wc.dst[3] = wt3;
        wc.src[4] = w1;    wc.dst[4] = w1t;
        wc.src[5] = w2;    wc.dst[5] = w2t;
        cvt_weights_kernel<<<512, 256>>>(wc);
    }
    {
        int tot = n * HID;
        init_kernel<<<(tot / 4 + 255) / 256, 256>>>(den, agg, n * NHEAD, tot);
    }
    ln_kernel<<<(n * 32 + 255) / 256, 256>>>(x, ln1_w, ln1_b, h, n);

    {
        GemmPtrs p;
        p.W[0] = wt0; p.bias[0] = bq;    p.out[0] = q;
        p.W[1] = wt1; p.bias[1] = bk;    p.out[1] = k;
        p.W[2] = wt2; p.bias[2] = bv;    p.out[2] = v;
        p.W[3] = wt3; p.bias[3] = bskip; p.out[3] = skip;
        dim3 g((n + 127) / 128, HID / 128, 4);     // 157 x 2 x 4
        gemm_tf32<0><<<g, 256>>>(h, p, nullptr, n, HID, HID);
    }

    edge_fused_kernel<<<(E + 7) / 8, 256>>>(ei, q, k, v, den, agg, E);

    add_ln_kernel<<<(n * 32 + 255) / 256, 256>>>(x, skip, agg, den, ln2_w, ln2_b, x1, h, n);

    {
        GemmPtrs p;
        p.W[0] = w1t; p.bias[0] = b1; p.out[0] = mid;
        dim3 g((n + 127) / 128, (2 * HID) / 128, 1);   // 157 x 4
        gemm_tf32<1><<<g, 256>>>(h, p, nullptr, n, 2 * HID, HID);
    }
    {
        GemmPtrs p;
        p.W[0] = w2t; p.bias[0] = b2; p.out[0] = d_out;
        dim3 g((n + 127) / 128, HID / 128, 1);         // 157 x 2
        gemm_tf32<2><<<g, 256>>>(mid, p, x1, n, HID, 2 * HID);
    }
}

// round 11
// speedup vs baseline: 2.4843x; 1.0754x over previous
#include <cuda_runtime.h>
#include <cstdint>

#define HID 256
#define NHEAD 4
#define MAXN 20000
#define MAXE 320000

// ---------------- scratch (device globals; no allocation allowed) ----------------
__device__ uint32_t g_h   [(size_t)MAXN * HID];        // ln1 out (tf32), reused as h2
__device__ float    g_q   [(size_t)MAXN * HID];
__device__ float    g_k   [(size_t)MAXN * HID];
__device__ float    g_v   [(size_t)MAXN * HID];
__device__ float    g_skip[(size_t)MAXN * HID];        // skip projection
__device__ float    g_agg [(size_t)MAXN * HID];        // unnormalized edge aggregate
__device__ uint32_t g_mid [(size_t)MAXN * 2 * HID];    // FF hidden (tf32)
__device__ float    g_den [MAXN * NHEAD];              // softmax denominators
__device__ int      g_is64;                            // edge_index stored as int64?
// tf32 weight copies
__device__ uint32_t g_wt  [4][HID * HID];              // wq, wk, wv, wskip
__device__ uint32_t g_w1t [HID * 2 * HID];
__device__ uint32_t g_w2t [2 * HID * HID];

// ---------------- helpers ----------------
__device__ __forceinline__ int load_idx(const int* __restrict__ ei, int pos, int is64) {
    return is64 ? ei[(size_t)pos * 2] : ei[pos];
}
__device__ __forceinline__ void red_add_v4(float* p, float a, float b, float c, float d) {
    asm volatile("red.global.add.v4.f32 [%0], {%1,%2,%3,%4};"
                 :: "l"(p), "f"(a), "f"(b), "f"(c), "f"(d) : "memory");
}
__device__ __forceinline__ void red_add_v2(float* p, float a, float b) {
    asm volatile("red.global.add.v2.f32 [%0], {%1,%2};"
                 :: "l"(p), "f"(a), "f"(b) : "memory");
}
__device__ __forceinline__ float gelu_exact(float v) {
    return 0.5f * v * (1.0f + erff(v * 0.7071067811865476f));
}
__device__ __forceinline__ uint32_t f2tf(float x) {
    uint32_t r; asm("cvt.rna.tf32.f32 %0, %1;" : "=r"(r) : "f"(x)); return r;
}
__device__ __forceinline__ void mma_tf32(float* c, uint32_t a0, uint32_t a1, uint32_t a2,
                                         uint32_t a3, uint32_t b0, uint32_t b1) {
    asm volatile("mma.sync.aligned.m16n8k8.row.col.f32.tf32.tf32.f32 "
                 "{%0,%1,%2,%3}, {%4,%5,%6,%7}, {%8,%9}, {%0,%1,%2,%3};"
                 : "+f"(c[0]), "+f"(c[1]), "+f"(c[2]), "+f"(c[3])
                 : "r"(a0), "r"(a1), "r"(a2), "r"(a3), "r"(b0), "r"(b1));
}

// ---------------- dtype detection (1 warp) ----------------
__global__ void detect_kernel(const int* __restrict__ ei, int E) {
    int lane = threadIdx.x;
    int nz = 0;
    for (int i = lane; i < 512 && i < E; i += 32)
        nz |= ei[2 * i + 1];
    #pragma unroll
    for (int o = 16; o > 0; o >>= 1) nz |= __shfl_xor_sync(0xffffffffu, nz, o);
    if (lane == 0) g_is64 = (nz == 0) ? 1 : 0;
}

// ---------------- one-shot weight conversion to tf32 ----------------
struct WCvt { const float* src[6]; uint32_t* dst[6]; };
__global__ void cvt_weights_kernel(WCvt wc) {
    int e4 = (blockIdx.x * blockDim.x + threadIdx.x) * 4;   // 524288 total elements
    int seg, base;
    if (e4 < 262144)      { seg = e4 >> 16; base = seg << 16; }
    else if (e4 < 393216) { seg = 4; base = 262144; }
    else                  { seg = 5; base = 393216; }
    int off = e4 - base;
    float4 v = *(const float4*)(wc.src[seg] + off);
    uint4 o = make_uint4(f2tf(v.x), f2tf(v.y), f2tf(v.z), f2tf(v.w));
    *(uint4*)(wc.dst[seg] + off) = o;
}

// ---------------- init: zero den and agg ----------------
__global__ void init_kernel(float* __restrict__ den, float* __restrict__ agg,
                            int nh, int total) {
    int i = blockIdx.x * blockDim.x + threadIdx.x;
    if (i < nh) den[i] = 0.0f;
    if (i * 4 < total) ((float4*)agg)[i] = make_float4(0.f, 0.f, 0.f, 0.f);
}

// ---------------- LayerNorm (warp per row of 256) -> tf32 out ----------------
__global__ void ln_kernel(const float* __restrict__ x, const float* __restrict__ w,
                          const float* __restrict__ b, uint32_t* __restrict__ out, int n) {
    int row = (blockIdx.x * blockDim.x + threadIdx.x) >> 5;
    if (row >= n) return;
    int lane = threadIdx.x & 31;
    const float4* xp = (const float4*)(x + (size_t)row * HID);
    float4 v0 = xp[lane * 2], v1 = xp[lane * 2 + 1];
    float s  = v0.x + v0.y + v0.z + v0.w + v1.x + v1.y + v1.z + v1.w;
    float sq = v0.x*v0.x + v0.y*v0.y + v0.z*v0.z + v0.w*v0.w
             + v1.x*v1.x + v1.y*v1.y + v1.z*v1.z + v1.w*v1.w;
    #pragma unroll
    for (int o = 16; o > 0; o >>= 1) {
        s  += __shfl_xor_sync(0xffffffffu, s,  o);
        sq += __shfl_xor_sync(0xffffffffu, sq, o);
    }
    float mean = s * (1.0f / HID);
    float var  = sq * (1.0f / HID) - mean * mean;
    float rstd = rsqrtf(var + 1e-5f);
    const float4* wp = (const float4*)w;
    const float4* bp = (const float4*)b;
    uint4* op = (uint4*)(out + (size_t)row * HID);
    #pragma unroll
    for (int i = 0; i < 2; i++) {
        float4 xv = (i == 0) ? v0 : v1;
        float4 wv = wp[lane * 2 + i], bv = bp[lane * 2 + i];
        uint4 o;
        o.x = f2tf((xv.x - mean) * rstd * wv.x + bv.x);
        o.y = f2tf((xv.y - mean) * rstd * wv.y + bv.y);
        o.z = f2tf((xv.z - mean) * rstd * wv.z + bv.z);
        o.w = f2tf((xv.w - mean) * rstd * wv.w + bv.w);
        op[lane * 2 + i] = o;
    }
}

// ---------------- x1 = x + skip + agg/den; dout = x1 + b2; h2 = LN2(x1) ----------------
// x1 is consumed ONLY as FF2's residual, so we store it pre-biased into d_out,
// which the split-K FF2 then red.adds its partial products onto.
__global__ void add_ln_kernel(const float* __restrict__ x, const float* __restrict__ skip,
                              const float* __restrict__ agg, const float* __restrict__ den,
                              const float* __restrict__ w, const float* __restrict__ b,
                              const float* __restrict__ b2,
                              float* __restrict__ dout, uint32_t* __restrict__ hout, int n) {
    int row = (blockIdx.x * blockDim.x + threadIdx.x) >> 5;
    if (row >= n) return;
    int lane = threadIdx.x & 31;
    int h = lane >> 3;
    float d = den[row * NHEAD + h];
    float rden = (d > 0.0f) ? (1.0f / d) : 0.0f;
    const float4* xp = (const float4*)(x    + (size_t)row * HID);
    const float4* sp = (const float4*)(skip + (size_t)row * HID);
    const float4* ap = (const float4*)(agg  + (size_t)row * HID);
    float4 a0 = xp[lane * 2], a1 = xp[lane * 2 + 1];
    float4 c0 = sp[lane * 2], c1 = sp[lane * 2 + 1];
    float4 g0 = ap[lane * 2], g1 = ap[lane * 2 + 1];
    float4 v0 = make_float4(a0.x + c0.x + g0.x * rden, a0.y + c0.y + g0.y * rden,
                            a0.z + c0.z + g0.z * rden, a0.w + c0.w + g0.w * rden);
    float4 v1 = make_float4(a1.x + c1.x + g1.x * rden, a1.y + c1.y + g1.y * rden,
                            a1.z + c1.z + g1.z * rden, a1.w + c1.w + g1.w * rden);
    // d_out seed: x1 + b2
    const float4* b2p = (const float4*)b2;
    float4 t0 = b2p[lane * 2], t1 = b2p[lane * 2 + 1];
    float4* dp = (float4*)(dout + (size_t)row * HID);
    dp[lane * 2]     = make_float4(v0.x + t0.x, v0.y + t0.y, v0.z + t0.z, v0.w + t0.w);
    dp[lane * 2 + 1] = make_float4(v1.x + t1.x, v1.y + t1.y, v1.z + t1.z, v1.w + t1.w);
    float s  = v0.x + v0.y + v0.z + v0.w + v1.x + v1.y + v1.z + v1.w;
    float sq = v0.x*v0.x + v0.y*v0.y + v0.z*v0.z + v0.w*v0.w
             + v1.x*v1.x + v1.y*v1.y + v1.z*v1.z + v1.w*v1.w;
    #pragma unroll
    for (int o = 16; o > 0; o >>= 1) {
        s  += __shfl_xor_sync(0xffffffffu, s,  o);
        sq += __shfl_xor_sync(0xffffffffu, sq, o);
    }
    float mean = s * (1.0f / HID);
    float var  = sq * (1.0f / HID) - mean * mean;
    float rstd = rsqrtf(var + 1e-5f);
    const float4* wp = (const float4*)w;
    const float4* bp = (const float4*)b;
    uint4* op = (uint4*)(hout + (size_t)row * HID);
    #pragma unroll
    for (int i = 0; i < 2; i++) {
        float4 xv = (i == 0) ? v0 : v1;
        float4 wv = wp[lane * 2 + i], bv = bp[lane * 2 + i];
        uint4 o;
        o.x = f2tf((xv.x - mean) * rstd * wv.x + bv.x);
        o.y = f2tf((xv.y - mean) * rstd * wv.y + bv.y);
        o.z = f2tf((xv.z - mean) * rstd * wv.z + bv.z);
        o.w = f2tf((xv.w - mean) * rstd * wv.w + bv.w);
        op[lane * 2 + i] = o;
    }
}

// ---------------- TF32 GEMM, pre-converted operands, hoisted swizzle ------
// EPI 0: bias -> f32 out; 1: bias+GELU -> tf32 out;
// EPI 3: split-K partial -> red.global.add onto pre-seeded f32 out (no bias).
//        blockIdx.z selects K-half: A column offset z*Kloop, W pointer p.W[z].
struct GemmPtrs { const uint32_t* W[4]; const float* bias[4]; void* out[4]; };

template<int EPI>
__global__ __launch_bounds__(256)
void gemm_tf32(const uint32_t* __restrict__ A, GemmPtrs p,
               int M, int N, int K, int Kloop) {
    __shared__ __align__(16) uint32_t As[2][2048];   // 8KB each
    __shared__ __align__(16) uint32_t Bs[2][2048];

    const uint32_t* __restrict__ W    = p.W[blockIdx.z];
    const float* __restrict__    bias = p.bias[blockIdx.z];
    const int aOff = (EPI == 3) ? blockIdx.z * Kloop : 0;

    const int t = threadIdx.x;
    const int lane = t & 31, wid = t >> 5;
    const int wm = wid & 1, wn = wid >> 1;          // 2 x 4 warp grid
    const int mBase = blockIdx.x * 128;
    const int nBase = blockIdx.y * 128;
    const int lr = lane >> 2, lc = lane & 3;

    const int rA = t >> 2,  cA = (t & 3) * 4;       // A: rows rA, rA+64; k cols cA..cA+3
    const int rB = t >> 5,  cB = (t & 31) * 4;      // B: k rows rB, rB+8; cols cB..cB+3

    const int laneA = lane ^ ((lane >> 3) & 3);

    // precompute swizzled store offsets (words) -- loop-invariant
    int offA[4], offB[4];
    {
        int mt = rA >> 4, s1 = (rA >> 3) & 1, lr0 = rA & 7;
        int ks = cA >> 3, s2 = (cA >> 2) & 1;
        int e  = s1 * 2 + s2;
        int blk = (mt * 2 + ks) * 32;
        #pragma unroll
        for (int j = 0; j < 4; j++) {
            int la = 4 * lr0 + j;
            la ^= (la >> 3) & 3;
            offA[j] = (blk + la) * 4 + e;
        }
        int sB = (rB >> 2) & 1, lcb = rB & 3;       // rB in 0..7 -> ks=0
        #pragma unroll
        for (int j = 0; j < 4; j++) {
            int nn = cB + j;
            int nt = nn >> 3, lrb = nn & 7;
            int lb = (4 * lrb + lcb) ^ nt;
            offB[j] = (nt * 2 * 32 + lb) * 2 + sB;
        }
    }

    float acc[4][4][4];
    #pragma unroll
    for (int i = 0; i < 4; i++)
        #pragma unroll
        for (int j = 0; j < 4; j++)
            #pragma unroll
            for (int r = 0; r < 4; r++) acc[i][j][r] = 0.0f;

    const int NK = Kloop >> 4;
    uint4 pa0, pa1, pb0, pb1;
    const uint4 z4 = make_uint4(0u, 0u, 0u, 0u);

    {   // prologue kb=0
        int gr0 = mBase + rA, gr1 = gr0 + 64;
        pa0 = (gr0 < M) ? *(const uint4*)(A + (size_t)gr0 * K + aOff + cA) : z4;
        pa1 = (gr1 < M) ? *(const uint4*)(A + (size_t)gr1 * K + aOff + cA) : z4;
        pb0 = *(const uint4*)(W + (size_t)rB       * N + nBase + cB);
        pb1 = *(const uint4*)(W + (size_t)(rB + 8) * N + nBase + cB);
        uint32_t* sa = As[0];
        sa[offA[0]] = pa0.x; sa[offA[1]] = pa0.y; sa[offA[2]] = pa0.z; sa[offA[3]] = pa0.w;
        sa += 1024;
        sa[offA[0]] = pa1.x; sa[offA[1]] = pa1.y; sa[offA[2]] = pa1.z; sa[offA[3]] = pa1.w;
        uint32_t* sb = Bs[0];
        sb[offB[0]] = pb0.x; sb[offB[1]] = pb0.y; sb[offB[2]] = pb0.z; sb[offB[3]] = pb0.w;
        sb += 64;
        sb[offB[0]] = pb1.x; sb[offB[1]] = pb1.y; sb[offB[2]] = pb1.z; sb[offB[3]] = pb1.w;
    }
    __syncthreads();

    for (int kb = 0; kb < NK; kb++) {
        const int buf = kb & 1;
        const bool more = (kb + 1 < NK);
        if (more) {
            int kofs = (kb + 1) * 16;
            int gr0 = mBase + rA, gr1 = gr0 + 64;
            pa0 = (gr0 < M) ? *(const uint4*)(A + (size_t)gr0 * K + aOff + kofs + cA) : z4;
            pa1 = (gr1 < M) ? *(const uint4*)(A + (size_t)gr1 * K + aOff + kofs + cA) : z4;
            pb0 = *(const uint4*)(W + (size_t)(kofs + rB)     * N + nBase + cB);
            pb1 = *(const uint4*)(W + (size_t)(kofs + rB + 8) * N + nBase + cB);
        }
        const uint32_t* curA = As[buf];
        const uint32_t* curB = Bs[buf];
        #pragma unroll
        for (int ks = 0; ks < 2; ks++) {
            uint4 a[4]; uint2 b[4];
            #pragma unroll
            for (int mt = 0; mt < 4; mt++) {
                int mt_g = wm * 4 + mt;
                a[mt] = *(const uint4*)&curA[((mt_g * 2 + ks) * 32 + laneA) * 4];
            }
            #pragma unroll
            for (int nt = 0; nt < 4; nt++) {
                int nt_g = wn * 4 + nt;
                b[nt] = *(const uint2*)&curB[((nt_g * 2 + ks) * 32 + (lane ^ nt_g)) * 2];
            }
            #pragma unroll
            for (int mt = 0; mt < 4; mt++)
                #pragma unroll
                for (int nt = 0; nt < 4; nt++)
                    mma_tf32(acc[mt][nt], a[mt].x, a[mt].z, a[mt].y, a[mt].w,
                             b[nt].x, b[nt].y);
        }
        if (more) {
            uint32_t* sa = As[buf ^ 1];
            sa[offA[0]] = pa0.x; sa[offA[1]] = pa0.y; sa[offA[2]] = pa0.z; sa[offA[3]] = pa0.w;
            sa += 1024;
            sa[offA[0]] = pa1.x; sa[offA[1]] = pa1.y; sa[offA[2]] = pa1.z; sa[offA[3]] = pa1.w;
            uint32_t* sb = Bs[buf ^ 1];
            sb[offB[0]] = pb0.x; sb[offB[1]] = pb0.y; sb[offB[2]] = pb0.z; sb[offB[3]] = pb0.w;
            sb += 64;
            sb[offB[0]] = pb1.x; sb[offB[1]] = pb1.y; sb[offB[2]] = pb1.z; sb[offB[3]] = pb1.w;
        }
        __syncthreads();
    }

    // epilogue: rows lr, lr+8; cols 2*lc, 2*lc+1 per fragment
    #pragma unroll
    for (int mt = 0; mt < 4; mt++) {
        int r0 = mBase + wm * 64 + mt * 16 + lr;
        #pragma unroll
        for (int nt = 0; nt < 4; nt++) {
            int col = nBase + wn * 32 + nt * 8 + lc * 2;
            float2 bv = make_float2(0.f, 0.f);
            if (EPI != 3) bv = *(const float2*)(bias + col);
            float* cc = acc[mt][nt];
            #pragma unroll
            for (int half = 0; half < 2; half++) {
                int r = r0 + half * 8;
                if (r >= M) continue;
                float ox = cc[half * 2 + 0] + bv.x;
                float oy = cc[half * 2 + 1] + bv.y;
                if (EPI == 1) {
                    ox = gelu_exact(ox); oy = gelu_exact(oy);
                    uint32_t* Cu = (uint32_t*)p.out[blockIdx.z];
                    *(uint2*)(Cu + (size_t)r * N + col) = make_uint2(f2tf(ox), f2tf(oy));
                } else if (EPI == 3) {
                    float* Cf = (float*)p.out[0];
                    red_add_v2(Cf + (size_t)r * N + col, ox, oy);
                } else {
                    float* Cf = (float*)p.out[blockIdx.z];
                    *(float2*)(Cf + (size_t)r * N + col) = make_float2(ox, oy);
                }
            }
        }
    }
}

// ---------------- fully fused edge kernel (warp per edge) ----------------
__global__ void edge_fused_kernel(const int* __restrict__ ei,
                                  const float* __restrict__ q, const float* __restrict__ k,
                                  const float* __restrict__ v,
                                  float* __restrict__ den, float* __restrict__ agg, int E) {
    int e = (blockIdx.x * blockDim.x + threadIdx.x) >> 5;
    if (e >= E) return;
    int lane = threadIdx.x & 31;
    int is64 = g_is64;
    int src = load_idx(ei, e, is64);
    int dst = load_idx(ei, E + e, is64);
    const float4* qp = (const float4*)(q + (size_t)dst * HID) + lane * 2;
    const float4* kp = (const float4*)(k + (size_t)src * HID) + lane * 2;
    float4 a0 = qp[0], a1 = qp[1];
    float4 b0 = kp[0], b1 = kp[1];
    float d = a0.x*b0.x + a0.y*b0.y + a0.z*b0.z + a0.w*b0.w
            + a1.x*b1.x + a1.y*b1.y + a1.z*b1.z + a1.w*b1.w;
    d += __shfl_xor_sync(0xffffffffu, d, 1);
    d += __shfl_xor_sync(0xffffffffu, d, 2);
    d += __shfl_xor_sync(0xffffffffu, d, 4);      // all 8 lanes of the head hold the dot
    float w = __expf(d * 0.125f);                 // 1/sqrt(64)
    int h = lane >> 3;
    if ((lane & 7) == 0) atomicAdd(&den[dst * NHEAD + h], w);
    const float4* vp = (const float4*)(v + (size_t)src * HID) + lane * 2;
    float4 v0 = vp[0], v1 = vp[1];
    float* op = agg + (size_t)dst * HID + lane * 8;
    red_add_v4(op,     w * v0.x, w * v0.y, w * v0.z, w * v0.w);
    red_add_v4(op + 4, w * v1.x, w * v1.y, w * v1.z, w * v1.w);
}

// ---------------- host launch ----------------
extern "C" void kernel_launch(void* const* d_in, const int* in_sizes, int n_in,
                              void* d_out, int out_size) {
    const float* x     = (const float*)d_in[0];
    const int*   ei    = (const int*)d_in[1];
    const float* ln1_w = (const float*)d_in[2];
    const float* ln1_b = (const float*)d_in[3];
    const float* ln2_w = (const float*)d_in[4];
    const float* ln2_b = (const float*)d_in[5];
    const float* wq    = (const float*)d_in[6];
    const float* bq    = (const float*)d_in[7];
    const float* wk    = (const float*)d_in[8];
    const float* bk    = (const float*)d_in[9];
    const float* wv    = (const float*)d_in[10];
    const float* bv    = (const float*)d_in[11];
    const float* wskip = (const float*)d_in[12];
    const float* bskip = (const float*)d_in[13];
    const float* w1    = (const float*)d_in[14];
    const float* b1    = (const float*)d_in[15];
    const float* w2    = (const float*)d_in[16];
    const float* b2    = (const float*)d_in[17];

    int n = in_sizes[0] / HID;
    int E = in_sizes[1] / 2;

    static uint32_t *h = nullptr, *mid, *wt0, *wt1, *wt2, *wt3, *w1t, *w2t;
    static float *q, *k, *v, *skip, *agg, *den;
    static cudaStream_t s2;
    static cudaEvent_t evA, evB;
    if (!h) {
        cudaGetSymbolAddress((void**)&h,      g_h);
        cudaGetSymbolAddress((void**)&q,      g_q);
        cudaGetSymbolAddress((void**)&k,      g_k);
        cudaGetSymbolAddress((void**)&v,      g_v);
        cudaGetSymbolAddress((void**)&skip,   g_skip);
        cudaGetSymbolAddress((void**)&agg,    g_agg);
        cudaGetSymbolAddress((void**)&mid,    g_mid);
        cudaGetSymbolAddress((void**)&den,    g_den);
        cudaGetSymbolAddress((void**)&wt0,    g_wt);
        wt1 = wt0 + HID * HID; wt2 = wt1 + HID * HID; wt3 = wt2 + HID * HID;
        cudaGetSymbolAddress((void**)&w1t,    g_w1t);
        cudaGetSymbolAddress((void**)&w2t,    g_w2t);
        cudaStreamCreateWithFlags(&s2, cudaStreamNonBlocking);
        cudaEventCreateWithFlags(&evA, cudaEventDisableTiming);
        cudaEventCreateWithFlags(&evB, cudaEventDisableTiming);
    }

    detect_kernel<<<1, 32>>>(ei, E);
    {
        WCvt wc;
        wc.src[0] = wq;    wc.dst[0] = wt0;
        wc.src[1] = wk;    wc.dst[1] = wt1;
        wc.src[2] = wv;    wc.dst[2] = wt2;
        wc.src[3] = wskip; wc.dst[3] = wt3;
        wc.src[4] = w1;    wc.dst[4] = w1t;
        wc.src[5] = w2;    wc.dst[5] = w2t;
        cvt_weights_kernel<<<512, 256>>>(wc);
    }
    {
        int tot = n * HID;
        init_kernel<<<(tot / 4 + 255) / 256, 256>>>(den, agg, n * NHEAD, tot);
    }
    ln_kernel<<<(n * 32 + 255) / 256, 256>>>(x, ln1_w, ln1_b, h, n);
    cudaEventRecord(evA, 0);                       // h ready

    // fork: skip projection on s2, overlapped with QKV + edge on the main stream
    cudaStreamWaitEvent(s2, evA, 0);
    {
        GemmPtrs p;
        p.W[0] = wt3; p.bias[0] = bskip; p.out[0] = skip;
        dim3 g((n + 127) / 128, HID / 128, 1);     // 157 x 2
        gemm_tf32<0><<<g, 256, 0, s2>>>(h, p, n, HID, HID, HID);
    }
    cudaEventRecord(evB, s2);

    {
        GemmPtrs p;
        p.W[0] = wt0; p.bias[0] = bq; p.out[0] = q;
        p.W[1] = wt1; p.bias[1] = bk; p.out[1] = k;
        p.W[2] = wt2; p.bias[2] = bv; p.out[2] = v;
        dim3 g((n + 127) / 128, HID / 128, 3);     // 157 x 2 x 3
        gemm_tf32<0><<<g, 256>>>(h, p, n, HID, HID, HID);
    }

    edge_fused_kernel<<<(E + 7) / 8, 256>>>(ei, q, k, v, den, agg, E);

    cudaStreamWaitEvent(0, evB, 0);                // join: skip ready
    add_ln_kernel<<<(n * 32 + 255) / 256, 256>>>(x, skip, agg, den, ln2_w, ln2_b, b2,
                                                 (float*)d_out, h, n);

    {
        GemmPtrs p;
        p.W[0] = w1t; p.bias[0] = b1; p.out[0] = mid;
        dim3 g((n + 127) / 128, (2 * HID) / 128, 1);   // 157 x 4
        gemm_tf32<1><<<g, 256>>>(h, p, n, 2 * HID, HID, HID);
    }
    {
        GemmPtrs p;                                     // split-K=2 onto seeded d_out
        p.W[0] = w2t;             p.bias[0] = b2; p.out[0] = d_out;
        p.W[1] = w2t + HID * HID; p.bias[1] = b2; p.out[1] = d_out;
        dim3 g((n + 127) / 128, HID / 128, 2);          // 157 x 2 x 2
        gemm_tf32<3><<<g, 256>>>(mid, p, n, HID, 2 * HID, HID);
    }
}

// round 13
// speedup vs baseline: 2.6293x; 1.0584x over previous
#include <cuda_runtime.h>
#include <cuda_bf16.h>
#include <cstdint>

#define HID 256
#define NHEAD 4
#define MAXN 20000
#define MAXE 320000

// ---------------- scratch (device globals; no allocation allowed) ----------------
__device__ uint32_t       g_h   [(size_t)MAXN * HID];      // ln1 out (tf32), reused as h2
__device__ __nv_bfloat16  g_q   [(size_t)MAXN * HID];      // bf16 projections
__device__ __nv_bfloat16  g_k   [(size_t)MAXN * HID];
__device__ __nv_bfloat16  g_v   [(size_t)MAXN * HID];
__device__ float          g_skip[(size_t)MAXN * HID];      // skip projection (f32)
__device__ float          g_agg [(size_t)MAXN * HID];      // unnormalized edge aggregate
__device__ uint32_t       g_mid [(size_t)MAXN * 2 * HID];  // FF hidden (tf32)
__device__ float          g_den [MAXN * NHEAD];            // softmax denominators
__device__ int            g_is64;
// tf32 weight copies
__device__ uint32_t g_wt  [4][HID * HID];                  // wq, wk, wv, wskip
__device__ uint32_t g_w1t [HID * 2 * HID];
__device__ uint32_t g_w2t [2 * HID * HID];

// ---------------- helpers ----------------
__device__ __forceinline__ int load_idx(const int* __restrict__ ei, int pos, int is64) {
    return is64 ? ei[(size_t)pos * 2] : ei[pos];
}
__device__ __forceinline__ void red_add_v4(float* p, float a, float b, float c, float d) {
    asm volatile("red.global.add.v4.f32 [%0], {%1,%2,%3,%4};"
                 :: "l"(p), "f"(a), "f"(b), "f"(c), "f"(d) : "memory");
}
__device__ __forceinline__ void red_add_v2(float* p, float a, float b) {
    asm volatile("red.global.add.v2.f32 [%0], {%1,%2};"
                 :: "l"(p), "f"(a), "f"(b) : "memory");
}
__device__ __forceinline__ float gelu_exact(float v) {
    return 0.5f * v * (1.0f + erff(v * 0.7071067811865476f));
}
__device__ __forceinline__ uint32_t f2tf(float x) {
    uint32_t r; asm("cvt.rna.tf32.f32 %0, %1;" : "=r"(r) : "f"(x)); return r;
}
__device__ __forceinline__ void mma_tf32(float* c, uint32_t a0, uint32_t a1, uint32_t a2,
                                         uint32_t a3, uint32_t b0, uint32_t b1) {
    asm volatile("mma.sync.aligned.m16n8k8.row.col.f32.tf32.tf32.f32 "
                 "{%0,%1,%2,%3}, {%4,%5,%6,%7}, {%8,%9}, {%0,%1,%2,%3};"
                 : "+f"(c[0]), "+f"(c[1]), "+f"(c[2]), "+f"(c[3])
                 : "r"(a0), "r"(a1), "r"(a2), "r"(a3), "r"(b0), "r"(b1));
}

// ---------------- dtype detection (1 warp) ----------------
__global__ void detect_kernel(const int* __restrict__ ei, int E) {
    int lane = threadIdx.x;
    int nz = 0;
    for (int i = lane; i < 512 && i < E; i += 32)
        nz |= ei[2 * i + 1];
    #pragma unroll
    for (int o = 16; o > 0; o >>= 1) nz |= __shfl_xor_sync(0xffffffffu, nz, o);
    if (lane == 0) g_is64 = (nz == 0) ? 1 : 0;
}

// ---------------- one-shot weight conversion to tf32 ----------------
struct WCvt { const float* src[6]; uint32_t* dst[6]; };
__global__ void cvt_weights_kernel(WCvt wc) {
    int e4 = (blockIdx.x * blockDim.x + threadIdx.x) * 4;   // 524288 total elements
    int seg, base;
    if (e4 < 262144)      { seg = e4 >> 16; base = seg << 16; }
    else if (e4 < 393216) { seg = 4; base = 262144; }
    else                  { seg = 5; base = 393216; }
    int off = e4 - base;
    float4 v = *(const float4*)(wc.src[seg] + off);
    uint4 o = make_uint4(f2tf(v.x), f2tf(v.y), f2tf(v.z), f2tf(v.w));
    *(uint4*)(wc.dst[seg] + off) = o;
}

// ---------------- init: zero den and agg ----------------
__global__ void init_kernel(float* __restrict__ den, float* __restrict__ agg,
                            int nh, int total) {
    int i = blockIdx.x * blockDim.x + threadIdx.x;
    if (i < nh) den[i] = 0.0f;
    if (i * 4 < total) ((float4*)agg)[i] = make_float4(0.f, 0.f, 0.f, 0.f);
}

// ---------------- LayerNorm (warp per row of 256) -> tf32 out ----------------
__global__ void ln_kernel(const float* __restrict__ x, const float* __restrict__ w,
                          const float* __restrict__ b, uint32_t* __restrict__ out, int n) {
    int row = (blockIdx.x * blockDim.x + threadIdx.x) >> 5;
    if (row >= n) return;
    int lane = threadIdx.x & 31;
    const float4* xp = (const float4*)(x + (size_t)row * HID);
    float4 v0 = xp[lane * 2], v1 = xp[lane * 2 + 1];
    float s  = v0.x + v0.y + v0.z + v0.w + v1.x + v1.y + v1.z + v1.w;
    float sq = v0.x*v0.x + v0.y*v0.y + v0.z*v0.z + v0.w*v0.w
             + v1.x*v1.x + v1.y*v1.y + v1.z*v1.z + v1.w*v1.w;
    #pragma unroll
    for (int o = 16; o > 0; o >>= 1) {
        s  += __shfl_xor_sync(0xffffffffu, s,  o);
        sq += __shfl_xor_sync(0xffffffffu, sq, o);
    }
    float mean = s * (1.0f / HID);
    float var  = sq * (1.0f / HID) - mean * mean;
    float rstd = rsqrtf(var + 1e-5f);
    const float4* wp = (const float4*)w;
    const float4* bp = (const float4*)b;
    uint4* op = (uint4*)(out + (size_t)row * HID);
    #pragma unroll
    for (int i = 0; i < 2; i++) {
        float4 xv = (i == 0) ? v0 : v1;
        float4 wv = wp[lane * 2 + i], bv = bp[lane * 2 + i];
        uint4 o;
        o.x = f2tf((xv.x - mean) * rstd * wv.x + bv.x);
        o.y = f2tf((xv.y - mean) * rstd * wv.y + bv.y);
        o.z = f2tf((xv.z - mean) * rstd * wv.z + bv.z);
        o.w = f2tf((xv.w - mean) * rstd * wv.w + bv.w);
        op[lane * 2 + i] = o;
    }
}

// ---------------- x1 = x + skip + agg/den; dout = x1 + b2; h2 = LN2(x1) ----------------
__global__ void add_ln_kernel(const float* __restrict__ x, const float* __restrict__ skip,
                              const float* __restrict__ agg, const float* __restrict__ den,
                              const float* __restrict__ w, const float* __restrict__ b,
                              const float* __restrict__ b2,
                              float* __restrict__ dout, uint32_t* __restrict__ hout, int n) {
    int row = (blockIdx.x * blockDim.x + threadIdx.x) >> 5;
    if (row >= n) return;
    int lane = threadIdx.x & 31;
    int h = lane >> 3;
    float d = den[row * NHEAD + h];
    float rden = (d > 0.0f) ? (1.0f / d) : 0.0f;
    const float4* xp = (const float4*)(x    + (size_t)row * HID);
    const float4* sp = (const float4*)(skip + (size_t)row * HID);
    const float4* ap = (const float4*)(agg  + (size_t)row * HID);
    float4 a0 = xp[lane * 2], a1 = xp[lane * 2 + 1];
    float4 c0 = sp[lane * 2], c1 = sp[lane * 2 + 1];
    float4 g0 = ap[lane * 2], g1 = ap[lane * 2 + 1];
    float4 v0 = make_float4(a0.x + c0.x + g0.x * rden, a0.y + c0.y + g0.y * rden,
                            a0.z + c0.z + g0.z * rden, a0.w + c0.w + g0.w * rden);
    float4 v1 = make_float4(a1.x + c1.x + g1.x * rden, a1.y + c1.y + g1.y * rden,
                            a1.z + c1.z + g1.z * rden, a1.w + c1.w + g1.w * rden);
    const float4* b2p = (const float4*)b2;
    float4 t0 = b2p[lane * 2], t1 = b2p[lane * 2 + 1];
    float4* dp = (float4*)(dout + (size_t)row * HID);
    dp[lane * 2]     = make_float4(v0.x + t0.x, v0.y + t0.y, v0.z + t0.z, v0.w + t0.w);
    dp[lane * 2 + 1] = make_float4(v1.x + t1.x, v1.y + t1.y, v1.z + t1.z, v1.w + t1.w);
    float s  = v0.x + v0.y + v0.z + v0.w + v1.x + v1.y + v1.z + v1.w;
    float sq = v0.x*v0.x + v0.y*v0.y + v0.z*v0.z + v0.w*v0.w
             + v1.x*v1.x + v1.y*v1.y + v1.z*v1.z + v1.w*v1.w;
    #pragma unroll
    for (int o = 16; o > 0; o >>= 1) {
        s  += __shfl_xor_sync(0xffffffffu, s,  o);
        sq += __shfl_xor_sync(0xffffffffu, sq, o);
    }
    float mean = s * (1.0f / HID);
    float var  = sq * (1.0f / HID) - mean * mean;
    float rstd = rsqrtf(var + 1e-5f);
    const float4* wp = (const float4*)w;
    const float4* bp = (const float4*)b;
    uint4* op = (uint4*)(hout + (size_t)row * HID);
    #pragma unroll
    for (int i = 0; i < 2; i++) {
        float4 xv = (i == 0) ? v0 : v1;
        float4 wv = wp[lane * 2 + i], bv = bp[lane * 2 + i];
        uint4 o;
        o.x = f2tf((xv.x - mean) * rstd * wv.x + bv.x);
        o.y = f2tf((xv.y - mean) * rstd * wv.y + bv.y);
        o.z = f2tf((xv.z - mean) * rstd * wv.z + bv.z);
        o.w = f2tf((xv.w - mean) * rstd * wv.w + bv.w);
        op[lane * 2 + i] = o;
    }
}

// ---------------- TF32 GEMM, pre-converted operands, hoisted swizzle ------
// EPI 0: bias -> f32 out; 1: bias+GELU -> tf32 out; 3: split-K red.add onto seeded f32;
// EPI 4: bias -> bf16 out (q/k/v)
struct GemmPtrs { const uint32_t* W[4]; const float* bias[4]; void* out[4]; };

template<int EPI>
__global__ __launch_bounds__(256)
void gemm_tf32(const uint32_t* __restrict__ A, GemmPtrs p,
               int M, int N, int K, int Kloop) {
    __shared__ __align__(16) uint32_t As[2][2048];   // 8KB each
    __shared__ __align__(16) uint32_t Bs[2][2048];

    const uint32_t* __restrict__ W    = p.W[blockIdx.z];
    const float* __restrict__    bias = p.bias[blockIdx.z];
    const int aOff = (EPI == 3) ? blockIdx.z * Kloop : 0;

    const int t = threadIdx.x;
    const int lane = t & 31, wid = t >> 5;
    const int wm = wid & 1, wn = wid >> 1;          // 2 x 4 warp grid
    const int mBase = blockIdx.x * 128;
    const int nBase = blockIdx.y * 128;
    const int lr = lane >> 2, lc = lane & 3;

    const int rA = t >> 2,  cA = (t & 3) * 4;
    const int rB = t >> 5,  cB = (t & 31) * 4;

    const int laneA = lane ^ ((lane >> 3) & 3);

    int offA[4], offB[4];
    {
        int mt = rA >> 4, s1 = (rA >> 3) & 1, lr0 = rA & 7;
        int ks = cA >> 3, s2 = (cA >> 2) & 1;
        int e  = s1 * 2 + s2;
        int blk = (mt * 2 + ks) * 32;
        #pragma unroll
        for (int j = 0; j < 4; j++) {
            int la = 4 * lr0 + j;
            la ^= (la >> 3) & 3;
            offA[j] = (blk + la) * 4 + e;
        }
        int sB = (rB >> 2) & 1, lcb = rB & 3;
        #pragma unroll
        for (int j = 0; j < 4; j++) {
            int nn = cB + j;
            int nt = nn >> 3, lrb = nn & 7;
            int lb = (4 * lrb + lcb) ^ nt;
            offB[j] = (nt * 2 * 32 + lb) * 2 + sB;
        }
    }

    float acc[4][4][4];
    #pragma unroll
    for (int i = 0; i < 4; i++)
        #pragma unroll
        for (int j = 0; j < 4; j++)
            #pragma unroll
            for (int r = 0; r < 4; r++) acc[i][j][r] = 0.0f;

    const int NK = Kloop >> 4;
    uint4 pa0, pa1, pb0, pb1;
    const uint4 z4 = make_uint4(0u, 0u, 0u, 0u);

    {   // prologue kb=0
        int gr0 = mBase + rA, gr1 = gr0 + 64;
        pa0 = (gr0 < M) ? *(const uint4*)(A + (size_t)gr0 * K + aOff + cA) : z4;
        pa1 = (gr1 < M) ? *(const uint4*)(A + (size_t)gr1 * K + aOff + cA) : z4;
        pb0 = *(const uint4*)(W + (size_t)rB       * N + nBase + cB);
        pb1 = *(const uint4*)(W + (size_t)(rB + 8) * N + nBase + cB);
        uint32_t* sa = As[0];
        sa[offA[0]] = pa0.x; sa[offA[1]] = pa0.y; sa[offA[2]] = pa0.z; sa[offA[3]] = pa0.w;
        sa += 1024;
        sa[offA[0]] = pa1.x; sa[offA[1]] = pa1.y; sa[offA[2]] = pa1.z; sa[offA[3]] = pa1.w;
        uint32_t* sb = Bs[0];
        sb[offB[0]] = pb0.x; sb[offB[1]] = pb0.y; sb[offB[2]] = pb0.z; sb[offB[3]] = pb0.w;
        sb += 64;
        sb[offB[0]] = pb1.x; sb[offB[1]] = pb1.y; sb[offB[2]] = pb1.z; sb[offB[3]] = pb1.w;
    }
    __syncthreads();

    for (int kb = 0; kb < NK; kb++) {
        const int buf = kb & 1;
        const bool more = (kb + 1 < NK);
        if (more) {
            int kofs = (kb + 1) * 16;
            int gr0 = mBase + rA, gr1 = gr0 + 64;
            pa0 = (gr0 < M) ? *(const uint4*)(A + (size_t)gr0 * K + aOff + kofs + cA) : z4;
            pa1 = (gr1 < M) ? *(const uint4*)(A + (size_t)gr1 * K + aOff + kofs + cA) : z4;
            pb0 = *(const uint4*)(W + (size_t)(kofs + rB)     * N + nBase + cB);
            pb1 = *(const uint4*)(W + (size_t)(kofs + rB + 8) * N + nBase + cB);
        }
        const uint32_t* curA = As[buf];
        const uint32_t* curB = Bs[buf];
        #pragma unroll
        for (int ks = 0; ks < 2; ks++) {
            uint4 a[4]; uint2 b[4];
            #pragma unroll
            for (int mt = 0; mt < 4; mt++) {
                int mt_g = wm * 4 + mt;
                a[mt] = *(const uint4*)&curA[((mt_g * 2 + ks) * 32 + laneA) * 4];
            }
            #pragma unroll
            for (int nt = 0; nt < 4; nt++) {
                int nt_g = wn * 4 + nt;
                b[nt] = *(const uint2*)&curB[((nt_g * 2 + ks) * 32 + (lane ^ nt_g)) * 2];
            }
            #pragma unroll
            for (int mt = 0; mt < 4; mt++)
                #pragma unroll
                for (int nt = 0; nt < 4; nt++)
                    mma_tf32(acc[mt][nt], a[mt].x, a[mt].z, a[mt].y, a[mt].w,
                             b[nt].x, b[nt].y);
        }
        if (more) {
            uint32_t* sa = As[buf ^ 1];
            sa[offA[0]] = pa0.x; sa[offA[1]] = pa0.y; sa[offA[2]] = pa0.z; sa[offA[3]] = pa0.w;
            sa += 1024;
            sa[offA[0]] = pa1.x; sa[offA[1]] = pa1.y; sa[offA[2]] = pa1.z; sa[offA[3]] = pa1.w;
            uint32_t* sb = Bs[buf ^ 1];
            sb[offB[0]] = pb0.x; sb[offB[1]] = pb0.y; sb[offB[2]] = pb0.z; sb[offB[3]] = pb0.w;
            sb += 64;
            sb[offB[0]] = pb1.x; sb[offB[1]] = pb1.y; sb[offB[2]] = pb1.z; sb[offB[3]] = pb1.w;
        }
        __syncthreads();
    }

    #pragma unroll
    for (int mt = 0; mt < 4; mt++) {
        int r0 = mBase + wm * 64 + mt * 16 + lr;
        #pragma unroll
        for (int nt = 0; nt < 4; nt++) {
            int col = nBase + wn * 32 + nt * 8 + lc * 2;
            float2 bv = make_float2(0.f, 0.f);
            if (EPI != 3) bv = *(const float2*)(bias + col);
            float* cc = acc[mt][nt];
            #pragma unroll
            for (int half = 0; half < 2; half++) {
                int r = r0 + half * 8;
                if (r >= M) continue;
                float ox = cc[half * 2 + 0] + bv.x;
                float oy = cc[half * 2 + 1] + bv.y;
                if (EPI == 1) {
                    ox = gelu_exact(ox); oy = gelu_exact(oy);
                    uint32_t* Cu = (uint32_t*)p.out[blockIdx.z];
                    *(uint2*)(Cu + (size_t)r * N + col) = make_uint2(f2tf(ox), f2tf(oy));
                } else if (EPI == 3) {
                    float* Cf = (float*)p.out[0];
                    red_add_v2(Cf + (size_t)r * N + col, ox, oy);
                } else if (EPI == 4) {
                    __nv_bfloat16* Cb = (__nv_bfloat16*)p.out[blockIdx.z];
                    *(__nv_bfloat162*)(Cb + (size_t)r * N + col) =
                        __float22bfloat162_rn(make_float2(ox, oy));
                } else {
                    float* Cf = (float*)p.out[blockIdx.z];
                    *(float2*)(Cf + (size_t)r * N + col) = make_float2(ox, oy);
                }
            }
        }
    }
}

// ---------------- fully fused edge kernel (warp per edge, bf16 q/k/v) ----------------
__global__ void edge_fused_kernel(const int* __restrict__ ei,
                                  const __nv_bfloat16* __restrict__ q,
                                  const __nv_bfloat16* __restrict__ k,
                                  const __nv_bfloat16* __restrict__ v,
                                  float* __restrict__ den, float* __restrict__ agg, int E) {
    int e = (blockIdx.x * blockDim.x + threadIdx.x) >> 5;
    if (e >= E) return;
    int lane = threadIdx.x & 31;
    int is64 = g_is64;
    int src = load_idx(ei, e, is64);
    int dst = load_idx(ei, E + e, is64);
    // lane covers elements [lane*8, lane*8+8): one uint4 = 8 bf16
    uint4 qv = ((const uint4*)(q + (size_t)dst * HID))[lane];
    uint4 kv = ((const uint4*)(k + (size_t)src * HID))[lane];
    float d = 0.0f;
    {
        const __nv_bfloat162* qh = (const __nv_bfloat162*)&qv;
        const __nv_bfloat162* kh = (const __nv_bfloat162*)&kv;
        #pragma unroll
        for (int i = 0; i < 4; i++) {
            float2 qa = __bfloat1622float2(qh[i]);
            float2 ka = __bfloat1622float2(kh[i]);
            d += qa.x * ka.x + qa.y * ka.y;
        }
    }
    d += __shfl_xor_sync(0xffffffffu, d, 1);
    d += __shfl_xor_sync(0xffffffffu, d, 2);
    d += __shfl_xor_sync(0xffffffffu, d, 4);      // 8 lanes of a head hold the dot
    float w = __expf(d * 0.125f);                 // 1/sqrt(64)
    int h = lane >> 3;
    if ((lane & 7) == 0) atomicAdd(&den[dst * NHEAD + h], w);
    uint4 vv = ((const uint4*)(v + (size_t)src * HID))[lane];
    const __nv_bfloat162* vh = (const __nv_bfloat162*)&vv;
    float2 f0 = __bfloat1622float2(vh[0]);
    float2 f1 = __bfloat1622float2(vh[1]);
    float2 f2 = __bfloat1622float2(vh[2]);
    float2 f3 = __bfloat1622float2(vh[3]);
    float* op = agg + (size_t)dst * HID + lane * 8;
    red_add_v4(op,     w * f0.x, w * f0.y, w * f1.x, w * f1.y);
    red_add_v4(op + 4, w * f2.x, w * f2.y, w * f3.x, w * f3.y);
}

// ---------------- host launch ----------------
extern "C" void kernel_launch(void* const* d_in, const int* in_sizes, int n_in,
                              void* d_out, int out_size) {
    const float* x     = (const float*)d_in[0];
    const int*   ei    = (const int*)d_in[1];
    const float* ln1_w = (const float*)d_in[2];
    const float* ln1_b = (const float*)d_in[3];
    const float* ln2_w = (const float*)d_in[4];
    const float* ln2_b = (const float*)d_in[5];
    const float* wq    = (const float*)d_in[6];
    const float* bq    = (const float*)d_in[7];
    const float* wk    = (const float*)d_in[8];
    const float* bk    = (const float*)d_in[9];
    const float* wv    = (const float*)d_in[10];
    const float* bv    = (const float*)d_in[11];
    const float* wskip = (const float*)d_in[12];
    const float* bskip = (const float*)d_in[13];
    const float* w1    = (const float*)d_in[14];
    const float* b1    = (const float*)d_in[15];
    const float* w2    = (const float*)d_in[16];
    const float* b2    = (const float*)d_in[17];

    int n = in_sizes[0] / HID;
    int E = in_sizes[1] / 2;

    static uint32_t *h = nullptr, *mid, *wt0, *wt1, *wt2, *wt3, *w1t, *w2t;
    static __nv_bfloat16 *q, *k, *v;
    static float *skip, *agg, *den;
    static cudaStream_t s2;
    static cudaEvent_t ev0, evA, evB, evC;
    if (!h) {
        cudaGetSymbolAddress((void**)&h,      g_h);
        cudaGetSymbolAddress((void**)&q,      g_q);
        cudaGetSymbolAddress((void**)&k,      g_k);
        cudaGetSymbolAddress((void**)&v,      g_v);
        cudaGetSymbolAddress((void**)&skip,   g_skip);
        cudaGetSymbolAddress((void**)&agg,    g_agg);
        cudaGetSymbolAddress((void**)&mid,    g_mid);
        cudaGetSymbolAddress((void**)&den,    g_den);
        cudaGetSymbolAddress((void**)&wt0,    g_wt);
        wt1 = wt0 + HID * HID; wt2 = wt1 + HID * HID; wt3 = wt2 + HID * HID;
        cudaGetSymbolAddress((void**)&w1t,    g_w1t);
        cudaGetSymbolAddress((void**)&w2t,    g_w2t);
        cudaStreamCreateWithFlags(&s2, cudaStreamNonBlocking);
        cudaEventCreateWithFlags(&ev0, cudaEventDisableTiming);
        cudaEventCreateWithFlags(&evA, cudaEventDisableTiming);
        cudaEventCreateWithFlags(&evB, cudaEventDisableTiming);
        cudaEventCreateWithFlags(&evC, cudaEventDisableTiming);
    }

    // Legal capture fork: s2's FIRST node must wait on an event recorded on the
    // capture (main) stream. R12 violated this by launching on s2 before any fork.
    cudaEventRecord(ev0, 0);
    cudaStreamWaitEvent(s2, ev0, 0);

    // s2: weight conversion, overlapped with detect/init/ln on the main stream
    {
        WCvt wc;
        wc.src[0] = wq;    wc.dst[0] = wt0;
        wc.src[1] = wk;    wc.dst[1] = wt1;
        wc.src[2] = wv;    wc.dst[2] = wt2;
        wc.src[3] = wskip; wc.dst[3] = wt3;
        wc.src[4] = w1;    wc.dst[4] = w1t;
        wc.src[5] = w2;    wc.dst[5] = w2t;
        cvt_weights_kernel<<<512, 256, 0, s2>>>(wc);
    }
    cudaEventRecord(evC, s2);                      // weights ready

    detect_kernel<<<1, 32>>>(ei, E);
    {
        int tot = n * HID;
        init_kernel<<<(tot / 4 + 255) / 256, 256>>>(den, agg, n * NHEAD, tot);
    }
    ln_kernel<<<(n * 32 + 255) / 256, 256>>>(x, ln1_w, ln1_b, h, n);
    cudaEventRecord(evA, 0);                       // h ready

    // s2: skip projection (needs weights [already on s2] + h [evA])
    cudaStreamWaitEvent(s2, evA, 0);
    {
        GemmPtrs p;
        p.W[0] = wt3; p.bias[0] = bskip; p.out[0] = skip;
        dim3 g((n + 127) / 128, HID / 128, 1);     // 157 x 2
        gemm_tf32<0><<<g, 256, 0, s2>>>(h, p, n, HID, HID, HID);
    }
    cudaEventRecord(evB, s2);

    cudaStreamWaitEvent(0, evC, 0);                // main: wait for weights
    {
        GemmPtrs p;
        p.W[0] = wt0; p.bias[0] = bq; p.out[0] = q;
        p.W[1] = wt1; p.bias[1] = bk; p.out[1] = k;
        p.W[2] = wt2; p.bias[2] = bv; p.out[2] = v;
        dim3 g((n + 127) / 128, HID / 128, 3);     // 157 x 2 x 3
        gemm_tf32<4><<<g, 256>>>(h, p, n, HID, HID, HID);
    }

    edge_fused_kernel<<<(E + 7) / 8, 256>>>(ei, q, k, v, den, agg, E);

    cudaStreamWaitEvent(0, evB, 0);                // join: skip ready
    add_ln_kernel<<<(n * 32 + 255) / 256, 256>>>(x, skip, agg, den, ln2_w, ln2_b, b2,
                                                 (float*)d_out, h, n);

    {
        GemmPtrs p;
        p.W[0] = w1t; p.bias[0] = b1; p.out[0] = mid;
        dim3 g((n + 127) / 128, (2 * HID) / 128, 1);   // 157 x 4
        gemm_tf32<1><<<g, 256>>>(h, p, n, 2 * HID, HID, HID);
    }
    {
        GemmPtrs p;                                     // split-K=2 onto seeded d_out
        p.W[0] = w2t;             p.bias[0] = b2; p.out[0] = d_out;
        p.W[1] = w2t + HID * HID; p.bias[1] = b2; p.out[1] = d_out;
        dim3 g((n + 127) / 128, HID / 128, 2);          // 157 x 2 x 2
        gemm_tf32<3><<<g, 256>>>(mid, p, n, HID, 2 * HID, HID);
    }
}

// round 14
// speedup vs baseline: 3.0937x; 1.1766x over previous
#include <cuda_runtime.h>
#include <cuda_bf16.h>
#include <cstdint>

#define HID 256
#define NHEAD 4
#define MAXN 20000
#define MAXE 320000
#define SCAN_T 1024

// ---------------- scratch (device globals; no allocation allowed) ----------------
__device__ uint32_t       g_h   [(size_t)MAXN * HID];      // ln1 out (tf32), reused as h2
__device__ __nv_bfloat16  g_q   [(size_t)MAXN * HID];      // bf16 projections
__device__ __nv_bfloat16  g_k   [(size_t)MAXN * HID];
__device__ __nv_bfloat16  g_v   [(size_t)MAXN * HID];
__device__ float          g_skip[(size_t)MAXN * HID];      // skip projection (f32)
__device__ float          g_agg [(size_t)MAXN * HID];      // edge aggregate (written by CSR kernel)
__device__ uint32_t       g_mid [(size_t)MAXN * 2 * HID];  // FF hidden (tf32)
__device__ float          g_den [MAXN * NHEAD];            // softmax denominators
__device__ int            g_is64;
// CSR scratch
__device__ int g_count [MAXN];
__device__ int g_rowptr[MAXN + 1];
__device__ int g_wpos  [MAXN];
__device__ int g_csrsrc[MAXE];
// tf32 weight copies
__device__ uint32_t g_wt  [4][HID * HID];                  // wq, wk, wv, wskip
__device__ uint32_t g_w1t [HID * 2 * HID];
__device__ uint32_t g_w2t [2 * HID * HID];

// ---------------- helpers ----------------
__device__ __forceinline__ int load_idx(const int* __restrict__ ei, int pos, int is64) {
    return is64 ? ei[(size_t)pos * 2] : ei[pos];
}
__device__ __forceinline__ void red_add_v2(float* p, float a, float b) {
    asm volatile("red.global.add.v2.f32 [%0], {%1,%2};"
                 :: "l"(p), "f"(a), "f"(b) : "memory");
}
__device__ __forceinline__ float gelu_exact(float v) {
    return 0.5f * v * (1.0f + erff(v * 0.7071067811865476f));
}
__device__ __forceinline__ uint32_t f2tf(float x) {
    uint32_t r; asm("cvt.rna.tf32.f32 %0, %1;" : "=r"(r) : "f"(x)); return r;
}
__device__ __forceinline__ void mma_tf32(float* c, uint32_t a0, uint32_t a1, uint32_t a2,
                                         uint32_t a3, uint32_t b0, uint32_t b1) {
    asm volatile("mma.sync.aligned.m16n8k8.row.col.f32.tf32.tf32.f32 "
                 "{%0,%1,%2,%3}, {%4,%5,%6,%7}, {%8,%9}, {%0,%1,%2,%3};"
                 : "+f"(c[0]), "+f"(c[1]), "+f"(c[2]), "+f"(c[3])
                 : "r"(a0), "r"(a1), "r"(a2), "r"(a3), "r"(b0), "r"(b1));
}

// ---------------- dtype detection (1 warp) ----------------
__global__ void detect_kernel(const int* __restrict__ ei, int E) {
    int lane = threadIdx.x;
    int nz = 0;
    for (int i = lane; i < 512 && i < E; i += 32)
        nz |= ei[2 * i + 1];
    #pragma unroll
    for (int o = 16; o > 0; o >>= 1) nz |= __shfl_xor_sync(0xffffffffu, nz, o);
    if (lane == 0) g_is64 = (nz == 0) ? 1 : 0;
}

// ---------------- one-shot weight conversion to tf32 ----------------
struct WCvt { const float* src[6]; uint32_t* dst[6]; };
__global__ void cvt_weights_kernel(WCvt wc) {
    int e4 = (blockIdx.x * blockDim.x + threadIdx.x) * 4;   // 524288 total elements
    int seg, base;
    if (e4 < 262144)      { seg = e4 >> 16; base = seg << 16; }
    else if (e4 < 393216) { seg = 4; base = 262144; }
    else                  { seg = 5; base = 393216; }
    int off = e4 - base;
    float4 v = *(const float4*)(wc.src[seg] + off);
    uint4 o = make_uint4(f2tf(v.x), f2tf(v.y), f2tf(v.z), f2tf(v.w));
    *(uint4*)(wc.dst[seg] + off) = o;
}

// ---------------- init: zero degree counters ----------------
__global__ void init_kernel(int* __restrict__ count, int n) {
    int i = blockIdx.x * blockDim.x + threadIdx.x;
    if (i < n) count[i] = 0;
}

// ---------------- CSR pass 1: degree count ----------------
__global__ void count_kernel(const int* __restrict__ ei, int* __restrict__ count, int E) {
    int e = blockIdx.x * blockDim.x + threadIdx.x;
    if (e >= E) return;
    int dst = load_idx(ei, E + e, g_is64);
    atomicAdd(&count[dst], 1);
}

// ---------------- CSR pass 2: exclusive scan (single block) ----------------
__global__ void scan_kernel(const int* __restrict__ count, int* __restrict__ rowptr,
                            int* __restrict__ wpos, int n) {
    __shared__ int part[SCAN_T];
    int t = threadIdx.x;
    int per = (n + SCAN_T - 1) / SCAN_T;
    int start = t * per;
    int end = min(start + per, n);
    int s = 0;
    for (int i = start; i < end; i++) s += count[i];
    part[t] = s;
    __syncthreads();
    for (int off = 1; off < SCAN_T; off <<= 1) {
        int vv = (t >= off) ? part[t - off] : 0;
        __syncthreads();
        part[t] += vv;
        __syncthreads();
    }
    int prefix = (t == 0) ? 0 : part[t - 1];
    for (int i = start; i < end; i++) {
        rowptr[i] = prefix;
        wpos[i]   = prefix;
        prefix += count[i];
    }
    if (t == SCAN_T - 1) rowptr[n] = part[SCAN_T - 1];
}

// ---------------- CSR pass 3: scatter src by dst ----------------
__global__ void scatter_kernel(const int* __restrict__ ei, int* __restrict__ wpos,
                               int* __restrict__ csrsrc, int E) {
    int e = blockIdx.x * blockDim.x + threadIdx.x;
    if (e >= E) return;
    int is64 = g_is64;
    int src = load_idx(ei, e, is64);
    int dst = load_idx(ei, E + e, is64);
    int pos = atomicAdd(&wpos[dst], 1);
    csrsrc[pos] = src;
}

// ---------------- LayerNorm (warp per row of 256) -> tf32 out ----------------
__global__ void ln_kernel(const float* __restrict__ x, const float* __restrict__ w,
                          const float* __restrict__ b, uint32_t* __restrict__ out, int n) {
    int row = (blockIdx.x * blockDim.x + threadIdx.x) >> 5;
    if (row >= n) return;
    int lane = threadIdx.x & 31;
    const float4* xp = (const float4*)(x + (size_t)row * HID);
    float4 v0 = xp[lane * 2], v1 = xp[lane * 2 + 1];
    float s  = v0.x + v0.y + v0.z + v0.w + v1.x + v1.y + v1.z + v1.w;
    float sq = v0.x*v0.x + v0.y*v0.y + v0.z*v0.z + v0.w*v0.w
             + v1.x*v1.x + v1.y*v1.y + v1.z*v1.z + v1.w*v1.w;
    #pragma unroll
    for (int o = 16; o > 0; o >>= 1) {
        s  += __shfl_xor_sync(0xffffffffu, s,  o);
        sq += __shfl_xor_sync(0xffffffffu, sq, o);
    }
    float mean = s * (1.0f / HID);
    float var  = sq * (1.0f / HID) - mean * mean;
    float rstd = rsqrtf(var + 1e-5f);
    const float4* wp = (const float4*)w;
    const float4* bp = (const float4*)b;
    uint4* op = (uint4*)(out + (size_t)row * HID);
    #pragma unroll
    for (int i = 0; i < 2; i++) {
        float4 xv = (i == 0) ? v0 : v1;
        float4 wv = wp[lane * 2 + i], bv = bp[lane * 2 + i];
        uint4 o;
        o.x = f2tf((xv.x - mean) * rstd * wv.x + bv.x);
        o.y = f2tf((xv.y - mean) * rstd * wv.y + bv.y);
        o.z = f2tf((xv.z - mean) * rstd * wv.z + bv.z);
        o.w = f2tf((xv.w - mean) * rstd * wv.w + bv.w);
        op[lane * 2 + i] = o;
    }
}

// ---------------- x1 = x + skip + agg/den; dout = x1 + b2; h2 = LN2(x1) ----------------
__global__ void add_ln_kernel(const float* __restrict__ x, const float* __restrict__ skip,
                              const float* __restrict__ agg, const float* __restrict__ den,
                              const float* __restrict__ w, const float* __restrict__ b,
                              const float* __restrict__ b2,
                              float* __restrict__ dout, uint32_t* __restrict__ hout, int n) {
    int row = (blockIdx.x * blockDim.x + threadIdx.x) >> 5;
    if (row >= n) return;
    int lane = threadIdx.x & 31;
    int h = lane >> 3;
    float d = den[row * NHEAD + h];
    float rden = (d > 0.0f) ? (1.0f / d) : 0.0f;
    const float4* xp = (const float4*)(x    + (size_t)row * HID);
    const float4* sp = (const float4*)(skip + (size_t)row * HID);
    const float4* ap = (const float4*)(agg  + (size_t)row * HID);
    float4 a0 = xp[lane * 2], a1 = xp[lane * 2 + 1];
    float4 c0 = sp[lane * 2], c1 = sp[lane * 2 + 1];
    float4 g0 = ap[lane * 2], g1 = ap[lane * 2 + 1];
    float4 v0 = make_float4(a0.x + c0.x + g0.x * rden, a0.y + c0.y + g0.y * rden,
                            a0.z + c0.z + g0.z * rden, a0.w + c0.w + g0.w * rden);
    float4 v1 = make_float4(a1.x + c1.x + g1.x * rden, a1.y + c1.y + g1.y * rden,
                            a1.z + c1.z + g1.z * rden, a1.w + c1.w + g1.w * rden);
    const float4* b2p = (const float4*)b2;
    float4 t0 = b2p[lane * 2], t1 = b2p[lane * 2 + 1];
    float4* dp = (float4*)(dout + (size_t)row * HID);
    dp[lane * 2]     = make_float4(v0.x + t0.x, v0.y + t0.y, v0.z + t0.z, v0.w + t0.w);
    dp[lane * 2 + 1] = make_float4(v1.x + t1.x, v1.y + t1.y, v1.z + t1.z, v1.w + t1.w);
    float s  = v0.x + v0.y + v0.z + v0.w + v1.x + v1.y + v1.z + v1.w;
    float sq = v0.x*v0.x + v0.y*v0.y + v0.z*v0.z + v0.w*v0.w
             + v1.x*v1.x + v1.y*v1.y + v1.z*v1.z + v1.w*v1.w;
    #pragma unroll
    for (int o = 16; o > 0; o >>= 1) {
        s  += __shfl_xor_sync(0xffffffffu, s,  o);
        sq += __shfl_xor_sync(0xffffffffu, sq, o);
    }
    float mean = s * (1.0f / HID);
    float var  = sq * (1.0f / HID) - mean * mean;
    float rstd = rsqrtf(var + 1e-5f);
    const float4* wp = (const float4*)w;
    const float4* bp = (const float4*)b;
    uint4* op = (uint4*)(hout + (size_t)row * HID);
    #pragma unroll
    for (int i = 0; i < 2; i++) {
        float4 xv = (i == 0) ? v0 : v1;
        float4 wv = wp[lane * 2 + i], bv = bp[lane * 2 + i];
        uint4 o;
        o.x = f2tf((xv.x - mean) * rstd * wv.x + bv.x);
        o.y = f2tf((xv.y - mean) * rstd * wv.y + bv.y);
        o.z = f2tf((xv.z - mean) * rstd * wv.z + bv.z);
        o.w = f2tf((xv.w - mean) * rstd * wv.w + bv.w);
        op[lane * 2 + i] = o;
    }
}

// ---------------- TF32 GEMM, pre-converted operands, hoisted swizzle ------
// EPI 0: bias -> f32 out; 1: bias+GELU -> tf32 out; 3: split-K red.add onto seeded f32;
// EPI 4: bias -> bf16 out (q/k/v)
struct GemmPtrs { const uint32_t* W[4]; const float* bias[4]; void* out[4]; };

template<int EPI>
__global__ __launch_bounds__(256)
void gemm_tf32(const uint32_t* __restrict__ A, GemmPtrs p,
               int M, int N, int K, int Kloop) {
    __shared__ __align__(16) uint32_t As[2][2048];   // 8KB each
    __shared__ __align__(16) uint32_t Bs[2][2048];

    const uint32_t* __restrict__ W    = p.W[blockIdx.z];
    const float* __restrict__    bias = p.bias[blockIdx.z];
    const int aOff = (EPI == 3) ? blockIdx.z * Kloop : 0;

    const int t = threadIdx.x;
    const int lane = t & 31, wid = t >> 5;
    const int wm = wid & 1, wn = wid >> 1;          // 2 x 4 warp grid
    const int mBase = blockIdx.x * 128;
    const int nBase = blockIdx.y * 128;
    const int lr = lane >> 2, lc = lane & 3;

    const int rA = t >> 2,  cA = (t & 3) * 4;
    const int rB = t >> 5,  cB = (t & 31) * 4;

    const int laneA = lane ^ ((lane >> 3) & 3);

    int offA[4], offB[4];
    {
        int mt = rA >> 4, s1 = (rA >> 3) & 1, lr0 = rA & 7;
        int ks = cA >> 3, s2 = (cA >> 2) & 1;
        int e  = s1 * 2 + s2;
        int blk = (mt * 2 + ks) * 32;
        #pragma unroll
        for (int j = 0; j < 4; j++) {
            int la = 4 * lr0 + j;
            la ^= (la >> 3) & 3;
            offA[j] = (blk + la) * 4 + e;
        }
        int sB = (rB >> 2) & 1, lcb = rB & 3;
        #pragma unroll
        for (int j = 0; j < 4; j++) {
            int nn = cB + j;
            int nt = nn >> 3, lrb = nn & 7;
            int lb = (4 * lrb + lcb) ^ nt;
            offB[j] = (nt * 2 * 32 + lb) * 2 + sB;
        }
    }

    float acc[4][4][4];
    #pragma unroll
    for (int i = 0; i < 4; i++)
        #pragma unroll
        for (int j = 0; j < 4; j++)
            #pragma unroll
            for (int r = 0; r < 4; r++) acc[i][j][r] = 0.0f;

    const int NK = Kloop >> 4;
    uint4 pa0, pa1, pb0, pb1;
    const uint4 z4 = make_uint4(0u, 0u, 0u, 0u);

    {   // prologue kb=0
        int gr0 = mBase + rA, gr1 = gr0 + 64;
        pa0 = (gr0 < M) ? *(const uint4*)(A + (size_t)gr0 * K + aOff + cA) : z4;
        pa1 = (gr1 < M) ? *(const uint4*)(A + (size_t)gr1 * K + aOff + cA) : z4;
        pb0 = *(const uint4*)(W + (size_t)rB       * N + nBase + cB);
        pb1 = *(const uint4*)(W + (size_t)(rB + 8) * N + nBase + cB);
        uint32_t* sa = As[0];
        sa[offA[0]] = pa0.x; sa[offA[1]] = pa0.y; sa[offA[2]] = pa0.z; sa[offA[3]] = pa0.w;
        sa += 1024;
        sa[offA[0]] = pa1.x; sa[offA[1]] = pa1.y; sa[offA[2]] = pa1.z; sa[offA[3]] = pa1.w;
        uint32_t* sb = Bs[0];
        sb[offB[0]] = pb0.x; sb[offB[1]] = pb0.y; sb[offB[2]] = pb0.z; sb[offB[3]] = pb0.w;
        sb += 64;
        sb[offB[0]] = pb1.x; sb[offB[1]] = pb1.y; sb[offB[2]] = pb1.z; sb[offB[3]] = pb1.w;
    }
    __syncthreads();

    for (int kb = 0; kb < NK; kb++) {
        const int buf = kb & 1;
        const bool more = (kb + 1 < NK);
        if (more) {
            int kofs = (kb + 1) * 16;
            int gr0 = mBase + rA, gr1 = gr0 + 64;
            pa0 = (gr0 < M) ? *(const uint4*)(A + (size_t)gr0 * K + aOff + kofs + cA) : z4;
            pa1 = (gr1 < M) ? *(const uint4*)(A + (size_t)gr1 * K + aOff + kofs + cA) : z4;
            pb0 = *(const uint4*)(W + (size_t)(kofs + rB)     * N + nBase + cB);
            pb1 = *(const uint4*)(W + (size_t)(kofs + rB + 8) * N + nBase + cB);
        }
        const uint32_t* curA = As[buf];
        const uint32_t* curB = Bs[buf];
        #pragma unroll
        for (int ks = 0; ks < 2; ks++) {
            uint4 a[4]; uint2 b[4];
            #pragma unroll
            for (int mt = 0; mt < 4; mt++) {
                int mt_g = wm * 4 + mt;
                a[mt] = *(const uint4*)&curA[((mt_g * 2 + ks) * 32 + laneA) * 4];
            }
            #pragma unroll
            for (int nt = 0; nt < 4; nt++) {
                int nt_g = wn * 4 + nt;
                b[nt] = *(const uint2*)&curB[((nt_g * 2 + ks) * 32 + (lane ^ nt_g)) * 2];
            }
            #pragma unroll
            for (int mt = 0; mt < 4; mt++)
                #pragma unroll
                for (int nt = 0; nt < 4; nt++)
                    mma_tf32(acc[mt][nt], a[mt].x, a[mt].z, a[mt].y, a[mt].w,
                             b[nt].x, b[nt].y);
        }
        if (more) {
            uint32_t* sa = As[buf ^ 1];
            sa[offA[0]] = pa0.x; sa[offA[1]] = pa0.y; sa[offA[2]] = pa0.z; sa[offA[3]] = pa0.w;
            sa += 1024;
            sa[offA[0]] = pa1.x; sa[offA[1]] = pa1.y; sa[offA[2]] = pa1.z; sa[offA[3]] = pa1.w;
            uint32_t* sb = Bs[buf ^ 1];
            sb[offB[0]] = pb0.x; sb[offB[1]] = pb0.y; sb[offB[2]] = pb0.z; sb[offB[3]] = pb0.w;
            sb += 64;
            sb[offB[0]] = pb1.x; sb[offB[1]] = pb1.y; sb[offB[2]] = pb1.z; sb[offB[3]] = pb1.w;
        }
        __syncthreads();
    }

    #pragma unroll
    for (int mt = 0; mt < 4; mt++) {
        int r0 = mBase + wm * 64 + mt * 16 + lr;
        #pragma unroll
        for (int nt = 0; nt < 4; nt++) {
            int col = nBase + wn * 32 + nt * 8 + lc * 2;
            float2 bv = make_float2(0.f, 0.f);
            if (EPI != 3) bv = *(const float2*)(bias + col);
            float* cc = acc[mt][nt];
            #pragma unroll
            for (int half = 0; half < 2; half++) {
                int r = r0 + half * 8;
                if (r >= M) continue;
                float ox = cc[half * 2 + 0] + bv.x;
                float oy = cc[half * 2 + 1] + bv.y;
                if (EPI == 1) {
                    ox = gelu_exact(ox); oy = gelu_exact(oy);
                    uint32_t* Cu = (uint32_t*)p.out[blockIdx.z];
                    *(uint2*)(Cu + (size_t)r * N + col) = make_uint2(f2tf(ox), f2tf(oy));
                } else if (EPI == 3) {
                    float* Cf = (float*)p.out[0];
                    red_add_v2(Cf + (size_t)r * N + col, ox, oy);
                } else if (EPI == 4) {
                    __nv_bfloat16* Cb = (__nv_bfloat16*)p.out[blockIdx.z];
                    *(__nv_bfloat162*)(Cb + (size_t)r * N + col) =
                        __float22bfloat162_rn(make_float2(ox, oy));
                } else {
                    float* Cf = (float*)p.out[blockIdx.z];
                    *(float2*)(Cf + (size_t)r * N + col) = make_float2(ox, oy);
                }
            }
        }
    }
}

// ---------------- CSR aggregation: warp per dst node, register accumulators ----------------
__global__ void agg_csr_kernel(const int* __restrict__ csrsrc,
                               const int* __restrict__ rowptr,
                               const __nv_bfloat16* __restrict__ q,
                               const __nv_bfloat16* __restrict__ k,
                               const __nv_bfloat16* __restrict__ v,
                               float* __restrict__ den, float* __restrict__ agg, int n) {
    int dst = (blockIdx.x * blockDim.x + threadIdx.x) >> 5;
    if (dst >= n) return;
    int lane = threadIdx.x & 31;
    // q row: lane covers elements [lane*8, lane*8+8)
    uint4 qv = ((const uint4*)(q + (size_t)dst * HID))[lane];
    float qf[8];
    {
        const __nv_bfloat162* qh = (const __nv_bfloat162*)&qv;
        #pragma unroll
        for (int i = 0; i < 4; i++) {
            float2 f = __bfloat1622float2(qh[i]);
            qf[2 * i] = f.x; qf[2 * i + 1] = f.y;
        }
    }
    float acc[8] = {0.f, 0.f, 0.f, 0.f, 0.f, 0.f, 0.f, 0.f};
    float densum = 0.0f;
    int beg = rowptr[dst], endi = rowptr[dst + 1];
    for (int i = beg; i < endi; i++) {
        int src = csrsrc[i];
        uint4 kv = ((const uint4*)(k + (size_t)src * HID))[lane];
        uint4 vv = ((const uint4*)(v + (size_t)src * HID))[lane];
        float d = 0.f;
        const __nv_bfloat162* kh = (const __nv_bfloat162*)&kv;
        #pragma unroll
        for (int j = 0; j < 4; j++) {
            float2 f = __bfloat1622float2(kh[j]);
            d += qf[2 * j] * f.x + qf[2 * j + 1] * f.y;
        }
        d += __shfl_xor_sync(0xffffffffu, d, 1);
        d += __shfl_xor_sync(0xffffffffu, d, 2);
        d += __shfl_xor_sync(0xffffffffu, d, 4);   // 8 lanes of a head hold the dot
        float w = __expf(d * 0.125f);              // 1/sqrt(64)
        densum += w;
        const __nv_bfloat162* vh = (const __nv_bfloat162*)&vv;
        #pragma unroll
        for (int j = 0; j < 4; j++) {
            float2 f = __bfloat1622float2(vh[j]);
            acc[2 * j]     += w * f.x;
            acc[2 * j + 1] += w * f.y;
        }
    }
    float* op = agg + (size_t)dst * HID + lane * 8;
    *(float4*)op       = make_float4(acc[0], acc[1], acc[2], acc[3]);
    *(float4*)(op + 4) = make_float4(acc[4], acc[5], acc[6], acc[7]);
    if ((lane & 7) == 0) den[dst * NHEAD + (lane >> 3)] = densum;
}

// ---------------- host launch ----------------
extern "C" void kernel_launch(void* const* d_in, const int* in_sizes, int n_in,
                              void* d_out, int out_size) {
    const float* x     = (const float*)d_in[0];
    const int*   ei    = (const int*)d_in[1];
    const float* ln1_w = (const float*)d_in[2];
    const float* ln1_b = (const float*)d_in[3];
    const float* ln2_w = (const float*)d_in[4];
    const float* ln2_b = (const float*)d_in[5];
    const float* wq    = (const float*)d_in[6];
    const float* bq    = (const float*)d_in[7];
    const float* wk    = (const float*)d_in[8];
    const float* bk    = (const float*)d_in[9];
    const float* wv    = (const float*)d_in[10];
    const float* bv    = (const float*)d_in[11];
    const float* wskip = (const float*)d_in[12];
    const float* bskip = (const float*)d_in[13];
    const float* w1    = (const float*)d_in[14];
    const float* b1    = (const float*)d_in[15];
    const float* w2    = (const float*)d_in[16];
    const float* b2    = (const float*)d_in[17];

    int n = in_sizes[0] / HID;
    int E = in_sizes[1] / 2;

    static uint32_t *h = nullptr, *mid, *wt0, *wt1, *wt2, *wt3, *w1t, *w2t;
    static __nv_bfloat16 *q, *k, *v;
    static float *skip, *agg, *den;
    static int *cnt, *rowptr, *wpos, *csrsrc;
    static cudaStream_t s2;
    static cudaEvent_t ev0, evA, evB, evC, evD, evS;
    if (!h) {
        cudaGetSymbolAddress((void**)&h,      g_h);
        cudaGetSymbolAddress((void**)&q,      g_q);
        cudaGetSymbolAddress((void**)&k,      g_k);
        cudaGetSymbolAddress((void**)&v,      g_v);
        cudaGetSymbolAddress((void**)&skip,   g_skip);
        cudaGetSymbolAddress((void**)&agg,    g_agg);
        cudaGetSymbolAddress((void**)&mid,    g_mid);
        cudaGetSymbolAddress((void**)&den,    g_den);
        cudaGetSymbolAddress((void**)&cnt,    g_count);
        cudaGetSymbolAddress((void**)&rowptr, g_rowptr);
        cudaGetSymbolAddress((void**)&wpos,   g_wpos);
        cudaGetSymbolAddress((void**)&csrsrc, g_csrsrc);
        cudaGetSymbolAddress((void**)&wt0,    g_wt);
        wt1 = wt0 + HID * HID; wt2 = wt1 + HID * HID; wt3 = wt2 + HID * HID;
        cudaGetSymbolAddress((void**)&w1t,    g_w1t);
        cudaGetSymbolAddress((void**)&w2t,    g_w2t);
        cudaStreamCreateWithFlags(&s2, cudaStreamNonBlocking);
        cudaEventCreateWithFlags(&ev0, cudaEventDisableTiming);
        cudaEventCreateWithFlags(&evA, cudaEventDisableTiming);
        cudaEventCreateWithFlags(&evB, cudaEventDisableTiming);
        cudaEventCreateWithFlags(&evC, cudaEventDisableTiming);
        cudaEventCreateWithFlags(&evD, cudaEventDisableTiming);
        cudaEventCreateWithFlags(&evS, cudaEventDisableTiming);
    }

    // Legal capture fork: s2's first node waits on an event from the capture stream.
    cudaEventRecord(ev0, 0);
    cudaStreamWaitEvent(s2, ev0, 0);

    // s2: weight conversion (independent of everything on main)
    {
        WCvt wc;
        wc.src[0] = wq;    wc.dst[0] = wt0;
        wc.src[1] = wk;    wc.dst[1] = wt1;
        wc.src[2] = wv;    wc.dst[2] = wt2;
        wc.src[3] = wskip; wc.dst[3] = wt3;
        wc.src[4] = w1;    wc.dst[4] = w1t;
        wc.src[5] = w2;    wc.dst[5] = w2t;
        cvt_weights_kernel<<<512, 256, 0, s2>>>(wc);
    }
    cudaEventRecord(evC, s2);                      // weights ready

    // main: zero degree counters, detect dtype
    init_kernel<<<(n + 255) / 256, 256>>>(cnt, n);
    detect_kernel<<<1, 32>>>(ei, E);
    cudaEventRecord(evD, 0);                       // count zeroed + is64 ready

    // s2: CSR build (count -> scan -> scatter), overlapped with ln + QKV on main
    cudaStreamWaitEvent(s2, evD, 0);
    count_kernel<<<(E + 255) / 256, 256, 0, s2>>>(ei, cnt, E);
    scan_kernel<<<1, SCAN_T, 0, s2>>>(cnt, rowptr, wpos, n);
    scatter_kernel<<<(E + 255) / 256, 256, 0, s2>>>(ei, wpos, csrsrc, E);
    cudaEventRecord(evS, s2);                      // CSR ready

    ln_kernel<<<(n * 32 + 255) / 256, 256>>>(x, ln1_w, ln1_b, h, n);
    cudaEventRecord(evA, 0);                       // h ready

    // s2: skip projection (weights already on s2; h via evA)
    cudaStreamWaitEvent(s2, evA, 0);
    {
        GemmPtrs p;
        p.W[0] = wt3; p.bias[0] = bskip; p.out[0] = skip;
        dim3 g((n + 127) / 128, HID / 128, 1);     // 157 x 2
        gemm_tf32<0><<<g, 256, 0, s2>>>(h, p, n, HID, HID, HID);
    }
    cudaEventRecord(evB, s2);

    cudaStreamWaitEvent(0, evC, 0);                // main: wait for weights
    {
        GemmPtrs p;
        p.W[0] = wt0; p.bias[0] = bq; p.out[0] = q;
        p.W[1] = wt1; p.bias[1] = bk; p.out[1] = k;
        p.W[2] = wt2; p.bias[2] = bv; p.out[2] = v;
        dim3 g((n + 127) / 128, HID / 128, 3);     // 157 x 2 x 3
        gemm_tf32<4><<<g, 256>>>(h, p, n, HID, HID, HID);
    }

    cudaStreamWaitEvent(0, evS, 0);                // main: CSR ready
    agg_csr_kernel<<<(n * 32 + 255) / 256, 256>>>(csrsrc, rowptr, q, k, v, den, agg, n);

    cudaStreamWaitEvent(0, evB, 0);                // join: skip ready
    add_ln_kernel<<<(n * 32 + 255) / 256, 256>>>(x, skip, agg, den, ln2_w, ln2_b, b2,
                                                 (float*)d_out, h, n);

    {
        GemmPtrs p;
        p.W[0] = w1t; p.bias[0] = b1; p.out[0] = mid;
        dim3 g((n + 127) / 128, (2 * HID) / 128, 1);   // 157 x 4
        gemm_tf32<1><<<g, 256>>>(h, p, n, 2 * HID, HID, HID);
    }
    {
        GemmPtrs p;                                     // split-K=2 onto seeded d_out
        p.W[0] = w2t;             p.bias[0] = b2; p.out[0] = d_out;
        p.W[1] = w2t + HID * HID; p.bias[1] = b2; p.out[1] = d_out;
        dim3 g((n + 127) / 128, HID / 128, 2);          // 157 x 2 x 2
        gemm_tf32<3><<<g, 256>>>(mid, p, n, HID, 2 * HID, HID);
    }
}

// round 15
// speedup vs baseline: 4.1260x; 1.3337x over previous
#include <cuda_runtime.h>
#include <cuda_bf16.h>
#include <cstdint>

#define HID 256
#define NHEAD 4
#define MAXN 20000
#define MAXE 320000
#define SCAN_T 1024

// ---------------- scratch (device globals; no allocation allowed) ----------------
__device__ uint32_t       g_h   [(size_t)MAXN * HID];      // ln1 out (tf32) for skip GEMM
__device__ uint32_t       g_h16 [(size_t)MAXN * HID / 2];  // ln1/ln2 out (bf16 pairs)
__device__ __nv_bfloat16  g_q   [(size_t)MAXN * HID];      // bf16 projections
__device__ __nv_bfloat16  g_k   [(size_t)MAXN * HID];
__device__ __nv_bfloat16  g_v   [(size_t)MAXN * HID];
__device__ float          g_skip[(size_t)MAXN * HID];      // skip projection (f32)
__device__ float          g_agg [(size_t)MAXN * HID];      // edge aggregate
__device__ __nv_bfloat16  g_mid [(size_t)MAXN * 2 * HID];  // FF hidden (bf16)
__device__ float          g_den [MAXN * NHEAD];            // softmax denominators
__device__ int            g_is64;
// CSR scratch
__device__ int g_count [MAXN];
__device__ int g_rowptr[MAXN + 1];
__device__ int g_wpos  [MAXN];
__device__ int g_csrsrc[MAXE];
// converted weights: slots 0-2 = wq/wk/wv bf16-packed [128,256]; slot 3 = wskip tf32 [256,256]
__device__ uint32_t g_wt  [4][HID * HID];
__device__ uint32_t g_w1t [HID * 2 * HID];                 // w1 bf16-packed [128,512] (oversized)
__device__ uint32_t g_w2t [2 * HID * HID];                 // w2 bf16-packed [256,256] (oversized)

// ---------------- helpers ----------------
__device__ __forceinline__ int load_idx(const int* __restrict__ ei, int pos, int is64) {
    return is64 ? ei[(size_t)pos * 2] : ei[pos];
}
__device__ __forceinline__ void red_add_v2(float* p, float a, float b) {
    asm volatile("red.global.add.v2.f32 [%0], {%1,%2};"
                 :: "l"(p), "f"(a), "f"(b) : "memory");
}
__device__ __forceinline__ float gelu_exact(float v) {
    return 0.5f * v * (1.0f + erff(v * 0.7071067811865476f));
}
__device__ __forceinline__ uint32_t f2tf(float x) {
    uint32_t r; asm("cvt.rna.tf32.f32 %0, %1;" : "=r"(r) : "f"(x)); return r;
}
__device__ __forceinline__ uint32_t pack_bf2(float lo, float hi) {
    uint32_t l = __bfloat16_as_ushort(__float2bfloat16_rn(lo));
    uint32_t h = __bfloat16_as_ushort(__float2bfloat16_rn(hi));
    return l | (h << 16);
}
__device__ __forceinline__ void mma_tf32(float* c, uint32_t a0, uint32_t a1, uint32_t a2,
                                         uint32_t a3, uint32_t b0, uint32_t b1) {
    asm volatile("mma.sync.aligned.m16n8k8.row.col.f32.tf32.tf32.f32 "
                 "{%0,%1,%2,%3}, {%4,%5,%6,%7}, {%8,%9}, {%0,%1,%2,%3};"
                 : "+f"(c[0]), "+f"(c[1]), "+f"(c[2]), "+f"(c[3])
                 : "r"(a0), "r"(a1), "r"(a2), "r"(a3), "r"(b0), "r"(b1));
}
__device__ __forceinline__ void mma_bf16(float* c, uint32_t a0, uint32_t a1, uint32_t a2,
                                         uint32_t a3, uint32_t b0, uint32_t b1) {
    asm volatile("mma.sync.aligned.m16n8k16.row.col.f32.bf16.bf16.f32 "
                 "{%0,%1,%2,%3}, {%4,%5,%6,%7}, {%8,%9}, {%0,%1,%2,%3};"
                 : "+f"(c[0]), "+f"(c[1]), "+f"(c[2]), "+f"(c[3])
                 : "r"(a0), "r"(a1), "r"(a2), "r"(a3), "r"(b0), "r"(b1));
}

// ---------------- dtype detection (1 warp) ----------------
__global__ void detect_kernel(const int* __restrict__ ei, int E) {
    int lane = threadIdx.x;
    int nz = 0;
    for (int i = lane; i < 512 && i < E; i += 32)
        nz |= ei[2 * i + 1];
    #pragma unroll
    for (int o = 16; o > 0; o >>= 1) nz |= __shfl_xor_sync(0xffffffffu, nz, o);
    if (lane == 0) g_is64 = (nz == 0) ? 1 : 0;
}

// ---------------- weight conversion: wskip -> tf32 ----------------
__global__ void cvt_wskip_kernel(const float* __restrict__ src, uint32_t* __restrict__ dst) {
    int i = (blockIdx.x * blockDim.x + threadIdx.x) * 4;    // 65536 words
    float4 v = *(const float4*)(src + i);
    *(uint4*)(dst + i) = make_uint4(f2tf(v.x), f2tf(v.y), f2tf(v.z), f2tf(v.w));
}

// ---------------- weight conversion: q/k/v/w1/w2 -> bf16 k-pair packed ----------------
// dst[kw*N + n] = (bf16 src[2kw][n], bf16 src[2kw+1][n])   [lo = even k]
struct WPack { const float* src[5]; uint32_t* dst[5]; };
__global__ void cvt_bf16pack_kernel(WPack wp) {
    int i4 = (blockIdx.x * blockDim.x + threadIdx.x) * 4;   // 229376 words total
    int seg, base, N;
    if (i4 < 98304)       { seg = i4 >> 15; base = seg << 15; N = 256; }
    else if (i4 < 163840) { seg = 3; base = 98304;  N = 512; }
    else                  { seg = 4; base = 163840; N = 256; }
    int off = i4 - base;
    int kw = off / N, n = off % N;                          // 4 consecutive n, same kw
    const float* s = wp.src[seg];
    float4 a = *(const float4*)(s + (size_t)(2 * kw) * N + n);
    float4 b = *(const float4*)(s + (size_t)(2 * kw + 1) * N + n);
    uint4 o;
    o.x = pack_bf2(a.x, b.x);
    o.y = pack_bf2(a.y, b.y);
    o.z = pack_bf2(a.z, b.z);
    o.w = pack_bf2(a.w, b.w);
    *(uint4*)(wp.dst[seg] + off) = o;
}

// ---------------- init: zero degree counters ----------------
__global__ void init_kernel(int* __restrict__ count, int n) {
    int i = blockIdx.x * blockDim.x + threadIdx.x;
    if (i < n) count[i] = 0;
}

// ---------------- CSR pass 1: degree count ----------------
__global__ void count_kernel(const int* __restrict__ ei, int* __restrict__ count, int E) {
    int e = blockIdx.x * blockDim.x + threadIdx.x;
    if (e >= E) return;
    int dst = load_idx(ei, E + e, g_is64);
    atomicAdd(&count[dst], 1);
}

// ---------------- CSR pass 2: exclusive scan (single block) ----------------
__global__ void scan_kernel(const int* __restrict__ count, int* __restrict__ rowptr,
                            int* __restrict__ wpos, int n) {
    __shared__ int part[SCAN_T];
    int t = threadIdx.x;
    int per = (n + SCAN_T - 1) / SCAN_T;
    int start = t * per;
    int end = min(start + per, n);
    int s = 0;
    for (int i = start; i < end; i++) s += count[i];
    part[t] = s;
    __syncthreads();
    for (int off = 1; off < SCAN_T; off <<= 1) {
        int vv = (t >= off) ? part[t - off] : 0;
        __syncthreads();
        part[t] += vv;
        __syncthreads();
    }
    int prefix = (t == 0) ? 0 : part[t - 1];
    for (int i = start; i < end; i++) {
        rowptr[i] = prefix;
        wpos[i]   = prefix;
        prefix += count[i];
    }
    if (t == SCAN_T - 1) rowptr[n] = part[SCAN_T - 1];
}

// ---------------- CSR pass 3: scatter src by dst ----------------
__global__ void scatter_kernel(const int* __restrict__ ei, int* __restrict__ wpos,
                               int* __restrict__ csrsrc, int E) {
    int e = blockIdx.x * blockDim.x + threadIdx.x;
    if (e >= E) return;
    int is64 = g_is64;
    int src = load_idx(ei, e, is64);
    int dst = load_idx(ei, E + e, is64);
    int pos = atomicAdd(&wpos[dst], 1);
    csrsrc[pos] = src;
}

// ---------------- LayerNorm -> tf32 out (skip) + bf16-pair out (QKV/FF1) ----------------
__global__ void ln_kernel(const float* __restrict__ x, const float* __restrict__ w,
                          const float* __restrict__ b, uint32_t* __restrict__ out32,
                          uint32_t* __restrict__ out16, int n) {
    int row = (blockIdx.x * blockDim.x + threadIdx.x) >> 5;
    if (row >= n) return;
    int lane = threadIdx.x & 31;
    const float4* xp = (const float4*)(x + (size_t)row * HID);
    float4 v0 = xp[lane * 2], v1 = xp[lane * 2 + 1];
    float s  = v0.x + v0.y + v0.z + v0.w + v1.x + v1.y + v1.z + v1.w;
    float sq = v0.x*v0.x + v0.y*v0.y + v0.z*v0.z + v0.w*v0.w
             + v1.x*v1.x + v1.y*v1.y + v1.z*v1.z + v1.w*v1.w;
    #pragma unroll
    for (int o = 16; o > 0; o >>= 1) {
        s  += __shfl_xor_sync(0xffffffffu, s,  o);
        sq += __shfl_xor_sync(0xffffffffu, sq, o);
    }
    float mean = s * (1.0f / HID);
    float var  = sq * (1.0f / HID) - mean * mean;
    float rstd = rsqrtf(var + 1e-5f);
    const float4* wp = (const float4*)w;
    const float4* bp = (const float4*)b;
    uint4* op = (uint4*)(out32 + (size_t)row * HID);
    float o8[8];
    #pragma unroll
    for (int i = 0; i < 2; i++) {
        float4 xv = (i == 0) ? v0 : v1;
        float4 wv = wp[lane * 2 + i], bv = bp[lane * 2 + i];
        o8[4*i+0] = (xv.x - mean) * rstd * wv.x + bv.x;
        o8[4*i+1] = (xv.y - mean) * rstd * wv.y + bv.y;
        o8[4*i+2] = (xv.z - mean) * rstd * wv.z + bv.z;
        o8[4*i+3] = (xv.w - mean) * rstd * wv.w + bv.w;
        op[lane * 2 + i] = make_uint4(f2tf(o8[4*i]), f2tf(o8[4*i+1]),
                                      f2tf(o8[4*i+2]), f2tf(o8[4*i+3]));
    }
    uint4 ob = make_uint4(pack_bf2(o8[0], o8[1]), pack_bf2(o8[2], o8[3]),
                          pack_bf2(o8[4], o8[5]), pack_bf2(o8[6], o8[7]));
    ((uint4*)(out16 + (size_t)row * (HID / 2)))[lane] = ob;
}

// ---------------- x1 = x + skip + agg/den; dout = x1 + b2; h2 = LN2(x1) bf16 ----------------
__global__ void add_ln_kernel(const float* __restrict__ x, const float* __restrict__ skip,
                              const float* __restrict__ agg, const float* __restrict__ den,
                              const float* __restrict__ w, const float* __restrict__ b,
                              const float* __restrict__ b2,
                              float* __restrict__ dout, uint32_t* __restrict__ hout16, int n) {
    int row = (blockIdx.x * blockDim.x + threadIdx.x) >> 5;
    if (row >= n) return;
    int lane = threadIdx.x & 31;
    int h = lane >> 3;
    float d = den[row * NHEAD + h];
    float rden = (d > 0.0f) ? (1.0f / d) : 0.0f;
    const float4* xp = (const float4*)(x    + (size_t)row * HID);
    const float4* sp = (const float4*)(skip + (size_t)row * HID);
    const float4* ap = (const float4*)(agg  + (size_t)row * HID);
    float4 a0 = xp[lane * 2], a1 = xp[lane * 2 + 1];
    float4 c0 = sp[lane * 2], c1 = sp[lane * 2 + 1];
    float4 g0 = ap[lane * 2], g1 = ap[lane * 2 + 1];
    float4 v0 = make_float4(a0.x + c0.x + g0.x * rden, a0.y + c0.y + g0.y * rden,
                            a0.z + c0.z + g0.z * rden, a0.w + c0.w + g0.w * rden);
    float4 v1 = make_float4(a1.x + c1.x + g1.x * rden, a1.y + c1.y + g1.y * rden,
                            a1.z + c1.z + g1.z * rden, a1.w + c1.w + g1.w * rden);
    const float4* b2p = (const float4*)b2;
    float4 t0 = b2p[lane * 2], t1 = b2p[lane * 2 + 1];
    float4* dp = (float4*)(dout + (size_t)row * HID);
    dp[lane * 2]     = make_float4(v0.x + t0.x, v0.y + t0.y, v0.z + t0.z, v0.w + t0.w);
    dp[lane * 2 + 1] = make_float4(v1.x + t1.x, v1.y + t1.y, v1.z + t1.z, v1.w + t1.w);
    float s  = v0.x + v0.y + v0.z + v0.w + v1.x + v1.y + v1.z + v1.w;
    float sq = v0.x*v0.x + v0.y*v0.y + v0.z*v0.z + v0.w*v0.w
             + v1.x*v1.x + v1.y*v1.y + v1.z*v1.z + v1.w*v1.w;
    #pragma unroll
    for (int o = 16; o > 0; o >>= 1) {
        s  += __shfl_xor_sync(0xffffffffu, s,  o);
        sq += __shfl_xor_sync(0xffffffffu, sq, o);
    }
    float mean = s * (1.0f / HID);
    float var  = sq * (1.0f / HID) - mean * mean;
    float rstd = rsqrtf(var + 1e-5f);
    const float4* wp = (const float4*)w;
    const float4* bp = (const float4*)b;
    float o8[8];
    #pragma unroll
    for (int i = 0; i < 2; i++) {
        float4 xv = (i == 0) ? v0 : v1;
        float4 wv = wp[lane * 2 + i], bv = bp[lane * 2 + i];
        o8[4*i+0] = (xv.x - mean) * rstd * wv.x + bv.x;
        o8[4*i+1] = (xv.y - mean) * rstd * wv.y + bv.y;
        o8[4*i+2] = (xv.z - mean) * rstd * wv.z + bv.z;
        o8[4*i+3] = (xv.w - mean) * rstd * wv.w + bv.w;
    }
    uint4 ob = make_uint4(pack_bf2(o8[0], o8[1]), pack_bf2(o8[2], o8[3]),
                          pack_bf2(o8[4], o8[5]), pack_bf2(o8[6], o8[7]));
    ((uint4*)(hout16 + (size_t)row * (HID / 2)))[lane] = ob;
}

struct GemmPtrs { const uint32_t* W[4]; const float* bias[4]; void* out[4]; };

// ---------------- TF32 GEMM (skip only, EPI 0) ----------------
template<int EPI>
__global__ __launch_bounds__(256)
void gemm_tf32(const uint32_t* __restrict__ A, GemmPtrs p,
               int M, int N, int K, int Kloop) {
    __shared__ __align__(16) uint32_t As[2][2048];
    __shared__ __align__(16) uint32_t Bs[2][2048];
    const uint32_t* __restrict__ W    = p.W[blockIdx.z];
    const float* __restrict__    bias = p.bias[blockIdx.z];
    const int t = threadIdx.x;
    const int lane = t & 31, wid = t >> 5;
    const int wm = wid & 1, wn = wid >> 1;
    const int mBase = blockIdx.x * 128;
    const int nBase = blockIdx.y * 128;
    const int lr = lane >> 2, lc = lane & 3;
    const int rA = t >> 2,  cA = (t & 3) * 4;
    const int rB = t >> 5,  cB = (t & 31) * 4;
    const int laneA = lane ^ ((lane >> 3) & 3);
    int offA[4], offB[4];
    {
        int mt = rA >> 4, s1 = (rA >> 3) & 1, lr0 = rA & 7;
        int ks = cA >> 3, s2 = (cA >> 2) & 1;
        int e  = s1 * 2 + s2;
        int blk = (mt * 2 + ks) * 32;
        #pragma unroll
        for (int j = 0; j < 4; j++) {
            int la = 4 * lr0 + j;
            la ^= (la >> 3) & 3;
            offA[j] = (blk + la) * 4 + e;
        }
        int sB = (rB >> 2) & 1, lcb = rB & 3;
        #pragma unroll
        for (int j = 0; j < 4; j++) {
            int nn = cB + j;
            int nt = nn >> 3, lrb = nn & 7;
            int lb = (4 * lrb + lcb) ^ nt;
            offB[j] = (nt * 2 * 32 + lb) * 2 + sB;
        }
    }
    float acc[4][4][4];
    #pragma unroll
    for (int i = 0; i < 4; i++)
        #pragma unroll
        for (int j = 0; j < 4; j++)
            #pragma unroll
            for (int r = 0; r < 4; r++) acc[i][j][r] = 0.0f;
    const int NK = Kloop >> 4;
    uint4 pa0, pa1, pb0, pb1;
    const uint4 z4 = make_uint4(0u, 0u, 0u, 0u);
    {
        int gr0 = mBase + rA, gr1 = gr0 + 64;
        pa0 = (gr0 < M) ? *(const uint4*)(A + (size_t)gr0 * K + cA) : z4;
        pa1 = (gr1 < M) ? *(const uint4*)(A + (size_t)gr1 * K + cA) : z4;
        pb0 = *(const uint4*)(W + (size_t)rB       * N + nBase + cB);
        pb1 = *(const uint4*)(W + (size_t)(rB + 8) * N + nBase + cB);
        uint32_t* sa = As[0];
        sa[offA[0]] = pa0.x; sa[offA[1]] = pa0.y; sa[offA[2]] = pa0.z; sa[offA[3]] = pa0.w;
        sa += 1024;
        sa[offA[0]] = pa1.x; sa[offA[1]] = pa1.y; sa[offA[2]] = pa1.z; sa[offA[3]] = pa1.w;
        uint32_t* sb = Bs[0];
        sb[offB[0]] = pb0.x; sb[offB[1]] = pb0.y; sb[offB[2]] = pb0.z; sb[offB[3]] = pb0.w;
        sb += 64;
        sb[offB[0]] = pb1.x; sb[offB[1]] = pb1.y; sb[offB[2]] = pb1.z; sb[offB[3]] = pb1.w;
    }
    __syncthreads();
    for (int kb = 0; kb < NK; kb++) {
        const int buf = kb & 1;
        const bool more = (kb + 1 < NK);
        if (more) {
            int kofs = (kb + 1) * 16;
            int gr0 = mBase + rA, gr1 = gr0 + 64;
            pa0 = (gr0 < M) ? *(const uint4*)(A + (size_t)gr0 * K + kofs + cA) : z4;
            pa1 = (gr1 < M) ? *(const uint4*)(A + (size_t)gr1 * K + kofs + cA) : z4;
            pb0 = *(const uint4*)(W + (size_t)(kofs + rB)     * N + nBase + cB);
            pb1 = *(const uint4*)(W + (size_t)(kofs + rB + 8) * N + nBase + cB);
        }
        const uint32_t* curA = As[buf];
        const uint32_t* curB = Bs[buf];
        #pragma unroll
        for (int ks = 0; ks < 2; ks++) {
            uint4 a[4]; uint2 b[4];
            #pragma unroll
            for (int mt = 0; mt < 4; mt++) {
                int mt_g = wm * 4 + mt;
                a[mt] = *(const uint4*)&curA[((mt_g * 2 + ks) * 32 + laneA) * 4];
            }
            #pragma unroll
            for (int nt = 0; nt < 4; nt++) {
                int nt_g = wn * 4 + nt;
                b[nt] = *(const uint2*)&curB[((nt_g * 2 + ks) * 32 + (lane ^ nt_g)) * 2];
            }
            #pragma unroll
            for (int mt = 0; mt < 4; mt++)
                #pragma unroll
                for (int nt = 0; nt < 4; nt++)
                    mma_tf32(acc[mt][nt], a[mt].x, a[mt].z, a[mt].y, a[mt].w,
                             b[nt].x, b[nt].y);
        }
        if (more) {
            uint32_t* sa = As[buf ^ 1];
            sa[offA[0]] = pa0.x; sa[offA[1]] = pa0.y; sa[offA[2]] = pa0.z; sa[offA[3]] = pa0.w;
            sa += 1024;
            sa[offA[0]] = pa1.x; sa[offA[1]] = pa1.y; sa[offA[2]] = pa1.z; sa[offA[3]] = pa1.w;
            uint32_t* sb = Bs[buf ^ 1];
            sb[offB[0]] = pb0.x; sb[offB[1]] = pb0.y; sb[offB[2]] = pb0.z; sb[offB[3]] = pb0.w;
            sb += 64;
            sb[offB[0]] = pb1.x; sb[offB[1]] = pb1.y; sb[offB[2]] = pb1.z; sb[offB[3]] = pb1.w;
        }
        __syncthreads();
    }
    #pragma unroll
    for (int mt = 0; mt < 4; mt++) {
        int r0 = mBase + wm * 64 + mt * 16 + lr;
        #pragma unroll
        for (int nt = 0; nt < 4; nt++) {
            int col = nBase + wn * 32 + nt * 8 + lc * 2;
            float2 bv = *(const float2*)(bias + col);
            float* cc = acc[mt][nt];
            #pragma unroll
            for (int half = 0; half < 2; half++) {
                int r = r0 + half * 8;
                if (r >= M) continue;
                float* Cf = (float*)p.out[blockIdx.z];
                *(float2*)(Cf + (size_t)r * N + col) =
                    make_float2(cc[half * 2 + 0] + bv.x, cc[half * 2 + 1] + bv.y);
            }
        }
    }
}

// ---------------- BF16 GEMM (m16n8k16), word = bf16 k-pair ----------------
// A: [M, K] bf16 as [M, K/2] words. W: bf16-packed [K/2, N] words.
// EPI 4: bias -> bf16 out; 5: bias+GELU -> bf16 out; 3: split-K red.add f32.
template<int EPI>
__global__ __launch_bounds__(256)
void gemm_bf16(const uint32_t* __restrict__ A, GemmPtrs p,
               int M, int N, int K, int Kloop) {
    __shared__ __align__(16) uint32_t As[2][2048];
    __shared__ __align__(16) uint32_t Bs[2][2048];
    const uint32_t* __restrict__ W    = p.W[blockIdx.z];
    const float* __restrict__    bias = p.bias[blockIdx.z];
    const int AKw  = K >> 1;                          // A row stride (words)
    const int aOffW = (EPI == 3) ? blockIdx.z * (Kloop >> 1) : 0;
    const int t = threadIdx.x;
    const int lane = t & 31, wid = t >> 5;
    const int wm = wid & 1, wn = wid >> 1;
    const int mBase = blockIdx.x * 128;
    const int nBase = blockIdx.y * 128;
    const int lr = lane >> 2, lc = lane & 3;
    const int rA = t >> 2,  cA = (t & 3) * 4;         // word cols 0..15
    const int rB = t >> 5,  cB = (t & 31) * 4;        // kpair rows rB, rB+8
    const int laneA = lane ^ ((lane >> 3) & 3);
    int offA[4], offB[4];
    {
        int mt = rA >> 4, s1 = (rA >> 3) & 1, lr0 = rA & 7;
        int ks = cA >> 3, s2 = (cA >> 2) & 1;
        int e  = s1 * 2 + s2;
        int blk = (mt * 2 + ks) * 32;
        #pragma unroll
        for (int j = 0; j < 4; j++) {
            int la = 4 * lr0 + j;
            la ^= (la >> 3) & 3;
            offA[j] = (blk + la) * 4 + e;
        }
        int sB = (rB >> 2) & 1, lcb = rB & 3;
        #pragma unroll
        for (int j = 0; j < 4; j++) {
            int nn = cB + j;
            int nt = nn >> 3, lrb = nn & 7;
            int lb = (4 * lrb + lcb) ^ nt;
            offB[j] = (nt * 2 * 32 + lb) * 2 + sB;
        }
    }
    float acc[4][4][4];
    #pragma unroll
    for (int i = 0; i < 4; i++)
        #pragma unroll
        for (int j = 0; j < 4; j++)
            #pragma unroll
            for (int r = 0; r < 4; r++) acc[i][j][r] = 0.0f;
    const int NK = Kloop >> 5;                        // 32 k-elems (16 words) per tile
    uint4 pa0, pa1, pb0, pb1;
    const uint4 z4 = make_uint4(0u, 0u, 0u, 0u);
    {
        int gr0 = mBase + rA, gr1 = gr0 + 64;
        pa0 = (gr0 < M) ? *(const uint4*)(A + (size_t)gr0 * AKw + aOffW + cA) : z4;
        pa1 = (gr1 < M) ? *(const uint4*)(A + (size_t)gr1 * AKw + aOffW + cA) : z4;
        pb0 = *(const uint4*)(W + (size_t)rB       * N + nBase + cB);
        pb1 = *(const uint4*)(W + (size_t)(rB + 8) * N + nBase + cB);
        uint32_t* sa = As[0];
        sa[offA[0]] = pa0.x; sa[offA[1]] = pa0.y; sa[offA[2]] = pa0.z; sa[offA[3]] = pa0.w;
        sa += 1024;
        sa[offA[0]] = pa1.x; sa[offA[1]] = pa1.y; sa[offA[2]] = pa1.z; sa[offA[3]] = pa1.w;
        uint32_t* sb = Bs[0];
        sb[offB[0]] = pb0.x; sb[offB[1]] = pb0.y; sb[offB[2]] = pb0.z; sb[offB[3]] = pb0.w;
        sb += 64;
        sb[offB[0]] = pb1.x; sb[offB[1]] = pb1.y; sb[offB[2]] = pb1.z; sb[offB[3]] = pb1.w;
    }
    __syncthreads();
    for (int kb = 0; kb < NK; kb++) {
        const int buf = kb & 1;
        const bool more = (kb + 1 < NK);
        if (more) {
            int kofsW = (kb + 1) * 16;
            int gr0 = mBase + rA, gr1 = gr0 + 64;
            pa0 = (gr0 < M) ? *(const uint4*)(A + (size_t)gr0 * AKw + aOffW + kofsW + cA) : z4;
            pa1 = (gr1 < M) ? *(const uint4*)(A + (size_t)gr1 * AKw + aOffW + kofsW + cA) : z4;
            pb0 = *(const uint4*)(W + (size_t)(kofsW + rB)     * N + nBase + cB);
            pb1 = *(const uint4*)(W + (size_t)(kofsW + rB + 8) * N + nBase + cB);
        }
        const uint32_t* curA = As[buf];
        const uint32_t* curB = Bs[buf];
        #pragma unroll
        for (int ks = 0; ks < 2; ks++) {
            uint4 a[4]; uint2 b[4];
            #pragma unroll
            for (int mt = 0; mt < 4; mt++) {
                int mt_g = wm * 4 + mt;
                a[mt] = *(const uint4*)&curA[((mt_g * 2 + ks) * 32 + laneA) * 4];
            }
            #pragma unroll
            for (int nt = 0; nt < 4; nt++) {
                int nt_g = wn * 4 + nt;
                b[nt] = *(const uint2*)&curB[((nt_g * 2 + ks) * 32 + (lane ^ nt_g)) * 2];
            }
            #pragma unroll
            for (int mt = 0; mt < 4; mt++)
                #pragma unroll
                for (int nt = 0; nt < 4; nt++)
                    mma_bf16(acc[mt][nt], a[mt].x, a[mt].z, a[mt].y, a[mt].w,
                             b[nt].x, b[nt].y);
        }
        if (more) {
            uint32_t* sa = As[buf ^ 1];
            sa[offA[0]] = pa0.x; sa[offA[1]] = pa0.y; sa[offA[2]] = pa0.z; sa[offA[3]] = pa0.w;
            sa += 1024;
            sa[offA[0]] = pa1.x; sa[offA[1]] = pa1.y; sa[offA[2]] = pa1.z; sa[offA[3]] = pa1.w;
            uint32_t* sb = Bs[buf ^ 1];
            sb[offB[0]] = pb0.x; sb[offB[1]] = pb0.y; sb[offB[2]] = pb0.z; sb[offB[3]] = pb0.w;
            sb += 64;
            sb[offB[0]] = pb1.x; sb[offB[1]] = pb1.y; sb[offB[2]] = pb1.z; sb[offB[3]] = pb1.w;
        }
        __syncthreads();
    }
    #pragma unroll
    for (int mt = 0; mt < 4; mt++) {
        int r0 = mBase + wm * 64 + mt * 16 + lr;
        #pragma unroll
        for (int nt = 0; nt < 4; nt++) {
            int col = nBase + wn * 32 + nt * 8 + lc * 2;
            float2 bv = make_float2(0.f, 0.f);
            if (EPI != 3) bv = *(const float2*)(bias + col);
            float* cc = acc[mt][nt];
            #pragma unroll
            for (int half = 0; half < 2; half++) {
                int r = r0 + half * 8;
                if (r >= M) continue;
                float ox = cc[half * 2 + 0] + bv.x;
                float oy = cc[half * 2 + 1] + bv.y;
                if (EPI == 3) {
                    float* Cf = (float*)p.out[0];
                    red_add_v2(Cf + (size_t)r * N + col, ox, oy);
                } else {
                    if (EPI == 5) { ox = gelu_exact(ox); oy = gelu_exact(oy); }
                    __nv_bfloat16* Cb = (__nv_bfloat16*)p.out[blockIdx.z];
                    *(uint32_t*)(Cb + (size_t)r * N + col) = pack_bf2(ox, oy);
                }
            }
        }
    }
}

// ---------------- CSR aggregation: warp per dst node, register accumulators ----------------
__global__ void agg_csr_kernel(const int* __restrict__ csrsrc,
                               const int* __restrict__ rowptr,
                               const __nv_bfloat16* __restrict__ q,
                               const __nv_bfloat16* __restrict__ k,
                               const __nv_bfloat16* __restrict__ v,
                               float* __restrict__ den, float* __restrict__ agg, int n) {
    int dst = (blockIdx.x * blockDim.x + threadIdx.x) >> 5;
    if (dst >= n) return;
    int lane = threadIdx.x & 31;
    uint4 qv = ((const uint4*)(q + (size_t)dst * HID))[lane];
    float qf[8];
    {
        const __nv_bfloat162* qh = (const __nv_bfloat162*)&qv;
        #pragma unroll
        for (int i = 0; i < 4; i++) {
            float2 f = __bfloat1622float2(qh[i]);
            qf[2 * i] = f.x; qf[2 * i + 1] = f.y;
        }
    }
    float acc[8] = {0.f, 0.f, 0.f, 0.f, 0.f, 0.f, 0.f, 0.f};
    float densum = 0.0f;
    int beg = rowptr[dst], endi = rowptr[dst + 1];
    for (int i = beg; i < endi; i++) {
        int src = csrsrc[i];
        uint4 kv = ((const uint4*)(k + (size_t)src * HID))[lane];
        uint4 vv = ((const uint4*)(v + (size_t)src * HID))[lane];
        float d = 0.f;
        const __nv_bfloat162* kh = (const __nv_bfloat162*)&kv;
        #pragma unroll
        for (int j = 0; j < 4; j++) {
            float2 f = __bfloat1622float2(kh[j]);
            d += qf[2 * j] * f.x + qf[2 * j + 1] * f.y;
        }
        d += __shfl_xor_sync(0xffffffffu, d, 1);
        d += __shfl_xor_sync(0xffffffffu, d, 2);
        d += __shfl_xor_sync(0xffffffffu, d, 4);
        float w = __expf(d * 0.125f);
        densum += w;
        const __nv_bfloat162* vh = (const __nv_bfloat162*)&vv;
        #pragma unroll
        for (int j = 0; j < 4; j++) {
            float2 f = __bfloat1622float2(vh[j]);
            acc[2 * j]     += w * f.x;
            acc[2 * j + 1] += w * f.y;
        }
    }
    float* op = agg + (size_t)dst * HID + lane * 8;
    *(float4*)op       = make_float4(acc[0], acc[1], acc[2], acc[3]);
    *(float4*)(op + 4) = make_float4(acc[4], acc[5], acc[6], acc[7]);
    if ((lane & 7) == 0) den[dst * NHEAD + (lane >> 3)] = densum;
}

// ---------------- host launch ----------------
extern "C" void kernel_launch(void* const* d_in, const int* in_sizes, int n_in,
                              void* d_out, int out_size) {
    const float* x     = (const float*)d_in[0];
    const int*   ei    = (const int*)d_in[1];
    const float* ln1_w = (const float*)d_in[2];
    const float* ln1_b = (const float*)d_in[3];
    const float* ln2_w = (const float*)d_in[4];
    const float* ln2_b = (const float*)d_in[5];
    const float* wq    = (const float*)d_in[6];
    const float* bq    = (const float*)d_in[7];
    const float* wk    = (const float*)d_in[8];
    const float* bk    = (const float*)d_in[9];
    const float* wv    = (const float*)d_in[10];
    const float* bv    = (const float*)d_in[11];
    const float* wskip = (const float*)d_in[12];
    const float* bskip = (const float*)d_in[13];
    const float* w1    = (const float*)d_in[14];
    const float* b1    = (const float*)d_in[15];
    const float* w2    = (const float*)d_in[16];
    const float* b2    = (const float*)d_in[17];

    int n = in_sizes[0] / HID;
    int E = in_sizes[1] / 2;

    static uint32_t *h = nullptr, *h16, *wt0, *wt1, *wt2, *wt3, *w1t, *w2t;
    static __nv_bfloat16 *q, *k, *v, *mid;
    static float *skip, *agg, *den;
    static int *cnt, *rowptr, *wpos, *csrsrc;
    static cudaStream_t s2;
    static cudaEvent_t ev0, evA, evB, evC, evD, evS;
    if (!h) {
        cudaGetSymbolAddress((void**)&h,      g_h);
        cudaGetSymbolAddress((void**)&h16,    g_h16);
        cudaGetSymbolAddress((void**)&q,      g_q);
        cudaGetSymbolAddress((void**)&k,      g_k);
        cudaGetSymbolAddress((void**)&v,      g_v);
        cudaGetSymbolAddress((void**)&skip,   g_skip);
        cudaGetSymbolAddress((void**)&agg,    g_agg);
        cudaGetSymbolAddress((void**)&mid,    g_mid);
        cudaGetSymbolAddress((void**)&den,    g_den);
        cudaGetSymbolAddress((void**)&cnt,    g_count);
        cudaGetSymbolAddress((void**)&rowptr, g_rowptr);
        cudaGetSymbolAddress((void**)&wpos,   g_wpos);
        cudaGetSymbolAddress((void**)&csrsrc, g_csrsrc);
        cudaGetSymbolAddress((void**)&wt0,    g_wt);
        wt1 = wt0 + HID * HID; wt2 = wt1 + HID * HID; wt3 = wt2 + HID * HID;
        cudaGetSymbolAddress((void**)&w1t,    g_w1t);
        cudaGetSymbolAddress((void**)&w2t,    g_w2t);
        cudaStreamCreateWithFlags(&s2, cudaStreamNonBlocking);
        cudaEventCreateWithFlags(&ev0, cudaEventDisableTiming);
        cudaEventCreateWithFlags(&evA, cudaEventDisableTiming);
        cudaEventCreateWithFlags(&evB, cudaEventDisableTiming);
        cudaEventCreateWithFlags(&evC, cudaEventDisableTiming);
        cudaEventCreateWithFlags(&evD, cudaEventDisableTiming);
        cudaEventCreateWithFlags(&evS, cudaEventDisableTiming);
    }

    // Legal capture fork: s2's first node waits on an event from the capture stream.
    cudaEventRecord(ev0, 0);
    cudaStreamWaitEvent(s2, ev0, 0);

    // s2: weight conversions (bf16 k-pair pack for q/k/v/w1/w2; tf32 for wskip)
    {
        WPack wp;
        wp.src[0] = wq; wp.dst[0] = wt0;
        wp.src[1] = wk; wp.dst[1] = wt1;
        wp.src[2] = wv; wp.dst[2] = wt2;
        wp.src[3] = w1; wp.dst[3] = w1t;
        wp.src[4] = w2; wp.dst[4] = w2t;
        cvt_bf16pack_kernel<<<224, 256, 0, s2>>>(wp);
        cvt_wskip_kernel<<<64, 256, 0, s2>>>(wskip, wt3);
    }
    cudaEventRecord(evC, s2);                      // weights ready

    // main: zero degree counters, detect dtype
    init_kernel<<<(n + 255) / 256, 256>>>(cnt, n);
    detect_kernel<<<1, 32>>>(ei, E);
    cudaEventRecord(evD, 0);

    // s2: CSR build, overlapped with ln + QKV on main
    cudaStreamWaitEvent(s2, evD, 0);
    count_kernel<<<(E + 255) / 256, 256, 0, s2>>>(ei, cnt, E);
    scan_kernel<<<1, SCAN_T, 0, s2>>>(cnt, rowptr, wpos, n);
    scatter_kernel<<<(E + 255) / 256, 256, 0, s2>>>(ei, wpos, csrsrc, E);
    cudaEventRecord(evS, s2);                      // CSR ready

    ln_kernel<<<(n * 32 + 255) / 256, 256>>>(x, ln1_w, ln1_b, h, h16, n);
    cudaEventRecord(evA, 0);                       // h ready

    // s2: skip projection (tf32; weights on s2, h via evA)
    cudaStreamWaitEvent(s2, evA, 0);
    {
        GemmPtrs p;
        p.W[0] = wt3; p.bias[0] = bskip; p.out[0] = skip;
        dim3 g((n + 127) / 128, HID / 128, 1);
        gemm_tf32<0><<<g, 256, 0, s2>>>(h, p, n, HID, HID, HID);
    }
    cudaEventRecord(evB, s2);

    cudaStreamWaitEvent(0, evC, 0);                // main: weights ready
    {
        GemmPtrs p;
        p.W[0] = wt0; p.bias[0] = bq; p.out[0] = q;
        p.W[1] = wt1; p.bias[1] = bk; p.out[1] = k;
        p.W[2] = wt2; p.bias[2] = bv; p.out[2] = v;
        dim3 g((n + 127) / 128, HID / 128, 3);
        gemm_bf16<4><<<g, 256>>>(h16, p, n, HID, HID, HID);
    }

    cudaStreamWaitEvent(0, evS, 0);                // main: CSR ready
    agg_csr_kernel<<<(n * 32 + 255) / 256, 256>>>(csrsrc, rowptr, q, k, v, den, agg, n);

    cudaStreamWaitEvent(0, evB, 0);                // join: skip ready
    add_ln_kernel<<<(n * 32 + 255) / 256, 256>>>(x, skip, agg, den, ln2_w, ln2_b, b2,
                                                 (float*)d_out, h16, n);

    {
        GemmPtrs p;
        p.W[0] = w1t; p.bias[0] = b1; p.out[0] = mid;
        dim3 g((n + 127) / 128, (2 * HID) / 128, 1);
        gemm_bf16<5><<<g, 256>>>(h16, p, n, 2 * HID, HID, HID);
    }
    {
        GemmPtrs p;                                 // split-K=2 onto seeded d_out
        p.W[0] = w2t;                  p.bias[0] = b2; p.out[0] = d_out;
        p.W[1] = w2t + 128 * HID;      p.bias[1] = b2; p.out[1] = d_out;
        dim3 g((n + 127) / 128, HID / 128, 2);
        gemm_bf16<3><<<g, 256>>>((const uint32_t*)mid, p, n, HID, 2 * HID, HID);
    }
}